// round 5
// baseline (speedup 1.0000x reference)
#include <cuda_runtime.h>
#include <math.h>

// ---------------------------------------------------------------------------
// Problem constants
// ---------------------------------------------------------------------------
#define Bn 16
#define Hn 32
#define En 64
#define Ln 3
#define Vn 258
#define Rn 64
#define Sn 64

// Global scratch: GRU outputs per (b, channel, row, col, hidden)
__device__ float g_outs[Bn * 3 * Rn * Sn * Hn];   // 25.2 MB, no allocation

// ---------------------------------------------------------------------------
// Shared-memory layout for the RNN kernel (units: floats)
// ---------------------------------------------------------------------------
constexpr int OFF_WIH0 = 0;              // 96 x 68   (layer0 Wih, K=65 padded to 68)
constexpr int OFF_WIH1 = 6528;           // 96 x 36   (layer1 Wih, K=32 padded to 36)
constexpr int OFF_WIH2 = 9984;           // 96 x 36
constexpr int OFF_WHH  = 13440;          // 3 x 96 x 36
constexpr int OFF_BIH  = 23808;          // 3 x 96
constexpr int OFF_BHH  = 24096;          // 3 x 96
constexpr int OFF_H2E  = 24384;          // 65 x 36
constexpr int OFF_H2EB = 26724;          // 68
constexpr int OFF_ADP  = 26792;          // 65 x 36
constexpr int OFF_ADPB = 29132;          // 68
constexpr int OFF_COMB = 29200;          // 64 x 68
constexpr int OFF_ROWA = 33552;          // 64 x 36
constexpr int OFF_ROWB = 35856;          // 64 x 36
constexpr int OFF_PREV = 38160;          // 64 x 36 (prev-channel row)
constexpr int OFF_H    = 40464;          // 3 x 36  (per-layer hidden state)
constexpr int OFF_RZ   = 40572;          // 64
constexpr int OFF_GIN  = 40636;          // 32
constexpr int OFF_GHN  = 40668;          // 32
constexpr int SM_TOT   = 40700;          // 162800 bytes

// ---------------------------------------------------------------------------
// Vectorized smem dot product over N4 float4 chunks (both operands 16B-aligned,
// padded with zeros so no remainder handling is needed).
// ---------------------------------------------------------------------------
template <int N4>
__device__ __forceinline__ float dot_sm(const float* __restrict__ a,
                                        const float* __restrict__ b) {
    const float4* A = reinterpret_cast<const float4*>(a);
    const float4* Bv = reinterpret_cast<const float4*>(b);
    float s0 = 0.f, s1 = 0.f;
#pragma unroll
    for (int i = 0; i < N4; ++i) {
        float4 x = A[i], y = Bv[i];
        if (i & 1) {
            s1 = fmaf(x.x, y.x, s1); s1 = fmaf(x.y, y.y, s1);
            s1 = fmaf(x.z, y.z, s1); s1 = fmaf(x.w, y.w, s1);
        } else {
            s0 = fmaf(x.x, y.x, s0); s0 = fmaf(x.y, y.y, s0);
            s0 = fmaf(x.z, y.z, s0); s0 = fmaf(x.w, y.w, s0);
        }
    }
    return s0 + s1;
}

__device__ __forceinline__ float sigm(float x) {
    return 1.f / (1.f + __expf(-x));
}

// ---------------------------------------------------------------------------
// Kernel 1: full conditional row-RNN. grid = 16 blocks (one per batch element),
// 128 threads. Everything (3 channels x 64 rows x 64 cols x 3 GRU layers) runs
// sequentially inside the block; weights live in shared memory.
// ---------------------------------------------------------------------------
__global__ __launch_bounds__(128, 1)
void rnn_kernel(const int* __restrict__ x, const float* __restrict__ emb,
                const float* __restrict__ Wih0, const float* __restrict__ WihR,
                const float* __restrict__ Whh, const float* __restrict__ bih,
                const float* __restrict__ bhh, const float* __restrict__ h2eW,
                const float* __restrict__ h2eb, const float* __restrict__ adpW,
                const float* __restrict__ adpb) {
    extern __shared__ float sm[];
    const int tid = threadIdx.x;
    const int b = blockIdx.x;
    if (b >= Bn) return;

    // Zero all shared memory once: establishes zero pads everywhere.
    for (int idx = tid; idx < SM_TOT; idx += 128) sm[idx] = 0.f;
    __syncthreads();

    for (int c = 0; c < 3; ++c) {
        __syncthreads();  // prior channel done with weights
        // ---- load channel weights into smem (padded rows) ----
        for (int idx = tid; idx < 96 * 65; idx += 128) {
            int g = idx / 65, k = idx - g * 65;
            sm[OFF_WIH0 + g * 68 + k] = Wih0[c * 6240 + idx];
        }
        for (int idx = tid; idx < 2 * 96 * 32; idx += 128) {
            int l = idx / 3072, rem = idx - l * 3072;
            int g = rem >> 5, k = rem & 31;
            sm[(l == 0 ? OFF_WIH1 : OFF_WIH2) + g * 36 + k] = WihR[c * 6144 + idx];
        }
        for (int idx = tid; idx < 3 * 96 * 32; idx += 128) {
            int l = idx / 3072, rem = idx - l * 3072;
            int g = rem >> 5, k = rem & 31;
            sm[OFF_WHH + l * 3456 + g * 36 + k] = Whh[c * 9216 + idx];
        }
        for (int idx = tid; idx < 288; idx += 128) {
            sm[OFF_BIH + idx] = bih[c * 288 + idx];
            sm[OFF_BHH + idx] = bhh[c * 288 + idx];
        }
        for (int idx = tid; idx < 65 * 32; idx += 128) {
            int k = idx >> 5, j = idx & 31;
            sm[OFF_H2E + k * 36 + j] = h2eW[c * 2080 + idx];
        }
        for (int idx = tid; idx < 65; idx += 128)
            sm[OFF_H2EB + idx] = h2eb[c * 65 + idx];
        if (c > 0) {
            for (int idx = tid; idx < 65 * 32; idx += 128) {
                int k = idx >> 5, j = idx & 31;
                sm[OFF_ADP + k * 36 + j] = adpW[(c - 1) * 2080 + idx];
            }
            for (int idx = tid; idx < 65; idx += 128)
                sm[OFF_ADPB + idx] = adpb[(c - 1) * 65 + idx];
        }
        // ph buffer for row 0 must be zeros
        for (int idx = tid; idx < 64 * 36; idx += 128) sm[OFF_ROWA + idx] = 0.f;
        __syncthreads();

        for (int r = 0; r < Rn; ++r) {
            float* ph  = sm + ((r & 1) ? OFF_ROWB : OFF_ROWA);
            float* cur = sm + ((r & 1) ? OFF_ROWA : OFF_ROWB);

            // zero per-layer hidden (GRU starts from h0 = 0 each row)
            if (tid < 108) sm[OFF_H + tid] = 0.f;
            // stage previous-channel outputs for this row
            if (c > 0) {
                const float* gp = g_outs + (((size_t)(b * 3 + (c - 1)) * Rn + r) * Sn) * Hn;
                for (int idx = tid; idx < Sn * Hn; idx += 128) {
                    int t = idx >> 5, j = idx & 31;
                    sm[OFF_PREV + t * 36 + j] = gp[idx];
                }
            }
            __syncthreads();

            // ---- comb precompute: comb[t][k], t<64, k<65 ----
            const float rowfeat = (float)r * (2.0f / 64.0f) - 1.0f;
            const int xrb = ((b * 3 + c) * Rn + r) * Sn;
            for (int idx = tid; idx < 64 * 65; idx += 128) {
                int t = idx / 65, k = idx - t * 65;
                float base;
                if (k < 64) {
                    int xv = x[xrb + t];
                    base = emb[(c * Vn + xv) * En + k];
                } else {
                    base = rowfeat;
                }
                float acc = base + sm[OFF_H2EB + k] +
                            dot_sm<9>(sm + OFF_H2E + k * 36, ph + t * 36);
                if (c > 0)
                    acc += sm[OFF_ADPB + k] +
                           dot_sm<9>(sm + OFF_ADP + k * 36, sm + OFF_PREV + t * 36);
                sm[OFF_COMB + t * 68 + k] = acc;
            }
            __syncthreads();

            float* gout_row = g_outs + (((size_t)(b * 3 + c) * Rn + r) * Sn) * Hn;

            // ---- GRU scan over columns ----
            for (int t = 0; t < Sn; ++t) {
                // layer 0 gates
                if (tid < 96) {
                    float ai = dot_sm<17>(sm + OFF_WIH0 + tid * 68,
                                          sm + OFF_COMB + t * 68) + sm[OFF_BIH + tid];
                    float ah = dot_sm<9>(sm + OFF_WHH + tid * 36, sm + OFF_H) +
                               sm[OFF_BHH + tid];
                    if (tid < 64) sm[OFF_RZ + tid] = sigm(ai + ah);
                    else { sm[OFF_GIN + tid - 64] = ai; sm[OFF_GHN + tid - 64] = ah; }
                }
                __syncthreads();
                if (tid < 32) {
                    float rr = sm[OFF_RZ + tid], zz = sm[OFF_RZ + 32 + tid];
                    float nn = tanhf(sm[OFF_GIN + tid] + rr * sm[OFF_GHN + tid]);
                    float hp = sm[OFF_H + tid];
                    sm[OFF_H + tid] = (1.f - zz) * nn + zz * hp;
                }
                __syncthreads();
#pragma unroll
                for (int l = 1; l < 3; ++l) {
                    if (tid < 96) {
                        const float* wih =
                            sm + (l == 1 ? OFF_WIH1 : OFF_WIH2) + tid * 36;
                        float ai = dot_sm<9>(wih, sm + OFF_H + (l - 1) * 36) +
                                   sm[OFF_BIH + l * 96 + tid];
                        float ah = dot_sm<9>(sm + OFF_WHH + l * 3456 + tid * 36,
                                             sm + OFF_H + l * 36) +
                                   sm[OFF_BHH + l * 96 + tid];
                        if (tid < 64) sm[OFF_RZ + tid] = sigm(ai + ah);
                        else { sm[OFF_GIN + tid - 64] = ai; sm[OFF_GHN + tid - 64] = ah; }
                    }
                    __syncthreads();
                    if (tid < 32) {
                        float rr = sm[OFF_RZ + tid], zz = sm[OFF_RZ + 32 + tid];
                        float nn = tanhf(sm[OFF_GIN + tid] + rr * sm[OFF_GHN + tid]);
                        float hp = sm[OFF_H + l * 36 + tid];
                        float hn = (1.f - zz) * nn + zz * hp;
                        sm[OFF_H + l * 36 + tid] = hn;
                        if (l == 2) {
                            cur[t * 36 + tid] = hn;
                            gout_row[t * Hn + tid] = hn;
                        }
                    }
                    __syncthreads();
                }
            }
        }
    }
}

// ---------------------------------------------------------------------------
// Kernel 2: output logits.
// grid = (B*R, 3), 256 threads. Stage full weight matrix + input rows in smem,
// 2x4 register tiling on outputs (32 FMA per 6 LDS.128).
// ---------------------------------------------------------------------------
template <int N4>
__device__ __forceinline__ void compute_logits(const float* __restrict__ Ws,
                                               const float* __restrict__ ins,
                                               const float* __restrict__ bs,
                                               float* __restrict__ outp, int tid) {
    constexpr int Kp = N4 * 4;
    // tiles: 65 v-groups of 4 (padded to 260 rows), 32 t-groups of 2
    for (int tile = tid; tile < 65 * 32; tile += 256) {
        int vg = tile / 32, tg = tile - vg * 32;   // lanes vary tg -> W broadcast
        int t0 = tg * 2, v0 = vg * 4;
        const float4* w0 = reinterpret_cast<const float4*>(&Ws[(v0 + 0) * Kp]);
        const float4* w1 = reinterpret_cast<const float4*>(&Ws[(v0 + 1) * Kp]);
        const float4* w2 = reinterpret_cast<const float4*>(&Ws[(v0 + 2) * Kp]);
        const float4* w3 = reinterpret_cast<const float4*>(&Ws[(v0 + 3) * Kp]);
        const float4* i0 = reinterpret_cast<const float4*>(&ins[t0 * Kp]);
        const float4* i1 = reinterpret_cast<const float4*>(&ins[(t0 + 1) * Kp]);
        float a0[4] = {0.f, 0.f, 0.f, 0.f};
        float a1[4] = {0.f, 0.f, 0.f, 0.f};
#pragma unroll 4
        for (int k = 0; k < N4; ++k) {
            float4 x0 = i0[k], x1 = i1[k];
            float4 y;
            y = w0[k];
            a0[0] = fmaf(x0.x, y.x, a0[0]); a0[0] = fmaf(x0.y, y.y, a0[0]);
            a0[0] = fmaf(x0.z, y.z, a0[0]); a0[0] = fmaf(x0.w, y.w, a0[0]);
            a1[0] = fmaf(x1.x, y.x, a1[0]); a1[0] = fmaf(x1.y, y.y, a1[0]);
            a1[0] = fmaf(x1.z, y.z, a1[0]); a1[0] = fmaf(x1.w, y.w, a1[0]);
            y = w1[k];
            a0[1] = fmaf(x0.x, y.x, a0[1]); a0[1] = fmaf(x0.y, y.y, a0[1]);
            a0[1] = fmaf(x0.z, y.z, a0[1]); a0[1] = fmaf(x0.w, y.w, a0[1]);
            a1[1] = fmaf(x1.x, y.x, a1[1]); a1[1] = fmaf(x1.y, y.y, a1[1]);
            a1[1] = fmaf(x1.z, y.z, a1[1]); a1[1] = fmaf(x1.w, y.w, a1[1]);
            y = w2[k];
            a0[2] = fmaf(x0.x, y.x, a0[2]); a0[2] = fmaf(x0.y, y.y, a0[2]);
            a0[2] = fmaf(x0.z, y.z, a0[2]); a0[2] = fmaf(x0.w, y.w, a0[2]);
            a1[2] = fmaf(x1.x, y.x, a1[2]); a1[2] = fmaf(x1.y, y.y, a1[2]);
            a1[2] = fmaf(x1.z, y.z, a1[2]); a1[2] = fmaf(x1.w, y.w, a1[2]);
            y = w3[k];
            a0[3] = fmaf(x0.x, y.x, a0[3]); a0[3] = fmaf(x0.y, y.y, a0[3]);
            a0[3] = fmaf(x0.z, y.z, a0[3]); a0[3] = fmaf(x0.w, y.w, a0[3]);
            a1[3] = fmaf(x1.x, y.x, a1[3]); a1[3] = fmaf(x1.y, y.y, a1[3]);
            a1[3] = fmaf(x1.z, y.z, a1[3]); a1[3] = fmaf(x1.w, y.w, a1[3]);
        }
        int ob0 = t0 * Vn, ob1 = ob0 + Vn;
#pragma unroll
        for (int v = 0; v < 4; ++v) {
            int vv = v0 + v;
            if (vv < Vn) {
                float bv = bs[vv];
                outp[ob0 + vv] = a0[v] + bv;
                outp[ob1 + vv] = a1[v] + bv;
            }
        }
    }
}

__global__ __launch_bounds__(256, 1)
void logits_kernel(const float* __restrict__ emb, const int* __restrict__ target,
                   const float* __restrict__ W0, const float* __restrict__ b0,
                   const float* __restrict__ W1, const float* __restrict__ b1,
                   const float* __restrict__ W2, const float* __restrict__ b2,
                   float* __restrict__ out) {
    extern __shared__ float sm[];
    const int tid = threadIdx.x;
    const int ch = blockIdx.y;
    const int bb = blockIdx.x >> 6;
    const int r = blockIdx.x & 63;

    const float* W;
    const float* Bb;
    int K;
    if (ch == 0)      { W = W0; Bb = b0; K = 32; }
    else if (ch == 1) { W = W1; Bb = b1; K = 96; }
    else              { W = W2; Bb = b2; K = 160; }
    const int Kp = K + 4;

    float* Ws = sm;                    // 260 x Kp (rows 258,259 zero-pad)
    float* ins = sm + 260 * Kp;        // 64 x Kp
    float* bs = ins + 64 * Kp;         // 260

    for (int idx = tid; idx < 260 * Kp; idx += 256) {
        int v = idx / Kp, k = idx - v * Kp;
        Ws[idx] = (v < Vn && k < K) ? W[v * K + k] : 0.f;
    }
    for (int idx = tid; idx < 260; idx += 256)
        bs[idx] = (idx < Vn) ? Bb[idx] : 0.f;

    const int rowbase = ((bb * 3 + ch) * Rn + r) * Sn;
    for (int idx = tid; idx < 64 * Kp; idx += 256) {
        int t = idx / Kp, k = idx - t * Kp;
        float val = 0.f;
        if (k < 32) {
            val = g_outs[(size_t)(rowbase + t) * Hn + k];
        } else if (k < K) {
            int kk = k - 32;
            int chE = (kk < 64) ? 0 : 1;
            int ke = (kk < 64) ? kk : kk - 64;
            int tg = target[((bb * 3 + chE) * Rn + r) * Sn + t];
            val = emb[(chE * Vn + tg) * En + ke];
        }
        ins[idx] = val;
    }
    __syncthreads();

    float* outp = out + (size_t)rowbase * Vn;
    if (K == 32)       compute_logits<9>(Ws, ins, bs, outp, tid);
    else if (K == 96)  compute_logits<25>(Ws, ins, bs, outp, tid);
    else               compute_logits<41>(Ws, ins, bs, outp, tid);
}

// ---------------------------------------------------------------------------
// Launch
// ---------------------------------------------------------------------------
extern "C" void kernel_launch(void* const* d_in, const int* in_sizes, int n_in,
                              void* d_out, int out_size) {
    (void)in_sizes; (void)n_in; (void)out_size;
    const int*   x      = (const int*)  d_in[0];
    const int*   target = (const int*)  d_in[1];
    const float* emb    = (const float*)d_in[2];
    const float* Wih0   = (const float*)d_in[3];
    const float* WihR   = (const float*)d_in[4];
    const float* Whh    = (const float*)d_in[5];
    const float* bih    = (const float*)d_in[6];
    const float* bhh    = (const float*)d_in[7];
    const float* h2eW   = (const float*)d_in[8];
    const float* h2eb   = (const float*)d_in[9];
    const float* adpW   = (const float*)d_in[10];
    const float* adpb   = (const float*)d_in[11];
    const float* redW   = (const float*)d_in[12];
    const float* redb   = (const float*)d_in[13];
    const float* greenW = (const float*)d_in[14];
    const float* greenb = (const float*)d_in[15];
    const float* blueW  = (const float*)d_in[16];
    const float* blueb  = (const float*)d_in[17];
    float* out = (float*)d_out;

    const size_t smem_rnn = (size_t)SM_TOT * sizeof(float);          // 162800 B
    const size_t smem_log = (size_t)(260 * 164 + 64 * 164 + 260) * sizeof(float); // 213584 B

    cudaFuncSetAttribute(rnn_kernel, cudaFuncAttributeMaxDynamicSharedMemorySize,
                         (int)smem_rnn);
    cudaFuncSetAttribute(logits_kernel, cudaFuncAttributeMaxDynamicSharedMemorySize,
                         (int)smem_log);

    rnn_kernel<<<Bn, 128, smem_rnn>>>(x, emb, Wih0, WihR, Whh, bih, bhh,
                                      h2eW, h2eb, adpW, adpb);
    logits_kernel<<<dim3(Bn * Rn, 3), 256, smem_log>>>(emb, target, redW, redb,
                                                       greenW, greenb, blueW,
                                                       blueb, out);
}

// round 6
// speedup vs baseline: 1.2072x; 1.2072x over previous
#include <cuda_runtime.h>
#include <math.h>

// ---------------------------------------------------------------------------
// Problem constants
// ---------------------------------------------------------------------------
#define Bn 16
#define Hn 32
#define En 64
#define Vn 258
#define Rn 64
#define Sn 64

// Global scratch: GRU outputs per (b, channel, row, col, hidden)
__device__ float g_outs[Bn * 3 * Rn * Sn * Hn];   // 25.2 MB

// ---------------------------------------------------------------------------
// Shared-memory layout for the wavefront RNN kernel (units: floats)
// ---------------------------------------------------------------------------
constexpr int OFF_WIH0 = 0;              // 96 x 68  (layer0 Wih, K=65 pad 68)
constexpr int OFF_WIH1 = 6528;           // 96 x 36
constexpr int OFF_WIH2 = 9984;           // 96 x 36
constexpr int OFF_WHH  = 13440;          // 3 x 96 x 36
constexpr int OFF_BIH  = 23808;          // 3 x 96
constexpr int OFF_BHH  = 24096;          // 3 x 96
constexpr int OFF_H2E  = 24384;          // 65 x 36
constexpr int OFF_H2EB = 26724;          // 68
constexpr int OFF_ADP  = 26792;          // 65 x 36
constexpr int OFF_ADPB = 29132;          // 68
constexpr int OFF_COMB = 29200;          // 64 x 68  per-row comb for current col
constexpr int OFF_H0   = 33552;          // 64 x 36  layer0 hidden per row
constexpr int OFF_H1   = 35856;          // 64 x 36
constexpr int OFF_H2   = 38160;          // 65 x 36  slot r+1 = row r; slot 0 = 0
constexpr int OFF_PC   = 40500;          // 64 x 36  prev-channel out per row
constexpr int OFF_GB   = 42804;          // 64 x 129 gate buffer per row
constexpr int SM_TOT   = 51060;          // 204240 bytes

// ---------------------------------------------------------------------------
// Vectorized smem dot over N4 float4 chunks (zero-padded, 16B-aligned).
// ---------------------------------------------------------------------------
template <int N4>
__device__ __forceinline__ float dot_sm(const float* __restrict__ a,
                                        const float* __restrict__ b) {
    const float4* A = reinterpret_cast<const float4*>(a);
    const float4* Bv = reinterpret_cast<const float4*>(b);
    float s0 = 0.f, s1 = 0.f;
#pragma unroll
    for (int i = 0; i < N4; ++i) {
        float4 x = A[i], y = Bv[i];
        if (i & 1) {
            s1 = fmaf(x.x, y.x, s1); s1 = fmaf(x.y, y.y, s1);
            s1 = fmaf(x.z, y.z, s1); s1 = fmaf(x.w, y.w, s1);
        } else {
            s0 = fmaf(x.x, y.x, s0); s0 = fmaf(x.y, y.y, s0);
            s0 = fmaf(x.z, y.z, s0); s0 = fmaf(x.w, y.w, s0);
        }
    }
    return s0 + s1;
}

__device__ __forceinline__ float sigm(float x) {
    return 1.f / (1.f + __expf(-x));
}

// ---------------------------------------------------------------------------
// Kernel 1: wavefront row-RNN. 16 blocks (one per batch), 512 threads.
// At wavefront step s, all rows r in [max(0,s-63), min(63,s)] process
// column t = s - r simultaneously. Gate GEMMs: warp fixes gate g (weight
// broadcast), lanes vary over rows (conflict-free strided float4).
// ---------------------------------------------------------------------------
__global__ __launch_bounds__(512, 1)
void rnn_kernel(const int* __restrict__ x, const float* __restrict__ emb,
                const float* __restrict__ Wih0, const float* __restrict__ WihR,
                const float* __restrict__ Whh, const float* __restrict__ bih,
                const float* __restrict__ bhh, const float* __restrict__ h2eW,
                const float* __restrict__ h2eb, const float* __restrict__ adpW,
                const float* __restrict__ adpb) {
    extern __shared__ float sm[];
    const int tid = threadIdx.x;
    const int warp = tid >> 5, lane = tid & 31;
    const int b = blockIdx.x;

    for (int i = tid; i < SM_TOT; i += 512) sm[i] = 0.f;
    __syncthreads();

    for (int c = 0; c < 3; ++c) {
        // ---- load channel weights (padded strides) ----
        for (int idx = tid; idx < 96 * 65; idx += 512) {
            int g = idx / 65, k = idx - g * 65;
            sm[OFF_WIH0 + g * 68 + k] = Wih0[c * 6240 + idx];
        }
        for (int idx = tid; idx < 2 * 96 * 32; idx += 512) {
            int l = idx / 3072, rem = idx - l * 3072;
            int g = rem >> 5, k = rem & 31;
            sm[(l == 0 ? OFF_WIH1 : OFF_WIH2) + g * 36 + k] = WihR[c * 6144 + idx];
        }
        for (int idx = tid; idx < 3 * 96 * 32; idx += 512) {
            int l = idx / 3072, rem = idx - l * 3072;
            int g = rem >> 5, k = rem & 31;
            sm[OFF_WHH + l * 3456 + g * 36 + k] = Whh[c * 9216 + idx];
        }
        for (int idx = tid; idx < 288; idx += 512) {
            sm[OFF_BIH + idx] = bih[c * 288 + idx];
            sm[OFF_BHH + idx] = bhh[c * 288 + idx];
        }
        for (int idx = tid; idx < 65 * 32; idx += 512) {
            int k = idx >> 5, j = idx & 31;
            sm[OFF_H2E + k * 36 + j] = h2eW[c * 2080 + idx];
        }
        for (int idx = tid; idx < 65; idx += 512)
            sm[OFF_H2EB + idx] = h2eb[c * 65 + idx];
        if (c > 0) {
            for (int idx = tid; idx < 65 * 32; idx += 512) {
                int k = idx >> 5, j = idx & 31;
                sm[OFF_ADP + k * 36 + j] = adpW[(c - 1) * 2080 + idx];
            }
            for (int idx = tid; idx < 65; idx += 512)
                sm[OFF_ADPB + idx] = adpb[(c - 1) * 65 + idx];
        }
        __syncthreads();

        const float* gprev =
            g_outs + (size_t)(b * 3 + c - 1) * Rn * Sn * Hn;   // valid iff c>0
        float* gcur = g_outs + (size_t)(b * 3 + c) * Rn * Sn * Hn;

        for (int s = 0; s < Rn + Sn - 1; ++s) {
            const int lo = (s > 63) ? s - 63 : 0;
            const int hi = (s < 63) ? s : 63;
            const int nact = hi - lo + 1;
            const int RG = (nact + 31) >> 5;

            // ---- phase A: new-row reset + comb base + prev-channel stage ----
            if (s <= 63) {   // row s becomes active at column 0: zero hidden
                for (int i = tid; i < 108; i += 512) {
                    int which = i / 36, k = i - which * 36;
                    if (which == 0)      sm[OFF_H0 + s * 36 + k] = 0.f;
                    else if (which == 1) sm[OFF_H1 + s * 36 + k] = 0.f;
                    else                 sm[OFF_H2 + (s + 1) * 36 + k] = 0.f;
                }
            }
            for (int idx = tid; idx < nact * 65; idx += 512) {
                int j = idx / 65, k = idx - j * 65;
                int r = lo + j, t = s - r;
                float base;
                if (k < 64) {
                    int xv = x[((b * 3 + c) * Rn + r) * Sn + t];
                    base = emb[(c * Vn + xv) * En + k];
                } else {
                    base = (float)r * 0.03125f - 1.0f;
                }
                float v = base + sm[OFF_H2EB + k];
                if (c > 0) v += sm[OFF_ADPB + k];
                sm[OFF_COMB + r * 68 + k] = v;
            }
            if (c > 0) {
                for (int idx = tid; idx < nact * 32; idx += 512) {
                    int j = idx >> 5, k = idx & 31;
                    int r = lo + j, t = s - r;
                    sm[OFF_PC + r * 36 + k] = gprev[(r * Sn + t) * Hn + k];
                }
            }
            __syncthreads();

            // ---- phase B: comb += h2eW @ out(r-1,t)  (+ adpW @ prevch) ----
            for (int u = warp; u < 65 * RG; u += 16) {
                int kk = u % 65, rg = u / 65;
                int jj = rg * 32 + lane;
                int jc = (jj < nact) ? jj : nact - 1;
                int r = lo + jc;
                float acc = dot_sm<9>(sm + OFF_H2E + kk * 36, sm + OFF_H2 + r * 36);
                if (c > 0)
                    acc += dot_sm<9>(sm + OFF_ADP + kk * 36, sm + OFF_PC + r * 36);
                if (jj < nact) sm[OFF_COMB + r * 68 + kk] += acc;
            }
            __syncthreads();

            // ---- three GRU layers ----
#pragma unroll
            for (int l = 0; l < 3; ++l) {
                // gate GEMM: 96 gates x active rows
                for (int u = warp; u < 96 * RG; u += 16) {
                    int g = u % 96, rg = u / 96;
                    int jj = rg * 32 + lane;
                    int jc = (jj < nact) ? jj : nact - 1;
                    int r = lo + jc;
                    float ai, ah;
                    if (l == 0) {
                        ai = dot_sm<17>(sm + OFF_WIH0 + g * 68,
                                        sm + OFF_COMB + r * 68);
                        ah = dot_sm<9>(sm + OFF_WHH + g * 36,
                                       sm + OFF_H0 + r * 36);
                    } else if (l == 1) {
                        ai = dot_sm<9>(sm + OFF_WIH1 + g * 36,
                                       sm + OFF_H0 + r * 36);
                        ah = dot_sm<9>(sm + OFF_WHH + 3456 + g * 36,
                                       sm + OFF_H1 + r * 36);
                    } else {
                        ai = dot_sm<9>(sm + OFF_WIH2 + g * 36,
                                       sm + OFF_H1 + r * 36);
                        ah = dot_sm<9>(sm + OFF_WHH + 6912 + g * 36,
                                       sm + OFF_H2 + (r + 1) * 36);
                    }
                    ai += sm[OFF_BIH + l * 96 + g];
                    ah += sm[OFF_BHH + l * 96 + g];
                    if (jj < nact) {
                        float* gb = sm + OFF_GB + r * 129;
                        if (g < 64) gb[g] = sigm(ai + ah);
                        else { gb[g] = ai; gb[g + 32] = ah; }
                    }
                }
                __syncthreads();
                // combine: h = (1-z)*n + z*h
                for (int idx = tid; idx < nact * 32; idx += 512) {
                    int j = idx >> 5, k = idx & 31;
                    int r = lo + j;
                    const float* gb = sm + OFF_GB + r * 129;
                    float rr = gb[k], zz = gb[32 + k];
                    float nn = tanhf(gb[64 + k] + rr * gb[96 + k]);
                    float* hp;
                    if (l == 0)      hp = sm + OFF_H0 + r * 36 + k;
                    else if (l == 1) hp = sm + OFF_H1 + r * 36 + k;
                    else             hp = sm + OFF_H2 + (r + 1) * 36 + k;
                    float hn = (1.f - zz) * nn + zz * (*hp);
                    *hp = hn;
                    if (l == 2) {
                        int t = s - r;
                        gcur[(r * Sn + t) * Hn + k] = hn;
                    }
                }
                __syncthreads();
            }
        }
        __syncthreads();
    }
}

// ---------------------------------------------------------------------------
// Kernel 2: output logits (unchanged this round).
// ---------------------------------------------------------------------------
template <int N4>
__device__ __forceinline__ void compute_logits(const float* __restrict__ Ws,
                                               const float* __restrict__ ins,
                                               const float* __restrict__ bs,
                                               float* __restrict__ outp, int tid) {
    constexpr int Kp = N4 * 4;
    for (int tile = tid; tile < 65 * 32; tile += 256) {
        int vg = tile / 32, tg = tile - vg * 32;
        int t0 = tg * 2, v0 = vg * 4;
        const float4* w0 = reinterpret_cast<const float4*>(&Ws[(v0 + 0) * Kp]);
        const float4* w1 = reinterpret_cast<const float4*>(&Ws[(v0 + 1) * Kp]);
        const float4* w2 = reinterpret_cast<const float4*>(&Ws[(v0 + 2) * Kp]);
        const float4* w3 = reinterpret_cast<const float4*>(&Ws[(v0 + 3) * Kp]);
        const float4* i0 = reinterpret_cast<const float4*>(&ins[t0 * Kp]);
        const float4* i1 = reinterpret_cast<const float4*>(&ins[(t0 + 1) * Kp]);
        float a0[4] = {0.f, 0.f, 0.f, 0.f};
        float a1[4] = {0.f, 0.f, 0.f, 0.f};
#pragma unroll 4
        for (int k = 0; k < N4; ++k) {
            float4 x0 = i0[k], x1 = i1[k];
            float4 y;
            y = w0[k];
            a0[0] = fmaf(x0.x, y.x, a0[0]); a0[0] = fmaf(x0.y, y.y, a0[0]);
            a0[0] = fmaf(x0.z, y.z, a0[0]); a0[0] = fmaf(x0.w, y.w, a0[0]);
            a1[0] = fmaf(x1.x, y.x, a1[0]); a1[0] = fmaf(x1.y, y.y, a1[0]);
            a1[0] = fmaf(x1.z, y.z, a1[0]); a1[0] = fmaf(x1.w, y.w, a1[0]);
            y = w1[k];
            a0[1] = fmaf(x0.x, y.x, a0[1]); a0[1] = fmaf(x0.y, y.y, a0[1]);
            a0[1] = fmaf(x0.z, y.z, a0[1]); a0[1] = fmaf(x0.w, y.w, a0[1]);
            a1[1] = fmaf(x1.x, y.x, a1[1]); a1[1] = fmaf(x1.y, y.y, a1[1]);
            a1[1] = fmaf(x1.z, y.z, a1[1]); a1[1] = fmaf(x1.w, y.w, a1[1]);
            y = w2[k];
            a0[2] = fmaf(x0.x, y.x, a0[2]); a0[2] = fmaf(x0.y, y.y, a0[2]);
            a0[2] = fmaf(x0.z, y.z, a0[2]); a0[2] = fmaf(x0.w, y.w, a0[2]);
            a1[2] = fmaf(x1.x, y.x, a1[2]); a1[2] = fmaf(x1.y, y.y, a1[2]);
            a1[2] = fmaf(x1.z, y.z, a1[2]); a1[2] = fmaf(x1.w, y.w, a1[2]);
            y = w3[k];
            a0[3] = fmaf(x0.x, y.x, a0[3]); a0[3] = fmaf(x0.y, y.y, a0[3]);
            a0[3] = fmaf(x0.z, y.z, a0[3]); a0[3] = fmaf(x0.w, y.w, a0[3]);
            a1[3] = fmaf(x1.x, y.x, a1[3]); a1[3] = fmaf(x1.y, y.y, a1[3]);
            a1[3] = fmaf(x1.w, y.w, a1[3]); a1[3] = fmaf(x1.z, y.z, a1[3]);
        }
        int ob0 = t0 * Vn, ob1 = ob0 + Vn;
#pragma unroll
        for (int v = 0; v < 4; ++v) {
            int vv = v0 + v;
            if (vv < Vn) {
                float bv = bs[vv];
                outp[ob0 + vv] = a0[v] + bv;
                outp[ob1 + vv] = a1[v] + bv;
            }
        }
    }
}

__global__ __launch_bounds__(256, 1)
void logits_kernel(const float* __restrict__ emb, const int* __restrict__ target,
                   const float* __restrict__ W0, const float* __restrict__ b0,
                   const float* __restrict__ W1, const float* __restrict__ b1,
                   const float* __restrict__ W2, const float* __restrict__ b2,
                   float* __restrict__ out) {
    extern __shared__ float sm[];
    const int tid = threadIdx.x;
    const int ch = blockIdx.y;
    const int bb = blockIdx.x >> 6;
    const int r = blockIdx.x & 63;

    const float* W;
    const float* Bb;
    int K;
    if (ch == 0)      { W = W0; Bb = b0; K = 32; }
    else if (ch == 1) { W = W1; Bb = b1; K = 96; }
    else              { W = W2; Bb = b2; K = 160; }
    const int Kp = K + 4;

    float* Ws = sm;
    float* ins = sm + 260 * Kp;
    float* bs = ins + 64 * Kp;

    for (int idx = tid; idx < 260 * Kp; idx += 256) {
        int v = idx / Kp, k = idx - v * Kp;
        Ws[idx] = (v < Vn && k < K) ? W[v * K + k] : 0.f;
    }
    for (int idx = tid; idx < 260; idx += 256)
        bs[idx] = (idx < Vn) ? Bb[idx] : 0.f;

    const int rowbase = ((bb * 3 + ch) * Rn + r) * Sn;
    for (int idx = tid; idx < 64 * Kp; idx += 256) {
        int t = idx / Kp, k = idx - t * Kp;
        float val = 0.f;
        if (k < 32) {
            val = g_outs[(size_t)(rowbase + t) * Hn + k];
        } else if (k < K) {
            int kk = k - 32;
            int chE = (kk < 64) ? 0 : 1;
            int ke = (kk < 64) ? kk : kk - 64;
            int tg = target[((bb * 3 + chE) * Rn + r) * Sn + t];
            val = emb[(chE * Vn + tg) * En + ke];
        }
        ins[idx] = val;
    }
    __syncthreads();

    float* outp = out + (size_t)rowbase * Vn;
    if (K == 32)       compute_logits<9>(Ws, ins, bs, outp, tid);
    else if (K == 96)  compute_logits<25>(Ws, ins, bs, outp, tid);
    else               compute_logits<41>(Ws, ins, bs, outp, tid);
}

// ---------------------------------------------------------------------------
// Launch
// ---------------------------------------------------------------------------
extern "C" void kernel_launch(void* const* d_in, const int* in_sizes, int n_in,
                              void* d_out, int out_size) {
    (void)in_sizes; (void)n_in; (void)out_size;
    const int*   x      = (const int*)  d_in[0];
    const int*   target = (const int*)  d_in[1];
    const float* emb    = (const float*)d_in[2];
    const float* Wih0   = (const float*)d_in[3];
    const float* WihR   = (const float*)d_in[4];
    const float* Whh    = (const float*)d_in[5];
    const float* bih    = (const float*)d_in[6];
    const float* bhh    = (const float*)d_in[7];
    const float* h2eW   = (const float*)d_in[8];
    const float* h2eb   = (const float*)d_in[9];
    const float* adpW   = (const float*)d_in[10];
    const float* adpb   = (const float*)d_in[11];
    const float* redW   = (const float*)d_in[12];
    const float* redb   = (const float*)d_in[13];
    const float* greenW = (const float*)d_in[14];
    const float* greenb = (const float*)d_in[15];
    const float* blueW  = (const float*)d_in[16];
    const float* blueb  = (const float*)d_in[17];
    float* out = (float*)d_out;

    const size_t smem_rnn = (size_t)SM_TOT * sizeof(float);                       // 204240 B
    const size_t smem_log = (size_t)(260 * 164 + 64 * 164 + 260) * sizeof(float); // 213584 B

    cudaFuncSetAttribute(rnn_kernel, cudaFuncAttributeMaxDynamicSharedMemorySize,
                         (int)smem_rnn);
    cudaFuncSetAttribute(logits_kernel, cudaFuncAttributeMaxDynamicSharedMemorySize,
                         (int)smem_log);

    rnn_kernel<<<Bn, 512, smem_rnn>>>(x, emb, Wih0, WihR, Whh, bih, bhh,
                                      h2eW, h2eb, adpW, adpb);
    logits_kernel<<<dim3(Bn * Rn, 3), 256, smem_log>>>(emb, target, redW, redb,
                                                       greenW, greenb, blueW,
                                                       blueb, out);
}

// round 7
// speedup vs baseline: 1.4804x; 1.2263x over previous
#include <cuda_runtime.h>
#include <math.h>

// ---------------------------------------------------------------------------
// Problem constants
// ---------------------------------------------------------------------------
#define Bn 16
#define Hn 32
#define En 64
#define Vn 258
#define Rn 64
#define Sn 64

// Global scratch: GRU outputs per (b, channel, row, col, hidden)
__device__ float g_outs[Bn * 3 * Rn * Sn * Hn];   // 25.2 MB

// ---------------------------------------------------------------------------
// Shared-memory layout (floats)
// ---------------------------------------------------------------------------
constexpr int OFF_WIH0 = 0;              // 96 x 68
constexpr int OFF_WIH1 = 6528;           // 96 x 36
constexpr int OFF_WIH2 = 9984;           // 96 x 36
constexpr int OFF_WHH  = 13440;          // 3 x 96 x 36
constexpr int OFF_BIH  = 23808;          // 3 x 96
constexpr int OFF_BHH  = 24096;          // 3 x 96
constexpr int OFF_H2E  = 24384;          // 65 x 36
constexpr int OFF_H2EB = 26724;          // 68
constexpr int OFF_ADP  = 26792;          // 65 x 36
constexpr int OFF_ADPB = 29132;          // 68
constexpr int OFF_COMB = 29200;          // 64 x 68
constexpr int OFF_H0   = 33552;          // 64 x 36
constexpr int OFF_H1   = 35856;          // 64 x 36
constexpr int OFF_H2   = 38160;          // 65 x 36 (slot r+1 = row r's out)
constexpr int OFF_GB   = 40500;          // 64 x 129
constexpr int SM_TOT   = 48756;          // 195024 bytes

// ---------------------------------------------------------------------------
// Dot helpers: weight row broadcast from smem, input resident in registers.
// ---------------------------------------------------------------------------
__device__ __forceinline__ float dot8r(const float* __restrict__ w,
                                       const float4 x[8]) {
    const float4* W = reinterpret_cast<const float4*>(w);
    float s0 = 0.f, s1 = 0.f;
#pragma unroll
    for (int i = 0; i < 8; ++i) {
        float4 y = W[i];
        if (i & 1) {
            s1 = fmaf(x[i].x, y.x, s1); s1 = fmaf(x[i].y, y.y, s1);
            s1 = fmaf(x[i].z, y.z, s1); s1 = fmaf(x[i].w, y.w, s1);
        } else {
            s0 = fmaf(x[i].x, y.x, s0); s0 = fmaf(x[i].y, y.y, s0);
            s0 = fmaf(x[i].z, y.z, s0); s0 = fmaf(x[i].w, y.w, s0);
        }
    }
    return s0 + s1;
}

__device__ __forceinline__ float dot17r(const float* __restrict__ w,
                                        const float4 x[17]) {
    const float4* W = reinterpret_cast<const float4*>(w);
    float s0 = 0.f, s1 = 0.f;
#pragma unroll
    for (int i = 0; i < 17; ++i) {
        float4 y = W[i];
        if (i & 1) {
            s1 = fmaf(x[i].x, y.x, s1); s1 = fmaf(x[i].y, y.y, s1);
            s1 = fmaf(x[i].z, y.z, s1); s1 = fmaf(x[i].w, y.w, s1);
        } else {
            s0 = fmaf(x[i].x, y.x, s0); s0 = fmaf(x[i].y, y.y, s0);
            s0 = fmaf(x[i].z, y.z, s0); s0 = fmaf(x[i].w, y.w, s0);
        }
    }
    return s0 + s1;
}

__device__ __forceinline__ float sigm(float x) {
    return 1.f / (1.f + __expf(-x));
}

// ---------------------------------------------------------------------------
// Kernel 1: wavefront row-RNN, register-blocked gate GEMMs.
// 16 blocks (one per batch), 512 threads (16 warps).
// Wavefront step s: rows r in [max(0,s-63), min(63,s)] process col t = s - r.
// Gate phase: warp owns a 32-row group (lane = row), inputs in registers,
// loops over a contiguous gate slice with broadcast weight loads.
// ---------------------------------------------------------------------------
__global__ __launch_bounds__(512, 1)
void rnn_kernel(const int* __restrict__ x, const float* __restrict__ emb,
                const float* __restrict__ Wih0, const float* __restrict__ WihR,
                const float* __restrict__ Whh, const float* __restrict__ bih,
                const float* __restrict__ bhh, const float* __restrict__ h2eW,
                const float* __restrict__ h2eb, const float* __restrict__ adpW,
                const float* __restrict__ adpb) {
    extern __shared__ float sm[];
    const int tid = threadIdx.x;
    const int warp = tid >> 5, lane = tid & 31;
    const int b = blockIdx.x;

    for (int i = tid; i < SM_TOT; i += 512) sm[i] = 0.f;
    __syncthreads();

    for (int c = 0; c < 3; ++c) {
        // ---- load channel weights (padded strides) ----
        for (int idx = tid; idx < 96 * 65; idx += 512) {
            int g = idx / 65, k = idx - g * 65;
            sm[OFF_WIH0 + g * 68 + k] = Wih0[c * 6240 + idx];
        }
        for (int idx = tid; idx < 2 * 96 * 32; idx += 512) {
            int l = idx / 3072, rem = idx - l * 3072;
            int g = rem >> 5, k = rem & 31;
            sm[(l == 0 ? OFF_WIH1 : OFF_WIH2) + g * 36 + k] = WihR[c * 6144 + idx];
        }
        for (int idx = tid; idx < 3 * 96 * 32; idx += 512) {
            int l = idx / 3072, rem = idx - l * 3072;
            int g = rem >> 5, k = rem & 31;
            sm[OFF_WHH + l * 3456 + g * 36 + k] = Whh[c * 9216 + idx];
        }
        for (int idx = tid; idx < 288; idx += 512) {
            sm[OFF_BIH + idx] = bih[c * 288 + idx];
            sm[OFF_BHH + idx] = bhh[c * 288 + idx];
        }
        for (int idx = tid; idx < 65 * 32; idx += 512) {
            int k = idx >> 5, j = idx & 31;
            sm[OFF_H2E + k * 36 + j] = h2eW[c * 2080 + idx];
        }
        for (int idx = tid; idx < 65; idx += 512)
            sm[OFF_H2EB + idx] = h2eb[c * 65 + idx];
        if (c > 0) {
            for (int idx = tid; idx < 65 * 32; idx += 512) {
                int k = idx >> 5, j = idx & 31;
                sm[OFF_ADP + k * 36 + j] = adpW[(c - 1) * 2080 + idx];
            }
            for (int idx = tid; idx < 65; idx += 512)
                sm[OFF_ADPB + idx] = adpb[(c - 1) * 65 + idx];
        }
        __syncthreads();

        const float* gprev = g_outs + (size_t)(b * 3 + c - 1) * Rn * Sn * Hn;
        float* gcur = g_outs + (size_t)(b * 3 + c) * Rn * Sn * Hn;

        for (int s = 0; s < Rn + Sn - 1; ++s) {
            const int lo = (s > 63) ? s - 63 : 0;
            const int hi = (s < 63) ? s : 63;
            const int nact = hi - lo + 1;
            const int RG = (nact > 32) ? 2 : 1;
            const int wpr = 16 / RG;            // warps per rowgroup
            const int rg = (RG == 2) ? (warp & 1) : 0;
            const int slice = (RG == 2) ? (warp >> 1) : warp;

            const int jj = rg * 32 + lane;
            const bool valid = jj < nact;
            const int r = lo + (valid ? jj : (nact - 1));
            const int t = s - r;

            // ============ phase 1: comb (+ new-row reset) ============
            if (s <= 63 && tid < 108) {
                int which = tid / 36, k = tid - which * 36;
                if (which == 0)      sm[OFF_H0 + s * 36 + k] = 0.f;
                else if (which == 1) sm[OFF_H1 + s * 36 + k] = 0.f;
                else                 sm[OFF_H2 + (s + 1) * 36 + k] = 0.f;
            }
            {
                float4 h2r[8], pcr[8];
                const float4* hp =
                    reinterpret_cast<const float4*>(sm + OFF_H2 + r * 36);
#pragma unroll
                for (int i = 0; i < 8; ++i) h2r[i] = hp[i];
                if (c > 0) {
                    const float4* pp = reinterpret_cast<const float4*>(
                        gprev + (size_t)(r * Sn + t) * Hn);
#pragma unroll
                    for (int i = 0; i < 8; ++i) pcr[i] = pp[i];
                }
                const int xv = x[((b * 3 + c) * Rn + r) * Sn + t];
                const float* erow = emb + (size_t)(c * Vn + xv) * En;
                const float rowfeat = (float)r * 0.03125f - 1.0f;

                for (int kg = slice; kg < 17; kg += wpr) {
                    const int k0 = kg * 4;
                    float4 base;
                    if (kg < 16)
                        base = *reinterpret_cast<const float4*>(erow + k0);
                    else
                        base = make_float4(rowfeat, 0.f, 0.f, 0.f);
                    float o[4];
#pragma unroll
                    for (int q = 0; q < 4; ++q) {
                        const int k = k0 + q;
                        if (kg == 16 && q > 0) { o[q] = 0.f; continue; }
                        float bq = (q == 0) ? base.x : (q == 1) ? base.y
                                 : (q == 2) ? base.z : base.w;
                        float v = bq + sm[OFF_H2EB + k] +
                                  dot8r(sm + OFF_H2E + k * 36, h2r);
                        if (c > 0)
                            v += sm[OFF_ADPB + k] +
                                 dot8r(sm + OFF_ADP + k * 36, pcr);
                        o[q] = v;
                    }
                    if (valid)
                        *reinterpret_cast<float4*>(sm + OFF_COMB + r * 68 + k0) =
                            make_float4(o[0], o[1], o[2], o[3]);
                }
            }
            __syncthreads();

            // ============ layer 0 ============
            {
                float4 cb[17], h0r[8];
                const float4* cp =
                    reinterpret_cast<const float4*>(sm + OFF_COMB + r * 68);
#pragma unroll
                for (int i = 0; i < 17; ++i) cb[i] = cp[i];
                const float4* hp =
                    reinterpret_cast<const float4*>(sm + OFF_H0 + r * 36);
#pragma unroll
                for (int i = 0; i < 8; ++i) h0r[i] = hp[i];

                const int gpw = 96 / wpr;
                const int g0 = slice * gpw;
                float* gb = sm + OFF_GB + r * 129;
                for (int g = g0; g < g0 + gpw; ++g) {
                    float ai = sm[OFF_BIH + g] +
                               dot17r(sm + OFF_WIH0 + g * 68, cb);
                    float ah = sm[OFF_BHH + g] +
                               dot8r(sm + OFF_WHH + g * 36, h0r);
                    if (valid) {
                        if (g < 64) gb[g] = sigm(ai + ah);
                        else { gb[g] = ai; gb[g + 32] = ah; }
                    }
                }
            }
            __syncthreads();
            for (int idx = tid; idx < nact * 32; idx += 512) {
                int j = idx >> 5, k = idx & 31;
                int rr_ = lo + j;
                const float* gb = sm + OFF_GB + rr_ * 129;
                float rv = gb[k], zv = gb[32 + k];
                float nn = tanhf(gb[64 + k] + rv * gb[96 + k]);
                float* hp = sm + OFF_H0 + rr_ * 36 + k;
                *hp = (1.f - zv) * nn + zv * (*hp);
            }
            __syncthreads();

            // ============ layer 1 ============
            {
                float4 h0r[8], h1r[8];
                const float4* p0 =
                    reinterpret_cast<const float4*>(sm + OFF_H0 + r * 36);
                const float4* p1 =
                    reinterpret_cast<const float4*>(sm + OFF_H1 + r * 36);
#pragma unroll
                for (int i = 0; i < 8; ++i) { h0r[i] = p0[i]; h1r[i] = p1[i]; }

                const int gpw = 96 / wpr;
                const int g0 = slice * gpw;
                float* gb = sm + OFF_GB + r * 129;
                for (int g = g0; g < g0 + gpw; ++g) {
                    float ai = sm[OFF_BIH + 96 + g] +
                               dot8r(sm + OFF_WIH1 + g * 36, h0r);
                    float ah = sm[OFF_BHH + 96 + g] +
                               dot8r(sm + OFF_WHH + 3456 + g * 36, h1r);
                    if (valid) {
                        if (g < 64) gb[g] = sigm(ai + ah);
                        else { gb[g] = ai; gb[g + 32] = ah; }
                    }
                }
            }
            __syncthreads();
            for (int idx = tid; idx < nact * 32; idx += 512) {
                int j = idx >> 5, k = idx & 31;
                int rr_ = lo + j;
                const float* gb = sm + OFF_GB + rr_ * 129;
                float rv = gb[k], zv = gb[32 + k];
                float nn = tanhf(gb[64 + k] + rv * gb[96 + k]);
                float* hp = sm + OFF_H1 + rr_ * 36 + k;
                *hp = (1.f - zv) * nn + zv * (*hp);
            }
            __syncthreads();

            // ============ layer 2 ============
            {
                float4 h1r[8], h2r[8];
                const float4* p1 =
                    reinterpret_cast<const float4*>(sm + OFF_H1 + r * 36);
                const float4* p2 =
                    reinterpret_cast<const float4*>(sm + OFF_H2 + (r + 1) * 36);
#pragma unroll
                for (int i = 0; i < 8; ++i) { h1r[i] = p1[i]; h2r[i] = p2[i]; }

                const int gpw = 96 / wpr;
                const int g0 = slice * gpw;
                float* gb = sm + OFF_GB + r * 129;
                for (int g = g0; g < g0 + gpw; ++g) {
                    float ai = sm[OFF_BIH + 192 + g] +
                               dot8r(sm + OFF_WIH2 + g * 36, h1r);
                    float ah = sm[OFF_BHH + 192 + g] +
                               dot8r(sm + OFF_WHH + 6912 + g * 36, h2r);
                    if (valid) {
                        if (g < 64) gb[g] = sigm(ai + ah);
                        else { gb[g] = ai; gb[g + 32] = ah; }
                    }
                }
            }
            __syncthreads();
            for (int idx = tid; idx < nact * 32; idx += 512) {
                int j = idx >> 5, k = idx & 31;
                int rr_ = lo + j;
                const float* gb = sm + OFF_GB + rr_ * 129;
                float rv = gb[k], zv = gb[32 + k];
                float nn = tanhf(gb[64 + k] + rv * gb[96 + k]);
                float* hp = sm + OFF_H2 + (rr_ + 1) * 36 + k;
                float hn = (1.f - zv) * nn + zv * (*hp);
                *hp = hn;
                gcur[(size_t)(rr_ * Sn + (s - rr_)) * Hn + k] = hn;
            }
            __syncthreads();
        }
        __syncthreads();
    }
}

// ---------------------------------------------------------------------------
// Kernel 2: output logits. 512 threads now (occupancy/latency hiding).
// ---------------------------------------------------------------------------
template <int N4>
__device__ __forceinline__ void compute_logits(const float* __restrict__ Ws,
                                               const float* __restrict__ ins,
                                               const float* __restrict__ bs,
                                               float* __restrict__ outp, int tid) {
    constexpr int Kp = N4 * 4;
    for (int tile = tid; tile < 65 * 32; tile += 512) {
        int vg = tile / 32, tg = tile - vg * 32;
        int t0 = tg * 2, v0 = vg * 4;
        const float4* w0 = reinterpret_cast<const float4*>(&Ws[(v0 + 0) * Kp]);
        const float4* w1 = reinterpret_cast<const float4*>(&Ws[(v0 + 1) * Kp]);
        const float4* w2 = reinterpret_cast<const float4*>(&Ws[(v0 + 2) * Kp]);
        const float4* w3 = reinterpret_cast<const float4*>(&Ws[(v0 + 3) * Kp]);
        const float4* i0 = reinterpret_cast<const float4*>(&ins[t0 * Kp]);
        const float4* i1 = reinterpret_cast<const float4*>(&ins[(t0 + 1) * Kp]);
        float a0[4] = {0.f, 0.f, 0.f, 0.f};
        float a1[4] = {0.f, 0.f, 0.f, 0.f};
#pragma unroll 4
        for (int k = 0; k < N4; ++k) {
            float4 x0 = i0[k], x1 = i1[k];
            float4 y;
            y = w0[k];
            a0[0] = fmaf(x0.x, y.x, a0[0]); a0[0] = fmaf(x0.y, y.y, a0[0]);
            a0[0] = fmaf(x0.z, y.z, a0[0]); a0[0] = fmaf(x0.w, y.w, a0[0]);
            a1[0] = fmaf(x1.x, y.x, a1[0]); a1[0] = fmaf(x1.y, y.y, a1[0]);
            a1[0] = fmaf(x1.z, y.z, a1[0]); a1[0] = fmaf(x1.w, y.w, a1[0]);
            y = w1[k];
            a0[1] = fmaf(x0.x, y.x, a0[1]); a0[1] = fmaf(x0.y, y.y, a0[1]);
            a0[1] = fmaf(x0.z, y.z, a0[1]); a0[1] = fmaf(x0.w, y.w, a0[1]);
            a1[1] = fmaf(x1.x, y.x, a1[1]); a1[1] = fmaf(x1.y, y.y, a1[1]);
            a1[1] = fmaf(x1.z, y.z, a1[1]); a1[1] = fmaf(x1.w, y.w, a1[1]);
            y = w2[k];
            a0[2] = fmaf(x0.x, y.x, a0[2]); a0[2] = fmaf(x0.y, y.y, a0[2]);
            a0[2] = fmaf(x0.z, y.z, a0[2]); a0[2] = fmaf(x0.w, y.w, a0[2]);
            a1[2] = fmaf(x1.x, y.x, a1[2]); a1[2] = fmaf(x1.y, y.y, a1[2]);
            a1[2] = fmaf(x1.z, y.z, a1[2]); a1[2] = fmaf(x1.w, y.w, a1[2]);
            y = w3[k];
            a0[3] = fmaf(x0.x, y.x, a0[3]); a0[3] = fmaf(x0.y, y.y, a0[3]);
            a0[3] = fmaf(x0.z, y.z, a0[3]); a0[3] = fmaf(x0.w, y.w, a0[3]);
            a1[3] = fmaf(x1.x, y.x, a1[3]); a1[3] = fmaf(x1.y, y.y, a1[3]);
            a1[3] = fmaf(x1.z, y.z, a1[3]); a1[3] = fmaf(x1.w, y.w, a1[3]);
        }
        int ob0 = t0 * Vn, ob1 = ob0 + Vn;
#pragma unroll
        for (int v = 0; v < 4; ++v) {
            int vv = v0 + v;
            if (vv < Vn) {
                float bv = bs[vv];
                outp[ob0 + vv] = a0[v] + bv;
                outp[ob1 + vv] = a1[v] + bv;
            }
        }
    }
}

__global__ __launch_bounds__(512, 1)
void logits_kernel(const float* __restrict__ emb, const int* __restrict__ target,
                   const float* __restrict__ W0, const float* __restrict__ b0,
                   const float* __restrict__ W1, const float* __restrict__ b1,
                   const float* __restrict__ W2, const float* __restrict__ b2,
                   float* __restrict__ out) {
    extern __shared__ float sm[];
    const int tid = threadIdx.x;
    const int ch = blockIdx.y;
    const int bb = blockIdx.x >> 6;
    const int r = blockIdx.x & 63;

    const float* W;
    const float* Bb;
    int K;
    if (ch == 0)      { W = W0; Bb = b0; K = 32; }
    else if (ch == 1) { W = W1; Bb = b1; K = 96; }
    else              { W = W2; Bb = b2; K = 160; }
    const int Kp = K + 4;

    float* Ws = sm;
    float* ins = sm + 260 * Kp;
    float* bs = ins + 64 * Kp;

    for (int idx = tid; idx < 260 * Kp; idx += 512) {
        int v = idx / Kp, k = idx - v * Kp;
        Ws[idx] = (v < Vn && k < K) ? W[v * K + k] : 0.f;
    }
    for (int idx = tid; idx < 260; idx += 512)
        bs[idx] = (idx < Vn) ? Bb[idx] : 0.f;

    const int rowbase = ((bb * 3 + ch) * Rn + r) * Sn;
    for (int idx = tid; idx < 64 * Kp; idx += 512) {
        int t = idx / Kp, k = idx - t * Kp;
        float val = 0.f;
        if (k < 32) {
            val = g_outs[(size_t)(rowbase + t) * Hn + k];
        } else if (k < K) {
            int kk = k - 32;
            int chE = (kk < 64) ? 0 : 1;
            int ke = (kk < 64) ? kk : kk - 64;
            int tg = target[((bb * 3 + chE) * Rn + r) * Sn + t];
            val = emb[(size_t)(chE * Vn + tg) * En + ke];
        }
        ins[idx] = val;
    }
    __syncthreads();

    float* outp = out + (size_t)rowbase * Vn;
    if (K == 32)       compute_logits<9>(Ws, ins, bs, outp, tid);
    else if (K == 96)  compute_logits<25>(Ws, ins, bs, outp, tid);
    else               compute_logits<41>(Ws, ins, bs, outp, tid);
}

// ---------------------------------------------------------------------------
// Launch
// ---------------------------------------------------------------------------
extern "C" void kernel_launch(void* const* d_in, const int* in_sizes, int n_in,
                              void* d_out, int out_size) {
    (void)in_sizes; (void)n_in; (void)out_size;
    const int*   x      = (const int*)  d_in[0];
    const int*   target = (const int*)  d_in[1];
    const float* emb    = (const float*)d_in[2];
    const float* Wih0   = (const float*)d_in[3];
    const float* WihR   = (const float*)d_in[4];
    const float* Whh    = (const float*)d_in[5];
    const float* bih    = (const float*)d_in[6];
    const float* bhh    = (const float*)d_in[7];
    const float* h2eW   = (const float*)d_in[8];
    const float* h2eb   = (const float*)d_in[9];
    const float* adpW   = (const float*)d_in[10];
    const float* adpb   = (const float*)d_in[11];
    const float* redW   = (const float*)d_in[12];
    const float* redb   = (const float*)d_in[13];
    const float* greenW = (const float*)d_in[14];
    const float* greenb = (const float*)d_in[15];
    const float* blueW  = (const float*)d_in[16];
    const float* blueb  = (const float*)d_in[17];
    float* out = (float*)d_out;

    const size_t smem_rnn = (size_t)SM_TOT * sizeof(float);                       // 195024 B
    const size_t smem_log = (size_t)(260 * 164 + 64 * 164 + 260) * sizeof(float); // 213584 B

    cudaFuncSetAttribute(rnn_kernel, cudaFuncAttributeMaxDynamicSharedMemorySize,
                         (int)smem_rnn);
    cudaFuncSetAttribute(logits_kernel, cudaFuncAttributeMaxDynamicSharedMemorySize,
                         (int)smem_log);

    rnn_kernel<<<Bn, 512, smem_rnn>>>(x, emb, Wih0, WihR, Whh, bih, bhh,
                                      h2eW, h2eb, adpW, adpb);
    logits_kernel<<<dim3(Bn * Rn, 3), 512, smem_log>>>(emb, target, redW, redb,
                                                       greenW, greenb, blueW,
                                                       blueb, out);
}

// round 8
// speedup vs baseline: 2.7002x; 1.8240x over previous
#include <cuda_runtime.h>
#include <math.h>

// ---------------------------------------------------------------------------
// Problem constants
// ---------------------------------------------------------------------------
#define Bn 16
#define Hn 32
#define En 64
#define Vn 258
#define Rn 64
#define Sn 64

// Global scratch (no allocation): GRU outputs + folded weight tables
__device__ float g_outs[Bn * 3 * Rn * Sn * Hn];   // 25.2 MB
__device__ float g_T0[3 * 258 * 96];              // Wih0 @ emb table
__device__ float g_M1[3 * 96 * 32];               // Wih0 @ h2eW
__device__ float g_M2[2 * 96 * 32];               // Wih0 @ adpW
__device__ float g_b0[3 * 96];                    // bih0 + Wih0@(h2eb[+adpb])

// ---------------------------------------------------------------------------
// Packed f32x2 helpers
// ---------------------------------------------------------------------------
union P4 { float4 f; ulonglong2 u; };

__device__ __forceinline__ void fma2(unsigned long long& acc,
                                     unsigned long long a,
                                     unsigned long long b) {
    asm("fma.rn.f32x2 %0, %1, %2, %0;" : "+l"(acc) : "l"(a), "l"(b));
}
__device__ __forceinline__ float red2(unsigned long long acc) {
    float x, y;
    asm("mov.b64 {%0, %1}, %2;" : "=f"(x), "=f"(y) : "l"(acc));
    return x + y;
}
// 32-float dot: weight row broadcast from smem, input cached in registers.
__device__ __forceinline__ void dot32(const float* __restrict__ w,
                                      const P4 x[8], unsigned long long& acc) {
    const ulonglong2* W = reinterpret_cast<const ulonglong2*>(w);
#pragma unroll
    for (int i = 0; i < 8; ++i) {
        ulonglong2 wv = W[i];
        fma2(acc, wv.x, x[i].u.x);
        fma2(acc, wv.y, x[i].u.y);
    }
}
__device__ __forceinline__ void load8s(const float* __restrict__ p, P4 x[8]) {
    const float4* q = reinterpret_cast<const float4*>(p);
#pragma unroll
    for (int i = 0; i < 8; ++i) x[i].f = q[i];
}
__device__ __forceinline__ float sigm(float x) {
    return 1.f / (1.f + __expf(-x));
}

// ---------------------------------------------------------------------------
// Pre-kernel: fold the comb linear algebra into tables (runs once, ~20us)
// ---------------------------------------------------------------------------
__global__ void pre_kernel(const float* __restrict__ emb,
                           const float* __restrict__ Wih0,
                           const float* __restrict__ h2eW,
                           const float* __restrict__ h2eb,
                           const float* __restrict__ adpW,
                           const float* __restrict__ adpb,
                           const float* __restrict__ bih) {
    int idx = blockIdx.x * 256 + threadIdx.x;
    if (idx < 74304) {                       // T0[c][v][g] = Wih0[c][g,:64] . emb[c][v]
        int c = idx / 24768, rem = idx % 24768;
        int v = rem / 96, g = rem % 96;
        const float* w = Wih0 + c * 6240 + g * 65;
        const float* e = emb + (size_t)(c * 258 + v) * 64;
        float s = 0.f;
        for (int j = 0; j < 64; ++j) s = fmaf(w[j], e[j], s);
        g_T0[idx] = s;
    } else if (idx < 74304 + 9216) {         // M1[c][g][j]
        int i = idx - 74304;
        int c = i / 3072, rem = i % 3072, g = rem / 32, j = rem % 32;
        const float* w = Wih0 + c * 6240 + g * 65;
        float s = 0.f;
        for (int e = 0; e < 65; ++e) s = fmaf(w[e], h2eW[c * 2080 + e * 32 + j], s);
        g_M1[i] = s;
    } else if (idx < 74304 + 9216 + 6144) {  // M2[c2][g][j], channel c2+1
        int i = idx - 74304 - 9216;
        int c2 = i / 3072, rem = i % 3072, g = rem / 32, j = rem % 32;
        const float* w = Wih0 + (c2 + 1) * 6240 + g * 65;
        float s = 0.f;
        for (int e = 0; e < 65; ++e) s = fmaf(w[e], adpW[c2 * 2080 + e * 32 + j], s);
        g_M2[i] = s;
    } else if (idx < 74304 + 9216 + 6144 + 288) {   // b0[c][g]
        int i = idx - 74304 - 9216 - 6144;
        int c = i / 96, g = i % 96;
        const float* w = Wih0 + c * 6240 + g * 65;
        float s = bih[c * 288 + g];          // bih[c][0][g]
        for (int e = 0; e < 65; ++e) s = fmaf(w[e], h2eb[c * 65 + e], s);
        if (c > 0)
            for (int e = 0; e < 65; ++e) s = fmaf(w[e], adpb[(c - 1) * 65 + e], s);
        g_b0[i] = s;
    }
}

// ---------------------------------------------------------------------------
// Shared-memory layout for the RNN kernel (floats)
// ---------------------------------------------------------------------------
constexpr int OFF_M1   = 0;        // 96 x 32
constexpr int OFF_M2   = 3072;     // 96 x 32
constexpr int OFF_WHH0 = 6144;     // 96 x 32
constexpr int OFF_WIH1 = 9216;
constexpr int OFF_WHH1 = 12288;
constexpr int OFF_WIH2 = 15360;
constexpr int OFF_WHH2 = 18432;
constexpr int OFF_B    = 21504;    // 3 x 128: l*128 + {rz 0..63, ni 64..95, nh 96..127}
constexpr int OFF_W64  = 21888;    // 96
constexpr int OFF_H0   = 21984;    // 2 x (64 x 36) ping-pong
constexpr int OFF_H1   = 26592;    // 2 x (64 x 36)
constexpr int OFF_H2   = 31200;    // 2 x (65 x 36): slot r+1 = row r; slot 0 = 0
constexpr int SM_TOT   = 35880;    // 143,520 bytes

// ---------------------------------------------------------------------------
// Kernel 1: wavefront row-RNN, fused gates, f32x2 dots, folded comb.
// 16 blocks (one per batch), 512 threads. Step s: rows [max(0,s-63),min(63,s)]
// process column t=s-r. Warp-task = one hidden unit k for 32 rows (lanes).
// ---------------------------------------------------------------------------
__global__ __launch_bounds__(512, 1)
void rnn_kernel(const int* __restrict__ x, const float* __restrict__ Wih0,
                const float* __restrict__ WihR, const float* __restrict__ Whh,
                const float* __restrict__ bih, const float* __restrict__ bhh) {
    extern __shared__ float sm[];
    const int tid = threadIdx.x;
    const int warp = tid >> 5, lane = tid & 31;
    const int b = blockIdx.x;

    for (int c = 0; c < 3; ++c) {
        const bool haspc = (c > 0);
        // ---- stage weights ----
        for (int i = tid; i < 3072; i += 512) {
            sm[OFF_M1 + i]   = g_M1[c * 3072 + i];
            sm[OFF_WHH0 + i] = Whh[c * 9216 + i];
            sm[OFF_WIH1 + i] = WihR[c * 6144 + i];
            sm[OFF_WHH1 + i] = Whh[c * 9216 + 3072 + i];
            sm[OFF_WIH2 + i] = WihR[c * 6144 + 3072 + i];
            sm[OFF_WHH2 + i] = Whh[c * 9216 + 6144 + i];
            if (haspc) sm[OFF_M2 + i] = g_M2[(c - 1) * 3072 + i];
        }
        for (int i = tid; i < 384; i += 512) {
            int l = i >> 7, o = i & 127;
            float v;
            if (o < 64)
                v = ((l == 0) ? g_b0[c * 96 + o] : bih[(c * 3 + l) * 96 + o]) +
                    bhh[(c * 3 + l) * 96 + o];
            else if (o < 96) {
                int g = 64 + (o - 64);
                v = (l == 0) ? g_b0[c * 96 + g] : bih[(c * 3 + l) * 96 + g];
            } else {
                int g = 64 + (o - 96);
                v = bhh[(c * 3 + l) * 96 + g];
            }
            sm[OFF_B + i] = v;
        }
        for (int g = tid; g < 96; g += 512)
            sm[OFF_W64 + g] = Wih0[c * 6240 + g * 65 + 64];
        // zero all H state (both buffers)
        for (int i = tid; i < 13896; i += 512) sm[OFF_H0 + i] = 0.f;
        __syncthreads();

        const float* gprev = g_outs + (size_t)(b * 3 + c - 1) * Rn * Sn * Hn;
        float* gcur = g_outs + (size_t)(b * 3 + c) * Rn * Sn * Hn;
        const int xbase = (b * 3 + c) * Rn * Sn;
        const float* t0base = g_T0 + (size_t)c * 258 * 96;

        for (int s = 0; s < Rn + Sn - 1; ++s) {
            const int pong = s & 1, next = 1 - pong;
            const int lo = (s > 63) ? s - 63 : 0;
            const int hi = (s < 63) ? s : 63;
            const int nact = hi - lo + 1;
            const int RG = (nact > 32) ? 2 : 1;
            const int wpr = (RG == 2) ? 8 : 16;
            const int rg = (RG == 2) ? (warp & 1) : 0;
            const int slice = (RG == 2) ? (warp >> 1) : warp;

            const int jj = rg * 32 + lane;
            const bool valid = jj < nact;
            const int r = lo + (valid ? jj : (nact - 1));
            const int t = s - r;

            // ================= layer 0 (comb folded in) =================
            {
                P4 h2p[8], h0c[8], pcc[8];
                load8s(sm + OFF_H2 + pong * 2340 + r * 36, h2p);
                load8s(sm + OFF_H0 + pong * 2304 + r * 36, h0c);
                if (haspc) {
                    const float4* pp = reinterpret_cast<const float4*>(
                        gprev + ((size_t)r * Sn + t) * Hn);
#pragma unroll
                    for (int i = 0; i < 8; ++i) pcc[i].f = pp[i];
                }
                const int xv = x[xbase + r * Sn + t];
                const float* t0p = t0base + xv * 96;
                const float rf = (float)r * 0.03125f - 1.0f;

                for (int k = slice; k < 32; k += wpr) {
                    float t0r = t0p[k], t0z = t0p[k + 32], t0n = t0p[k + 64];
                    unsigned long long ar = 0ull, az = 0ull, ani = 0ull, anh = 0ull;
                    dot32(sm + OFF_M1 + k * 32, h2p, ar);
                    dot32(sm + OFF_M1 + (k + 32) * 32, h2p, az);
                    dot32(sm + OFF_M1 + (k + 64) * 32, h2p, ani);
                    if (haspc) {
                        dot32(sm + OFF_M2 + k * 32, pcc, ar);
                        dot32(sm + OFF_M2 + (k + 32) * 32, pcc, az);
                        dot32(sm + OFF_M2 + (k + 64) * 32, pcc, ani);
                    }
                    dot32(sm + OFF_WHH0 + k * 32, h0c, ar);
                    dot32(sm + OFF_WHH0 + (k + 32) * 32, h0c, az);
                    dot32(sm + OFF_WHH0 + (k + 64) * 32, h0c, anh);
                    float vr = red2(ar) + t0r + rf * sm[OFF_W64 + k] + sm[OFF_B + k];
                    float vz = red2(az) + t0z + rf * sm[OFF_W64 + k + 32] +
                               sm[OFF_B + k + 32];
                    float vni = red2(ani) + t0n + rf * sm[OFF_W64 + k + 64] +
                                sm[OFF_B + 64 + k];
                    float vnh = red2(anh) + sm[OFF_B + 96 + k];
                    float rr = sigm(vr), zz = sigm(vz);
                    float nn = tanhf(vni + rr * vnh);
                    float hold = sm[OFF_H0 + pong * 2304 + r * 36 + k];
                    float hnew = (1.f - zz) * nn + zz * hold;
                    if (valid) sm[OFF_H0 + next * 2304 + r * 36 + k] = hnew;
                }
            }
            __syncthreads();

            // ================= layer 1 =================
            {
                P4 h0n[8], h1c[8];
                load8s(sm + OFF_H0 + next * 2304 + r * 36, h0n);
                load8s(sm + OFF_H1 + pong * 2304 + r * 36, h1c);
                for (int k = slice; k < 32; k += wpr) {
                    unsigned long long ar = 0ull, az = 0ull, ani = 0ull, anh = 0ull;
                    dot32(sm + OFF_WIH1 + k * 32, h0n, ar);
                    dot32(sm + OFF_WHH1 + k * 32, h1c, ar);
                    dot32(sm + OFF_WIH1 + (k + 32) * 32, h0n, az);
                    dot32(sm + OFF_WHH1 + (k + 32) * 32, h1c, az);
                    dot32(sm + OFF_WIH1 + (k + 64) * 32, h0n, ani);
                    dot32(sm + OFF_WHH1 + (k + 64) * 32, h1c, anh);
                    float vr = red2(ar) + sm[OFF_B + 128 + k];
                    float vz = red2(az) + sm[OFF_B + 128 + k + 32];
                    float vni = red2(ani) + sm[OFF_B + 128 + 64 + k];
                    float vnh = red2(anh) + sm[OFF_B + 128 + 96 + k];
                    float rr = sigm(vr), zz = sigm(vz);
                    float nn = tanhf(vni + rr * vnh);
                    float hold = sm[OFF_H1 + pong * 2304 + r * 36 + k];
                    float hnew = (1.f - zz) * nn + zz * hold;
                    if (valid) sm[OFF_H1 + next * 2304 + r * 36 + k] = hnew;
                }
            }
            __syncthreads();

            // ================= layer 2 =================
            {
                P4 h1n[8], h2c[8];
                load8s(sm + OFF_H1 + next * 2304 + r * 36, h1n);
                load8s(sm + OFF_H2 + pong * 2340 + (r + 1) * 36, h2c);
                for (int k = slice; k < 32; k += wpr) {
                    unsigned long long ar = 0ull, az = 0ull, ani = 0ull, anh = 0ull;
                    dot32(sm + OFF_WIH2 + k * 32, h1n, ar);
                    dot32(sm + OFF_WHH2 + k * 32, h2c, ar);
                    dot32(sm + OFF_WIH2 + (k + 32) * 32, h1n, az);
                    dot32(sm + OFF_WHH2 + (k + 32) * 32, h2c, az);
                    dot32(sm + OFF_WIH2 + (k + 64) * 32, h1n, ani);
                    dot32(sm + OFF_WHH2 + (k + 64) * 32, h2c, anh);
                    float vr = red2(ar) + sm[OFF_B + 256 + k];
                    float vz = red2(az) + sm[OFF_B + 256 + k + 32];
                    float vni = red2(ani) + sm[OFF_B + 256 + 64 + k];
                    float vnh = red2(anh) + sm[OFF_B + 256 + 96 + k];
                    float rr = sigm(vr), zz = sigm(vz);
                    float nn = tanhf(vni + rr * vnh);
                    float hold = sm[OFF_H2 + pong * 2340 + (r + 1) * 36 + k];
                    float hnew = (1.f - zz) * nn + zz * hold;
                    if (valid) {
                        sm[OFF_H2 + next * 2340 + (r + 1) * 36 + k] = hnew;
                        gcur[((size_t)r * Sn + t) * Hn + k] = hnew;
                    }
                }
            }
            // rolling zero: activate row s+1 for step s+1 (reads buffer `next`)
            if (s + 1 <= 63 && tid < 108) {
                int which = tid / 36, kk = tid - which * 36;
                if (which == 0)      sm[OFF_H0 + next * 2304 + (s + 1) * 36 + kk] = 0.f;
                else if (which == 1) sm[OFF_H1 + next * 2304 + (s + 1) * 36 + kk] = 0.f;
                else                 sm[OFF_H2 + next * 2340 + (s + 2) * 36 + kk] = 0.f;
            }
            __syncthreads();
        }
        __syncthreads();
    }
}

// ---------------------------------------------------------------------------
// Kernel 2: output logits, f32x2 inner loop.
// ---------------------------------------------------------------------------
template <int N4>
__device__ __forceinline__ void compute_logits(const float* __restrict__ Ws,
                                               const float* __restrict__ ins,
                                               const float* __restrict__ bs,
                                               float* __restrict__ outp, int tid) {
    constexpr int Kp = N4 * 4;
    for (int tile = tid; tile < 65 * 32; tile += 512) {
        int vg = tile / 32, tg = tile - vg * 32;
        int t0 = tg * 2, v0 = vg * 4;
        const ulonglong2* w0 = reinterpret_cast<const ulonglong2*>(&Ws[(v0 + 0) * Kp]);
        const ulonglong2* w1 = reinterpret_cast<const ulonglong2*>(&Ws[(v0 + 1) * Kp]);
        const ulonglong2* w2 = reinterpret_cast<const ulonglong2*>(&Ws[(v0 + 2) * Kp]);
        const ulonglong2* w3 = reinterpret_cast<const ulonglong2*>(&Ws[(v0 + 3) * Kp]);
        const ulonglong2* i0 = reinterpret_cast<const ulonglong2*>(&ins[t0 * Kp]);
        const ulonglong2* i1 = reinterpret_cast<const ulonglong2*>(&ins[(t0 + 1) * Kp]);
        unsigned long long a0[4] = {0ull, 0ull, 0ull, 0ull};
        unsigned long long a1[4] = {0ull, 0ull, 0ull, 0ull};
#pragma unroll 4
        for (int k = 0; k < N4; ++k) {
            ulonglong2 x0 = i0[k], x1 = i1[k];
            ulonglong2 y;
            y = w0[k];
            fma2(a0[0], y.x, x0.x); fma2(a0[0], y.y, x0.y);
            fma2(a1[0], y.x, x1.x); fma2(a1[0], y.y, x1.y);
            y = w1[k];
            fma2(a0[1], y.x, x0.x); fma2(a0[1], y.y, x0.y);
            fma2(a1[1], y.x, x1.x); fma2(a1[1], y.y, x1.y);
            y = w2[k];
            fma2(a0[2], y.x, x0.x); fma2(a0[2], y.y, x0.y);
            fma2(a1[2], y.x, x1.x); fma2(a1[2], y.y, x1.y);
            y = w3[k];
            fma2(a0[3], y.x, x0.x); fma2(a0[3], y.y, x0.y);
            fma2(a1[3], y.x, x1.x); fma2(a1[3], y.y, x1.y);
        }
        int ob0 = t0 * Vn, ob1 = ob0 + Vn;
#pragma unroll
        for (int v = 0; v < 4; ++v) {
            int vv = v0 + v;
            if (vv < Vn) {
                float bv = bs[vv];
                outp[ob0 + vv] = red2(a0[v]) + bv;
                outp[ob1 + vv] = red2(a1[v]) + bv;
            }
        }
    }
}

__global__ __launch_bounds__(512, 1)
void logits_kernel(const float* __restrict__ emb, const int* __restrict__ target,
                   const float* __restrict__ W0, const float* __restrict__ b0,
                   const float* __restrict__ W1, const float* __restrict__ b1,
                   const float* __restrict__ W2, const float* __restrict__ b2,
                   float* __restrict__ out) {
    extern __shared__ float sm[];
    const int tid = threadIdx.x;
    const int ch = blockIdx.y;
    const int bb = blockIdx.x >> 6;
    const int r = blockIdx.x & 63;

    const float* W;
    const float* Bb;
    int K;
    if (ch == 0)      { W = W0; Bb = b0; K = 32; }
    else if (ch == 1) { W = W1; Bb = b1; K = 96; }
    else              { W = W2; Bb = b2; K = 160; }
    const int Kp = K + 4;

    float* Ws = sm;
    float* ins = sm + 260 * Kp;
    float* bs = ins + 64 * Kp;

    for (int idx = tid; idx < 260 * Kp; idx += 512) {
        int v = idx / Kp, k = idx - v * Kp;
        Ws[idx] = (v < Vn && k < K) ? W[v * K + k] : 0.f;
    }
    for (int idx = tid; idx < 260; idx += 512)
        bs[idx] = (idx < Vn) ? Bb[idx] : 0.f;

    const int rowbase = ((bb * 3 + ch) * Rn + r) * Sn;
    for (int idx = tid; idx < 64 * Kp; idx += 512) {
        int t = idx / Kp, k = idx - t * Kp;
        float val = 0.f;
        if (k < 32) {
            val = g_outs[(size_t)(rowbase + t) * Hn + k];
        } else if (k < K) {
            int kk = k - 32;
            int chE = (kk < 64) ? 0 : 1;
            int ke = (kk < 64) ? kk : kk - 64;
            int tg = target[((bb * 3 + chE) * Rn + r) * Sn + t];
            val = emb[(size_t)(chE * Vn + tg) * En + ke];
        }
        ins[idx] = val;
    }
    __syncthreads();

    float* outp = out + (size_t)rowbase * Vn;
    if (K == 32)       compute_logits<9>(Ws, ins, bs, outp, tid);
    else if (K == 96)  compute_logits<25>(Ws, ins, bs, outp, tid);
    else               compute_logits<41>(Ws, ins, bs, outp, tid);
}

// ---------------------------------------------------------------------------
// Launch
// ---------------------------------------------------------------------------
extern "C" void kernel_launch(void* const* d_in, const int* in_sizes, int n_in,
                              void* d_out, int out_size) {
    (void)in_sizes; (void)n_in; (void)out_size;
    const int*   x      = (const int*)  d_in[0];
    const int*   target = (const int*)  d_in[1];
    const float* emb    = (const float*)d_in[2];
    const float* Wih0   = (const float*)d_in[3];
    const float* WihR   = (const float*)d_in[4];
    const float* Whh    = (const float*)d_in[5];
    const float* bih    = (const float*)d_in[6];
    const float* bhh    = (const float*)d_in[7];
    const float* h2eW   = (const float*)d_in[8];
    const float* h2eb   = (const float*)d_in[9];
    const float* adpW   = (const float*)d_in[10];
    const float* adpb   = (const float*)d_in[11];
    const float* redW   = (const float*)d_in[12];
    const float* redb   = (const float*)d_in[13];
    const float* greenW = (const float*)d_in[14];
    const float* greenb = (const float*)d_in[15];
    const float* blueW  = (const float*)d_in[16];
    const float* blueb  = (const float*)d_in[17];
    float* out = (float*)d_out;

    const size_t smem_rnn = (size_t)SM_TOT * sizeof(float);                       // 143,520 B
    const size_t smem_log = (size_t)(260 * 164 + 64 * 164 + 260) * sizeof(float); // 213,584 B

    cudaFuncSetAttribute(rnn_kernel, cudaFuncAttributeMaxDynamicSharedMemorySize,
                         (int)smem_rnn);
    cudaFuncSetAttribute(logits_kernel, cudaFuncAttributeMaxDynamicSharedMemorySize,
                         (int)smem_log);

    pre_kernel<<<352, 256>>>(emb, Wih0, h2eW, h2eb, adpW, adpb, bih);
    rnn_kernel<<<Bn, 512, smem_rnn>>>(x, Wih0, WihR, Whh, bih, bhh);
    logits_kernel<<<dim3(Bn * Rn, 3), 512, smem_log>>>(emb, target, redW, redb,
                                                       greenW, greenb, blueW,
                                                       blueb, out);
}

// round 9
// speedup vs baseline: 3.0618x; 1.1339x over previous
#include <cuda_runtime.h>
#include <math.h>

// ---------------------------------------------------------------------------
// Problem constants
// ---------------------------------------------------------------------------
#define Bn 16
#define Hn 32
#define En 64
#define Vn 258
#define Rn 64
#define Sn 64
#define Dn 127   // number of wavefront diagonals (r + t)

// ---------------------------------------------------------------------------
// Global scratch (static __device__, no allocation)
// ---------------------------------------------------------------------------
__device__ float g_outs_d[Bn * 3 * Dn * Rn * Hn];   // ~50 MB, diag layout [b][c][s][r][k]
__device__ float g_comb0[(size_t)Bn * 3 * Dn * 96 * 64]; // ~150 MB, [b][c][s][g][r]
__device__ float g_T0[3 * 258 * 96];                // Wih0 @ emb
__device__ float g_M1[3 * 96 * 32];                 // Wih0 @ h2eW
__device__ float g_M2[2 * 96 * 32];                 // Wih0 @ adpW
__device__ float g_b0[3 * 96];                      // bih0 + Wih0@(h2eb[+adpb])

// ---------------------------------------------------------------------------
// Packed f32x2 helpers
// ---------------------------------------------------------------------------
union P4 { float4 f; ulonglong2 u; };

__device__ __forceinline__ void fma2(unsigned long long& acc,
                                     unsigned long long a,
                                     unsigned long long b) {
    asm("fma.rn.f32x2 %0, %1, %2, %0;" : "+l"(acc) : "l"(a), "l"(b));
}
__device__ __forceinline__ float red2(unsigned long long acc) {
    float x, y;
    asm("mov.b64 {%0, %1}, %2;" : "=f"(x), "=f"(y) : "l"(acc));
    return x + y;
}
__device__ __forceinline__ void dot32(const float* __restrict__ w,
                                      const P4 x[8], unsigned long long& acc) {
    const ulonglong2* W = reinterpret_cast<const ulonglong2*>(w);
#pragma unroll
    for (int i = 0; i < 8; ++i) {
        ulonglong2 wv = W[i];
        fma2(acc, wv.x, x[i].u.x);
        fma2(acc, wv.y, x[i].u.y);
    }
}
__device__ __forceinline__ void load8s(const float* __restrict__ p, P4 x[8]) {
    const float4* q = reinterpret_cast<const float4*>(p);
#pragma unroll
    for (int i = 0; i < 8; ++i) x[i].f = q[i];
}
__device__ __forceinline__ float sigm(float x) {
    return 1.f / (1.f + __expf(-x));
}

// ---------------------------------------------------------------------------
// Pre-kernel 1: fold comb linear algebra into tables
// ---------------------------------------------------------------------------
__global__ void pre_kernel(const float* __restrict__ emb,
                           const float* __restrict__ Wih0,
                           const float* __restrict__ h2eW,
                           const float* __restrict__ h2eb,
                           const float* __restrict__ adpW,
                           const float* __restrict__ adpb,
                           const float* __restrict__ bih) {
    int idx = blockIdx.x * 256 + threadIdx.x;
    if (idx < 74304) {                       // T0[c][v][g]
        int c = idx / 24768, rem = idx % 24768;
        int v = rem / 96, g = rem % 96;
        const float* w = Wih0 + c * 6240 + g * 65;
        const float* e = emb + (size_t)(c * 258 + v) * 64;
        float s = 0.f;
        for (int j = 0; j < 64; ++j) s = fmaf(w[j], e[j], s);
        g_T0[idx] = s;
    } else if (idx < 74304 + 9216) {         // M1[c][g][j]
        int i = idx - 74304;
        int c = i / 3072, rem = i % 3072, g = rem / 32, j = rem % 32;
        const float* w = Wih0 + c * 6240 + g * 65;
        float s = 0.f;
        for (int e = 0; e < 65; ++e) s = fmaf(w[e], h2eW[c * 2080 + e * 32 + j], s);
        g_M1[i] = s;
    } else if (idx < 74304 + 9216 + 6144) {  // M2[c2][g][j]
        int i = idx - 74304 - 9216;
        int c2 = i / 3072, rem = i % 3072, g = rem / 32, j = rem % 32;
        const float* w = Wih0 + (c2 + 1) * 6240 + g * 65;
        float s = 0.f;
        for (int e = 0; e < 65; ++e) s = fmaf(w[e], adpW[c2 * 2080 + e * 32 + j], s);
        g_M2[i] = s;
    } else if (idx < 74304 + 9216 + 6144 + 288) {   // b0[c][g]
        int i = idx - 74304 - 9216 - 6144;
        int c = i / 96, g = i % 96;
        const float* w = Wih0 + c * 6240 + g * 65;
        float s = bih[c * 288 + g];
        for (int e = 0; e < 65; ++e) s = fmaf(w[e], h2eb[c * 65 + e], s);
        if (c > 0)
            for (int e = 0; e < 65; ++e) s = fmaf(w[e], adpb[(c - 1) * 65 + e], s);
        g_b0[i] = s;
    }
}

// ---------------------------------------------------------------------------
// Pre-kernel 2: materialize comb0 per cell, diagonal layout [b][c][s][g][r].
// comb0 = T0[x] + rowfeat * w64 + (b0 [+ bhh for r,z gates]).
// grid = (127 diagonals, 48 b*c), 256 threads.
// ---------------------------------------------------------------------------
__global__ void pre2_kernel(const int* __restrict__ x,
                            const float* __restrict__ Wih0,
                            const float* __restrict__ bhh) {
    __shared__ float w64s[96], bias_s[96];
    __shared__ int xs[64];
    const int s = blockIdx.x;
    const int bc = blockIdx.y;           // b*3 + c
    const int c = bc % 3;
    const int tid = threadIdx.x;
    const int lo = (s > 63) ? s - 63 : 0;
    const int hi = (s < 63) ? s : 63;
    if (tid < 96) {
        w64s[tid] = Wih0[c * 6240 + tid * 65 + 64];
        float bb = g_b0[c * 96 + tid];
        if (tid < 64) bb += bhh[c * 288 + tid];      // bhh r,z (layer 0)
        bias_s[tid] = bb;
    }
    if (tid >= 96 && tid - 96 <= hi - lo) {
        int r = lo + (tid - 96);
        xs[r] = x[(bc * 64 + r) * 64 + (s - r)];
    }
    __syncthreads();
    float* outp = g_comb0 + ((size_t)bc * Dn + s) * 6144;
    const float* t0c = g_T0 + c * 258 * 96;
    for (int idx = tid; idx < 96 * 64; idx += 256) {
        int g = idx >> 6, r = idx & 63;
        if (r < lo || r > hi) continue;
        float rf = (float)r * 0.03125f - 1.0f;
        outp[idx] = t0c[xs[r] * 96 + g] + rf * w64s[g] + bias_s[g];
    }
}

// ---------------------------------------------------------------------------
// Shared-memory layout for the RNN kernel (floats)
// ---------------------------------------------------------------------------
constexpr int OFF_M1   = 0;        // 96 x 32
constexpr int OFF_M2   = 3072;
constexpr int OFF_WHH0 = 6144;
constexpr int OFF_WIH1 = 9216;
constexpr int OFF_WHH1 = 12288;
constexpr int OFF_WIH2 = 15360;
constexpr int OFF_WHH2 = 18432;
constexpr int OFF_B    = 21504;    // 3 x 128 (layer biases; l=0 uses only nh part)
constexpr int OFF_H0   = 21888;    // 2 x (64 x 36) ping-pong
constexpr int OFF_H1   = 26496;    // 2 x (64 x 36)
constexpr int OFF_H2   = 31104;    // 2 x (65 x 36), slot r+1 = row r, slot 0 = 0
constexpr int OFF_PC   = 35784;    // 2 x (64 x 36) prev-channel staging (double buf)
constexpr int SM_TOT   = 40392;    // 161,568 bytes

// ---------------------------------------------------------------------------
// Kernel: wavefront row-RNN. 16 blocks (one per batch), 512 threads.
// ---------------------------------------------------------------------------
__global__ __launch_bounds__(512, 1)
void rnn_kernel(const float* __restrict__ WihR, const float* __restrict__ Whh,
                const float* __restrict__ bih, const float* __restrict__ bhh) {
    extern __shared__ float sm[];
    const int tid = threadIdx.x;
    const int warp = tid >> 5, lane = tid & 31;
    const int b = blockIdx.x;

    for (int c = 0; c < 3; ++c) {
        const bool haspc = (c > 0);
        // ---- stage weights ----
        for (int i = tid; i < 3072; i += 512) {
            sm[OFF_M1 + i]   = g_M1[c * 3072 + i];
            sm[OFF_WHH0 + i] = Whh[c * 9216 + i];
            sm[OFF_WIH1 + i] = WihR[c * 6144 + i];
            sm[OFF_WHH1 + i] = Whh[c * 9216 + 3072 + i];
            sm[OFF_WIH2 + i] = WihR[c * 6144 + 3072 + i];
            sm[OFF_WHH2 + i] = Whh[c * 9216 + 6144 + i];
            if (haspc) sm[OFF_M2 + i] = g_M2[(c - 1) * 3072 + i];
        }
        for (int i = tid; i < 384; i += 512) {
            int l = i >> 7, o = i & 127;
            float v;
            if (o < 64)
                v = ((l == 0) ? 0.f : bih[(c * 3 + l) * 96 + o] +
                                      bhh[(c * 3 + l) * 96 + o]);
            else if (o < 96) {
                int g = 64 + (o - 64);
                v = (l == 0) ? 0.f : bih[(c * 3 + l) * 96 + g];
            } else {
                int g = 64 + (o - 96);
                v = bhh[(c * 3 + l) * 96 + g];
            }
            sm[OFF_B + i] = v;
        }
        for (int i = tid; i < 13896; i += 512) sm[OFF_H0 + i] = 0.f;

        const float* gprev = g_outs_d + (size_t)(b * 3 + c - 1) * Dn * 2048;
        float* gcur = g_outs_d + (size_t)(b * 3 + c) * Dn * 2048;
        const float* cchan = g_comb0 + (size_t)(b * 3 + c) * Dn * 6144;

        // prologue: stage prev-channel vector for step 0 (diag 0, row 0)
        if (haspc && tid < 32) sm[OFF_PC + tid] = gprev[tid];
        __syncthreads();

        for (int s = 0; s < Dn; ++s) {
            const int pong = s & 1, next = 1 - pong;
            const int lo = (s > 63) ? s - 63 : 0;
            const int hi = (s < 63) ? s : 63;
            const int nact = hi - lo + 1;
            const int RG = (nact > 32) ? 2 : 1;
            const int wpr = (RG == 2) ? 8 : 16;
            const int rg = (RG == 2) ? (warp & 1) : 0;
            const int slice = (RG == 2) ? (warp >> 1) : warp;

            const int jj = rg * 32 + lane;
            const bool valid = jj < nact;
            const int r = lo + (valid ? jj : (nact - 1));

            // ---- coalesced copy-out of previous step's layer-2 results ----
            if (s > 0) {
                const int lop = (s - 1 > 63) ? s - 64 : 0;
                const int hip = (s - 1 < 63) ? s - 1 : 63;
                const int np = hip - lop + 1;
                for (int idx = tid; idx < np * 32; idx += 512) {
                    int j = idx >> 5, k = idx & 31, rr = lop + j;
                    gcur[((size_t)(s - 1) * 64 + rr) * 32 + k] =
                        sm[OFF_H2 + pong * 2340 + (rr + 1) * 36 + k];
                }
            }

            // ================= layer 0 (comb folded into g_comb0) ==========
            {
                P4 h2p[8], h0c[8], pcc[8];
                load8s(sm + OFF_H2 + pong * 2340 + r * 36, h2p);
                load8s(sm + OFF_H0 + pong * 2304 + r * 36, h0c);
                if (haspc) load8s(sm + OFF_PC + pong * 2304 + r * 36, pcc);
                const float* cb = cchan + (size_t)s * 6144 + r;

                for (int k = slice; k < 32; k += wpr) {
                    float c0r = cb[k * 64];
                    float c0z = cb[(k + 32) * 64];
                    float c0n = cb[(k + 64) * 64];
                    unsigned long long ar = 0ull, az = 0ull, ani = 0ull, anh = 0ull;
                    dot32(sm + OFF_M1 + k * 32, h2p, ar);
                    dot32(sm + OFF_M1 + (k + 32) * 32, h2p, az);
                    dot32(sm + OFF_M1 + (k + 64) * 32, h2p, ani);
                    if (haspc) {
                        dot32(sm + OFF_M2 + k * 32, pcc, ar);
                        dot32(sm + OFF_M2 + (k + 32) * 32, pcc, az);
                        dot32(sm + OFF_M2 + (k + 64) * 32, pcc, ani);
                    }
                    dot32(sm + OFF_WHH0 + k * 32, h0c, ar);
                    dot32(sm + OFF_WHH0 + (k + 32) * 32, h0c, az);
                    dot32(sm + OFF_WHH0 + (k + 64) * 32, h0c, anh);
                    float vr = red2(ar) + c0r;
                    float vz = red2(az) + c0z;
                    float vni = red2(ani) + c0n;
                    float vnh = red2(anh) + sm[OFF_B + 96 + k];
                    float rr = sigm(vr), zz = sigm(vz);
                    float nn = tanhf(vni + rr * vnh);
                    float hold = sm[OFF_H0 + pong * 2304 + r * 36 + k];
                    float hnew = (1.f - zz) * nn + zz * hold;
                    if (valid) sm[OFF_H0 + next * 2304 + r * 36 + k] = hnew;
                }
            }
            __syncthreads();

            // ---- stage prev-channel vectors for step s+1 (buffer `next`) ----
            if (haspc && s + 1 < Dn) {
                const int lo2 = (s + 1 > 63) ? s - 62 : 0;
                const int hi2 = (s + 1 < 63) ? s + 1 : 63;
                const int n2 = hi2 - lo2 + 1;
                for (int idx = tid; idx < n2 * 32; idx += 512) {
                    int j = idx >> 5, k = idx & 31, rr = lo2 + j;
                    sm[OFF_PC + next * 2304 + rr * 36 + k] =
                        gprev[((size_t)(s + 1) * 64 + rr) * 32 + k];
                }
            }

            // ================= layer 1 =================
            {
                P4 h0n[8], h1c[8];
                load8s(sm + OFF_H0 + next * 2304 + r * 36, h0n);
                load8s(sm + OFF_H1 + pong * 2304 + r * 36, h1c);
                for (int k = slice; k < 32; k += wpr) {
                    unsigned long long ar = 0ull, az = 0ull, ani = 0ull, anh = 0ull;
                    dot32(sm + OFF_WIH1 + k * 32, h0n, ar);
                    dot32(sm + OFF_WHH1 + k * 32, h1c, ar);
                    dot32(sm + OFF_WIH1 + (k + 32) * 32, h0n, az);
                    dot32(sm + OFF_WHH1 + (k + 32) * 32, h1c, az);
                    dot32(sm + OFF_WIH1 + (k + 64) * 32, h0n, ani);
                    dot32(sm + OFF_WHH1 + (k + 64) * 32, h1c, anh);
                    float vr = red2(ar) + sm[OFF_B + 128 + k];
                    float vz = red2(az) + sm[OFF_B + 128 + k + 32];
                    float vni = red2(ani) + sm[OFF_B + 128 + 64 + k];
                    float vnh = red2(anh) + sm[OFF_B + 128 + 96 + k];
                    float rr = sigm(vr), zz = sigm(vz);
                    float nn = tanhf(vni + rr * vnh);
                    float hold = sm[OFF_H1 + pong * 2304 + r * 36 + k];
                    float hnew = (1.f - zz) * nn + zz * hold;
                    if (valid) sm[OFF_H1 + next * 2304 + r * 36 + k] = hnew;
                }
            }
            __syncthreads();

            // ================= layer 2 =================
            {
                P4 h1n[8], h2c[8];
                load8s(sm + OFF_H1 + next * 2304 + r * 36, h1n);
                load8s(sm + OFF_H2 + pong * 2340 + (r + 1) * 36, h2c);
                for (int k = slice; k < 32; k += wpr) {
                    unsigned long long ar = 0ull, az = 0ull, ani = 0ull, anh = 0ull;
                    dot32(sm + OFF_WIH2 + k * 32, h1n, ar);
                    dot32(sm + OFF_WHH2 + k * 32, h2c, ar);
                    dot32(sm + OFF_WIH2 + (k + 32) * 32, h1n, az);
                    dot32(sm + OFF_WHH2 + (k + 32) * 32, h2c, az);
                    dot32(sm + OFF_WIH2 + (k + 64) * 32, h1n, ani);
                    dot32(sm + OFF_WHH2 + (k + 64) * 32, h2c, anh);
                    float vr = red2(ar) + sm[OFF_B + 256 + k];
                    float vz = red2(az) + sm[OFF_B + 256 + k + 32];
                    float vni = red2(ani) + sm[OFF_B + 256 + 64 + k];
                    float vnh = red2(anh) + sm[OFF_B + 256 + 96 + k];
                    float rr = sigm(vr), zz = sigm(vz);
                    float nn = tanhf(vni + rr * vnh);
                    float hold = sm[OFF_H2 + pong * 2340 + (r + 1) * 36 + k];
                    float hnew = (1.f - zz) * nn + zz * hold;
                    if (valid) sm[OFF_H2 + next * 2340 + (r + 1) * 36 + k] = hnew;
                }
            }
            // rolling zero: activate row s+1 for step s+1 (buffer `next`)
            if (s + 1 <= 63 && tid < 108) {
                int which = tid / 36, kk = tid - which * 36;
                if (which == 0)      sm[OFF_H0 + next * 2304 + (s + 1) * 36 + kk] = 0.f;
                else if (which == 1) sm[OFF_H1 + next * 2304 + (s + 1) * 36 + kk] = 0.f;
                else                 sm[OFF_H2 + next * 2340 + (s + 2) * 36 + kk] = 0.f;
            }
            __syncthreads();
        }
        // final copy-out: step 126 results live in buffer next(126) = 1
        if (tid < 32)
            gcur[((size_t)126 * 64 + 63) * 32 + tid] =
                sm[OFF_H2 + 1 * 2340 + 64 * 36 + tid];
        __syncthreads();
    }
}

// ---------------------------------------------------------------------------
// Kernel: output logits, f32x2 inner loop.
// ---------------------------------------------------------------------------
template <int N4>
__device__ __forceinline__ void compute_logits(const float* __restrict__ Ws,
                                               const float* __restrict__ ins,
                                               const float* __restrict__ bs,
                                               float* __restrict__ outp, int tid) {
    constexpr int Kp = N4 * 4;
    for (int tile = tid; tile < 65 * 32; tile += 512) {
        int vg = tile / 32, tg = tile - vg * 32;
        int t0 = tg * 2, v0 = vg * 4;
        const ulonglong2* w0 = reinterpret_cast<const ulonglong2*>(&Ws[(v0 + 0) * Kp]);
        const ulonglong2* w1 = reinterpret_cast<const ulonglong2*>(&Ws[(v0 + 1) * Kp]);
        const ulonglong2* w2 = reinterpret_cast<const ulonglong2*>(&Ws[(v0 + 2) * Kp]);
        const ulonglong2* w3 = reinterpret_cast<const ulonglong2*>(&Ws[(v0 + 3) * Kp]);
        const ulonglong2* i0 = reinterpret_cast<const ulonglong2*>(&ins[t0 * Kp]);
        const ulonglong2* i1 = reinterpret_cast<const ulonglong2*>(&ins[(t0 + 1) * Kp]);
        unsigned long long a0[4] = {0ull, 0ull, 0ull, 0ull};
        unsigned long long a1[4] = {0ull, 0ull, 0ull, 0ull};
#pragma unroll 4
        for (int k = 0; k < N4; ++k) {
            ulonglong2 x0 = i0[k], x1 = i1[k];
            ulonglong2 y;
            y = w0[k];
            fma2(a0[0], y.x, x0.x); fma2(a0[0], y.y, x0.y);
            fma2(a1[0], y.x, x1.x); fma2(a1[0], y.y, x1.y);
            y = w1[k];
            fma2(a0[1], y.x, x0.x); fma2(a0[1], y.y, x0.y);
            fma2(a1[1], y.x, x1.x); fma2(a1[1], y.y, x1.y);
            y = w2[k];
            fma2(a0[2], y.x, x0.x); fma2(a0[2], y.y, x0.y);
            fma2(a1[2], y.x, x1.x); fma2(a1[2], y.y, x1.y);
            y = w3[k];
            fma2(a0[3], y.x, x0.x); fma2(a0[3], y.y, x0.y);
            fma2(a1[3], y.x, x1.x); fma2(a1[3], y.y, x1.y);
        }
        int ob0 = t0 * Vn, ob1 = ob0 + Vn;
#pragma unroll
        for (int v = 0; v < 4; ++v) {
            int vv = v0 + v;
            if (vv < Vn) {
                float bv = bs[vv];
                outp[ob0 + vv] = red2(a0[v]) + bv;
                outp[ob1 + vv] = red2(a1[v]) + bv;
            }
        }
    }
}

__global__ __launch_bounds__(512, 1)
void logits_kernel(const float* __restrict__ emb, const int* __restrict__ target,
                   const float* __restrict__ W0, const float* __restrict__ b0,
                   const float* __restrict__ W1, const float* __restrict__ b1,
                   const float* __restrict__ W2, const float* __restrict__ b2,
                   float* __restrict__ out) {
    extern __shared__ float sm[];
    const int tid = threadIdx.x;
    const int ch = blockIdx.y;
    const int bb = blockIdx.x >> 6;
    const int r = blockIdx.x & 63;

    const float* W;
    const float* Bb;
    int K;
    if (ch == 0)      { W = W0; Bb = b0; K = 32; }
    else if (ch == 1) { W = W1; Bb = b1; K = 96; }
    else              { W = W2; Bb = b2; K = 160; }
    const int Kp = K + 4;

    float* Ws = sm;
    float* ins = sm + 260 * Kp;
    float* bs = ins + 64 * Kp;

    for (int idx = tid; idx < 260 * Kp; idx += 512) {
        int v = idx / Kp, k = idx - v * Kp;
        Ws[idx] = (v < Vn && k < K) ? W[v * K + k] : 0.f;
    }
    for (int idx = tid; idx < 260; idx += 512)
        bs[idx] = (idx < Vn) ? Bb[idx] : 0.f;

    const size_t diagbase = (size_t)(bb * 3 + ch) * Dn;
    for (int idx = tid; idx < 64 * Kp; idx += 512) {
        int t = idx / Kp, k = idx - t * Kp;
        float val = 0.f;
        if (k < 32) {
            val = g_outs_d[(diagbase + (r + t)) * 2048 + r * 32 + k];
        } else if (k < K) {
            int kk = k - 32;
            int chE = (kk < 64) ? 0 : 1;
            int ke = (kk < 64) ? kk : kk - 64;
            int tg = target[((bb * 3 + chE) * Rn + r) * Sn + t];
            val = emb[(size_t)(chE * Vn + tg) * En + ke];
        }
        ins[idx] = val;
    }
    __syncthreads();

    const int rowbase = ((bb * 3 + ch) * Rn + r) * Sn;
    float* outp = out + (size_t)rowbase * Vn;
    if (K == 32)       compute_logits<9>(Ws, ins, bs, outp, tid);
    else if (K == 96)  compute_logits<25>(Ws, ins, bs, outp, tid);
    else               compute_logits<41>(Ws, ins, bs, outp, tid);
}

// ---------------------------------------------------------------------------
// Launch
// ---------------------------------------------------------------------------
extern "C" void kernel_launch(void* const* d_in, const int* in_sizes, int n_in,
                              void* d_out, int out_size) {
    (void)in_sizes; (void)n_in; (void)out_size;
    const int*   x      = (const int*)  d_in[0];
    const int*   target = (const int*)  d_in[1];
    const float* emb    = (const float*)d_in[2];
    const float* Wih0   = (const float*)d_in[3];
    const float* WihR   = (const float*)d_in[4];
    const float* Whh    = (const float*)d_in[5];
    const float* bih    = (const float*)d_in[6];
    const float* bhh    = (const float*)d_in[7];
    const float* h2eW   = (const float*)d_in[8];
    const float* h2eb   = (const float*)d_in[9];
    const float* adpW   = (const float*)d_in[10];
    const float* adpb   = (const float*)d_in[11];
    const float* redW   = (const float*)d_in[12];
    const float* redb   = (const float*)d_in[13];
    const float* greenW = (const float*)d_in[14];
    const float* greenb = (const float*)d_in[15];
    const float* blueW  = (const float*)d_in[16];
    const float* blueb  = (const float*)d_in[17];
    float* out = (float*)d_out;

    const size_t smem_rnn = (size_t)SM_TOT * sizeof(float);                       // 161,568 B
    const size_t smem_log = (size_t)(260 * 164 + 64 * 164 + 260) * sizeof(float); // 213,584 B

    cudaFuncSetAttribute(rnn_kernel, cudaFuncAttributeMaxDynamicSharedMemorySize,
                         (int)smem_rnn);
    cudaFuncSetAttribute(logits_kernel, cudaFuncAttributeMaxDynamicSharedMemorySize,
                         (int)smem_log);

    pre_kernel<<<352, 256>>>(emb, Wih0, h2eW, h2eb, adpW, adpb, bih);
    pre2_kernel<<<dim3(Dn, Bn * 3), 256>>>(x, Wih0, bhh);
    rnn_kernel<<<Bn, 512, smem_rnn>>>(WihR, Whh, bih, bhh);
    logits_kernel<<<dim3(Bn * Rn, 3), 512, smem_log>>>(emb, target, redW, redb,
                                                       greenW, greenb, blueW,
                                                       blueb, out);
}

// round 10
// speedup vs baseline: 6.1557x; 2.0105x over previous
#include <cuda_runtime.h>
#include <math.h>

// ---------------------------------------------------------------------------
// Problem constants
// ---------------------------------------------------------------------------
#define Bn 16
#define Hn 32
#define En 64
#define Vn 258
#define Rn 64
#define Sn 64
#define Dn 127   // number of wavefront diagonals (r + t)

// ---------------------------------------------------------------------------
// Global scratch (static __device__, no allocation)
// ---------------------------------------------------------------------------
__device__ float g_outs_d[Bn * 3 * Dn * Rn * Hn];        // diag layout [b][c][s][r][k]
__device__ float g_comb0[(size_t)Bn * 3 * Dn * 96 * 64]; // [b][c][s][g][r]
__device__ float g_T0[3 * 258 * 96];                     // Wih0 @ emb
__device__ float g_M1[3 * 96 * 32];                      // Wih0 @ h2eW
__device__ float g_M2[2 * 96 * 32];                      // Wih0 @ adpW
__device__ float g_b0[3 * 96];                           // bih0 + Wih0@(h2eb[+adpb])
__device__ int   g_flag[Bn * 3];                         // diag progress per (b,c)

// ---------------------------------------------------------------------------
// Packed f32x2 helpers
// ---------------------------------------------------------------------------
union P4 { float4 f; ulonglong2 u; };

__device__ __forceinline__ void fma2(unsigned long long& acc,
                                     unsigned long long a,
                                     unsigned long long b) {
    asm("fma.rn.f32x2 %0, %1, %2, %0;" : "+l"(acc) : "l"(a), "l"(b));
}
__device__ __forceinline__ float red2(unsigned long long acc) {
    float x, y;
    asm("mov.b64 {%0, %1}, %2;" : "=f"(x), "=f"(y) : "l"(acc));
    return x + y;
}
__device__ __forceinline__ void dot32(const float* __restrict__ w,
                                      const P4 x[8], unsigned long long& acc) {
    const ulonglong2* W = reinterpret_cast<const ulonglong2*>(w);
#pragma unroll
    for (int i = 0; i < 8; ++i) {
        ulonglong2 wv = W[i];
        fma2(acc, wv.x, x[i].u.x);
        fma2(acc, wv.y, x[i].u.y);
    }
}
__device__ __forceinline__ void load8s(const float* __restrict__ p, P4 x[8]) {
    const float4* q = reinterpret_cast<const float4*>(p);
#pragma unroll
    for (int i = 0; i < 8; ++i) x[i].f = q[i];
}
__device__ __forceinline__ float sigm(float x) {
    return 1.f / (1.f + __expf(-x));
}
__device__ __forceinline__ int ld_acq(const int* p) {
    int v;
    asm volatile("ld.global.acquire.gpu.s32 %0, [%1];" : "=r"(v) : "l"(p));
    return v;
}

// ---------------------------------------------------------------------------
// Pre-kernel 1: fold comb linear algebra into tables (+ zero pipeline flags)
// ---------------------------------------------------------------------------
__global__ void pre_kernel(const float* __restrict__ emb,
                           const float* __restrict__ Wih0,
                           const float* __restrict__ h2eW,
                           const float* __restrict__ h2eb,
                           const float* __restrict__ adpW,
                           const float* __restrict__ adpb,
                           const float* __restrict__ bih) {
    int idx = blockIdx.x * 256 + threadIdx.x;
    if (idx < 74304) {                       // T0[c][v][g]
        int c = idx / 24768, rem = idx % 24768;
        int v = rem / 96, g = rem % 96;
        const float* w = Wih0 + c * 6240 + g * 65;
        const float* e = emb + (size_t)(c * 258 + v) * 64;
        float s = 0.f;
        for (int j = 0; j < 64; ++j) s = fmaf(w[j], e[j], s);
        g_T0[idx] = s;
    } else if (idx < 74304 + 9216) {         // M1[c][g][j]
        int i = idx - 74304;
        int c = i / 3072, rem = i % 3072, g = rem / 32, j = rem % 32;
        const float* w = Wih0 + c * 6240 + g * 65;
        float s = 0.f;
        for (int e = 0; e < 65; ++e) s = fmaf(w[e], h2eW[c * 2080 + e * 32 + j], s);
        g_M1[i] = s;
    } else if (idx < 74304 + 9216 + 6144) {  // M2[c2][g][j]
        int i = idx - 74304 - 9216;
        int c2 = i / 3072, rem = i % 3072, g = rem / 32, j = rem % 32;
        const float* w = Wih0 + (c2 + 1) * 6240 + g * 65;
        float s = 0.f;
        for (int e = 0; e < 65; ++e) s = fmaf(w[e], adpW[c2 * 2080 + e * 32 + j], s);
        g_M2[i] = s;
    } else if (idx < 74304 + 9216 + 6144 + 288) {   // b0[c][g]
        int i = idx - 74304 - 9216 - 6144;
        int c = i / 96, g = i % 96;
        const float* w = Wih0 + c * 6240 + g * 65;
        float s = bih[c * 288 + g];
        for (int e = 0; e < 65; ++e) s = fmaf(w[e], h2eb[c * 65 + e], s);
        if (c > 0)
            for (int e = 0; e < 65; ++e) s = fmaf(w[e], adpb[(c - 1) * 65 + e], s);
        g_b0[i] = s;
    } else if (idx < 89952 + 48) {           // zero pipeline flags
        g_flag[idx - 89952] = 0;
    }
}

// ---------------------------------------------------------------------------
// Pre-kernel 2: materialize comb0 per cell, diagonal layout [b][c][s][g][r].
// ---------------------------------------------------------------------------
__global__ void pre2_kernel(const int* __restrict__ x,
                            const float* __restrict__ Wih0,
                            const float* __restrict__ bhh) {
    __shared__ float w64s[96], bias_s[96];
    __shared__ int xs[64];
    const int s = blockIdx.x;
    const int bc = blockIdx.y;           // b*3 + c
    const int c = bc % 3;
    const int tid = threadIdx.x;
    const int lo = (s > 63) ? s - 63 : 0;
    const int hi = (s < 63) ? s : 63;
    if (tid < 96) {
        w64s[tid] = Wih0[c * 6240 + tid * 65 + 64];
        float bb = g_b0[c * 96 + tid];
        if (tid < 64) bb += bhh[c * 288 + tid];      // bhh r,z (layer 0)
        bias_s[tid] = bb;
    }
    if (tid >= 96 && tid - 96 <= hi - lo) {
        int r = lo + (tid - 96);
        xs[r] = x[(bc * 64 + r) * 64 + (s - r)];
    }
    __syncthreads();
    float* outp = g_comb0 + ((size_t)bc * Dn + s) * 6144;
    const float* t0c = g_T0 + c * 258 * 96;
    for (int idx = tid; idx < 96 * 64; idx += 256) {
        int g = idx >> 6, r = idx & 63;
        if (r < lo || r > hi) continue;
        float rf = (float)r * 0.03125f - 1.0f;
        outp[idx] = t0c[xs[r] * 96 + g] + rf * w64s[g] + bias_s[g];
    }
}

// ---------------------------------------------------------------------------
// Shared-memory layout for the RNN kernel (floats)
// ---------------------------------------------------------------------------
constexpr int OFF_M1   = 0;        // 96 x 32
constexpr int OFF_M2   = 3072;
constexpr int OFF_WHH0 = 6144;
constexpr int OFF_WIH1 = 9216;
constexpr int OFF_WHH1 = 12288;
constexpr int OFF_WIH2 = 15360;
constexpr int OFF_WHH2 = 18432;
constexpr int OFF_B    = 21504;    // 3 x 128 (layer biases; l=0 uses only nh part)
constexpr int OFF_H0   = 21888;    // 2 x (64 x 36) ping-pong
constexpr int OFF_H1   = 26496;    // 2 x (64 x 36)
constexpr int OFF_H2   = 31104;    // 2 x (65 x 36), slot r+1 = row r, slot 0 = 0
constexpr int OFF_PC   = 35784;    // 2 x (64 x 36) prev-channel staging (double buf)
constexpr int SM_TOT   = 40392;    // 161,568 bytes

// ---------------------------------------------------------------------------
// Kernel: channel-pipelined wavefront row-RNN.
// 48 blocks (one per batch x channel), 512 threads. Channel c+1 trails
// channel c by 2 wavefront steps, synchronized via per-(b,c) diag flags.
// ---------------------------------------------------------------------------
__global__ __launch_bounds__(512, 1)
void rnn_kernel(const float* __restrict__ WihR, const float* __restrict__ Whh,
                const float* __restrict__ bih, const float* __restrict__ bhh) {
    extern __shared__ float sm[];
    const int tid = threadIdx.x;
    const int warp = tid >> 5, lane = tid & 31;
    const int bc = blockIdx.x;
    const int c = bc % 3;
    const bool haspc = (c > 0);

    // ---- stage weights (once) ----
    for (int i = tid; i < 3072; i += 512) {
        sm[OFF_M1 + i]   = g_M1[c * 3072 + i];
        sm[OFF_WHH0 + i] = Whh[c * 9216 + i];
        sm[OFF_WIH1 + i] = WihR[c * 6144 + i];
        sm[OFF_WHH1 + i] = Whh[c * 9216 + 3072 + i];
        sm[OFF_WIH2 + i] = WihR[c * 6144 + 3072 + i];
        sm[OFF_WHH2 + i] = Whh[c * 9216 + 6144 + i];
        if (haspc) sm[OFF_M2 + i] = g_M2[(c - 1) * 3072 + i];
    }
    for (int i = tid; i < 384; i += 512) {
        int l = i >> 7, o = i & 127;
        float v;
        if (o < 64)
            v = ((l == 0) ? 0.f : bih[(c * 3 + l) * 96 + o] +
                                  bhh[(c * 3 + l) * 96 + o]);
        else if (o < 96) {
            int g = 64 + (o - 64);
            v = (l == 0) ? 0.f : bih[(c * 3 + l) * 96 + g];
        } else {
            int g = 64 + (o - 96);
            v = bhh[(c * 3 + l) * 96 + g];
        }
        sm[OFF_B + i] = v;
    }
    for (int i = tid; i < 13896; i += 512) sm[OFF_H0 + i] = 0.f;

    const float* gprev = g_outs_d + (size_t)(bc - 1) * Dn * 2048;  // valid iff c>0
    float* gcur = g_outs_d + (size_t)bc * Dn * 2048;
    const float* cchan = g_comb0 + (size_t)bc * Dn * 6144;
    const int* flag_prev = &g_flag[bc - 1];

    // prologue: stage prev-channel vector for step 0 (diag 0, row 0)
    if (haspc) {
        while (ld_acq(flag_prev) < 1) {}
        if (tid < 32) sm[OFF_PC + tid] = gprev[tid];
    }
    __syncthreads();

    for (int s = 0; s < Dn; ++s) {
        const int pong = s & 1, next = 1 - pong;
        const int lo = (s > 63) ? s - 63 : 0;
        const int hi = (s < 63) ? s : 63;
        const int nact = hi - lo + 1;
        const int RG = (nact > 32) ? 2 : 1;
        const int wpr = (RG == 2) ? 8 : 16;
        const int rg = (RG == 2) ? (warp & 1) : 0;
        const int slice = (RG == 2) ? (warp >> 1) : warp;

        const int jj = rg * 32 + lane;
        const bool valid = jj < nact;
        const int r = lo + (valid ? jj : (nact - 1));

        // ---- coalesced copy-out of previous step's layer-2 results ----
        if (s > 0) {
            const int lop = (s - 1 > 63) ? s - 64 : 0;
            const int hip = (s - 1 < 63) ? s - 1 : 63;
            const int np = hip - lop + 1;
            for (int idx = tid; idx < np * 32; idx += 512) {
                int j = idx >> 5, k = idx & 31, rr = lop + j;
                gcur[((size_t)(s - 1) * 64 + rr) * 32 + k] =
                    sm[OFF_H2 + pong * 2340 + (rr + 1) * 36 + k];
            }
        }

        // ================= layer 0 (comb folded into g_comb0) ==========
        {
            P4 h2p[8], h0c[8], pcc[8];
            load8s(sm + OFF_H2 + pong * 2340 + r * 36, h2p);
            load8s(sm + OFF_H0 + pong * 2304 + r * 36, h0c);
            if (haspc) load8s(sm + OFF_PC + pong * 2304 + r * 36, pcc);
            const float* cb = cchan + (size_t)s * 6144 + r;

            for (int k = slice; k < 32; k += wpr) {
                float c0r = cb[k * 64];
                float c0z = cb[(k + 32) * 64];
                float c0n = cb[(k + 64) * 64];
                unsigned long long ar = 0ull, az = 0ull, ani = 0ull, anh = 0ull;
                dot32(sm + OFF_M1 + k * 32, h2p, ar);
                dot32(sm + OFF_M1 + (k + 32) * 32, h2p, az);
                dot32(sm + OFF_M1 + (k + 64) * 32, h2p, ani);
                if (haspc) {
                    dot32(sm + OFF_M2 + k * 32, pcc, ar);
                    dot32(sm + OFF_M2 + (k + 32) * 32, pcc, az);
                    dot32(sm + OFF_M2 + (k + 64) * 32, pcc, ani);
                }
                dot32(sm + OFF_WHH0 + k * 32, h0c, ar);
                dot32(sm + OFF_WHH0 + (k + 32) * 32, h0c, az);
                dot32(sm + OFF_WHH0 + (k + 64) * 32, h0c, anh);
                float vr = red2(ar) + c0r;
                float vz = red2(az) + c0z;
                float vni = red2(ani) + c0n;
                float vnh = red2(anh) + sm[OFF_B + 96 + k];
                float rr = sigm(vr), zz = sigm(vz);
                float nn = tanhf(vni + rr * vnh);
                float hold = sm[OFF_H0 + pong * 2304 + r * 36 + k];
                float hnew = (1.f - zz) * nn + zz * hold;
                if (valid) sm[OFF_H0 + next * 2304 + r * 36 + k] = hnew;
            }
        }
        __syncthreads();

        // ---- publish: diags 0..s-1 of this channel are in g_outs_d ----
        if (c < 2 && tid == 0) {
            asm volatile("fence.acq_rel.gpu;" ::: "memory");
            asm volatile("st.global.release.gpu.s32 [%0], %1;"
                         :: "l"(&g_flag[bc]), "r"(s) : "memory");
        }

        // ---- stage prev-channel vectors for step s+1 (buffer `next`) ----
        if (haspc && s + 1 < Dn) {
            while (ld_acq(flag_prev) < s + 2) {}
            const int lo2 = (s + 1 > 63) ? s - 62 : 0;
            const int hi2 = (s + 1 < 63) ? s + 1 : 63;
            const int n2 = hi2 - lo2 + 1;
            for (int idx = tid; idx < n2 * 32; idx += 512) {
                int j = idx >> 5, k = idx & 31, rr = lo2 + j;
                sm[OFF_PC + next * 2304 + rr * 36 + k] =
                    gprev[((size_t)(s + 1) * 64 + rr) * 32 + k];
            }
        }

        // ================= layer 1 =================
        {
            P4 h0n[8], h1c[8];
            load8s(sm + OFF_H0 + next * 2304 + r * 36, h0n);
            load8s(sm + OFF_H1 + pong * 2304 + r * 36, h1c);
            for (int k = slice; k < 32; k += wpr) {
                unsigned long long ar = 0ull, az = 0ull, ani = 0ull, anh = 0ull;
                dot32(sm + OFF_WIH1 + k * 32, h0n, ar);
                dot32(sm + OFF_WHH1 + k * 32, h1c, ar);
                dot32(sm + OFF_WIH1 + (k + 32) * 32, h0n, az);
                dot32(sm + OFF_WHH1 + (k + 32) * 32, h1c, az);
                dot32(sm + OFF_WIH1 + (k + 64) * 32, h0n, ani);
                dot32(sm + OFF_WHH1 + (k + 64) * 32, h1c, anh);
                float vr = red2(ar) + sm[OFF_B + 128 + k];
                float vz = red2(az) + sm[OFF_B + 128 + k + 32];
                float vni = red2(ani) + sm[OFF_B + 128 + 64 + k];
                float vnh = red2(anh) + sm[OFF_B + 128 + 96 + k];
                float rr = sigm(vr), zz = sigm(vz);
                float nn = tanhf(vni + rr * vnh);
                float hold = sm[OFF_H1 + pong * 2304 + r * 36 + k];
                float hnew = (1.f - zz) * nn + zz * hold;
                if (valid) sm[OFF_H1 + next * 2304 + r * 36 + k] = hnew;
            }
        }
        __syncthreads();

        // ================= layer 2 =================
        {
            P4 h1n[8], h2c[8];
            load8s(sm + OFF_H1 + next * 2304 + r * 36, h1n);
            load8s(sm + OFF_H2 + pong * 2340 + (r + 1) * 36, h2c);
            for (int k = slice; k < 32; k += wpr) {
                unsigned long long ar = 0ull, az = 0ull, ani = 0ull, anh = 0ull;
                dot32(sm + OFF_WIH2 + k * 32, h1n, ar);
                dot32(sm + OFF_WHH2 + k * 32, h2c, ar);
                dot32(sm + OFF_WIH2 + (k + 32) * 32, h1n, az);
                dot32(sm + OFF_WHH2 + (k + 32) * 32, h2c, az);
                dot32(sm + OFF_WIH2 + (k + 64) * 32, h1n, ani);
                dot32(sm + OFF_WHH2 + (k + 64) * 32, h2c, anh);
                float vr = red2(ar) + sm[OFF_B + 256 + k];
                float vz = red2(az) + sm[OFF_B + 256 + k + 32];
                float vni = red2(ani) + sm[OFF_B + 256 + 64 + k];
                float vnh = red2(anh) + sm[OFF_B + 256 + 96 + k];
                float rr = sigm(vr), zz = sigm(vz);
                float nn = tanhf(vni + rr * vnh);
                float hold = sm[OFF_H2 + pong * 2340 + (r + 1) * 36 + k];
                float hnew = (1.f - zz) * nn + zz * hold;
                if (valid) sm[OFF_H2 + next * 2340 + (r + 1) * 36 + k] = hnew;
            }
        }
        // rolling zero: activate row s+1 for step s+1 (buffer `next`)
        if (s + 1 <= 63 && tid < 108) {
            int which = tid / 36, kk = tid - which * 36;
            if (which == 0)      sm[OFF_H0 + next * 2304 + (s + 1) * 36 + kk] = 0.f;
            else if (which == 1) sm[OFF_H1 + next * 2304 + (s + 1) * 36 + kk] = 0.f;
            else                 sm[OFF_H2 + next * 2340 + (s + 2) * 36 + kk] = 0.f;
        }
        __syncthreads();
    }
    // final copy-out: step 126 results live in buffer next(126) = 1
    if (tid < 32)
        gcur[((size_t)126 * 64 + 63) * 32 + tid] =
            sm[OFF_H2 + 1 * 2340 + 64 * 36 + tid];
    if (c < 2) {
        __syncthreads();
        if (tid == 0) {
            asm volatile("fence.acq_rel.gpu;" ::: "memory");
            asm volatile("st.global.release.gpu.s32 [%0], %1;"
                         :: "l"(&g_flag[bc]), "r"(200) : "memory");
        }
    }
}

// ---------------------------------------------------------------------------
// Kernel: output logits, f32x2 inner loop, 4 rows per block (weights staged once)
// ---------------------------------------------------------------------------
template <int N4>
__device__ __forceinline__ void compute_logits(const float* __restrict__ Ws,
                                               const float* __restrict__ ins,
                                               const float* __restrict__ bs,
                                               float* __restrict__ outp, int tid) {
    constexpr int Kp = N4 * 4;
    for (int tile = tid; tile < 65 * 32; tile += 512) {
        int vg = tile / 32, tg = tile - vg * 32;
        int t0 = tg * 2, v0 = vg * 4;
        const ulonglong2* w0 = reinterpret_cast<const ulonglong2*>(&Ws[(v0 + 0) * Kp]);
        const ulonglong2* w1 = reinterpret_cast<const ulonglong2*>(&Ws[(v0 + 1) * Kp]);
        const ulonglong2* w2 = reinterpret_cast<const ulonglong2*>(&Ws[(v0 + 2) * Kp]);
        const ulonglong2* w3 = reinterpret_cast<const ulonglong2*>(&Ws[(v0 + 3) * Kp]);
        const ulonglong2* i0 = reinterpret_cast<const ulonglong2*>(&ins[t0 * Kp]);
        const ulonglong2* i1 = reinterpret_cast<const ulonglong2*>(&ins[(t0 + 1) * Kp]);
        unsigned long long a0[4] = {0ull, 0ull, 0ull, 0ull};
        unsigned long long a1[4] = {0ull, 0ull, 0ull, 0ull};
#pragma unroll 4
        for (int k = 0; k < N4; ++k) {
            ulonglong2 x0 = i0[k], x1 = i1[k];
            ulonglong2 y;
            y = w0[k];
            fma2(a0[0], y.x, x0.x); fma2(a0[0], y.y, x0.y);
            fma2(a1[0], y.x, x1.x); fma2(a1[0], y.y, x1.y);
            y = w1[k];
            fma2(a0[1], y.x, x0.x); fma2(a0[1], y.y, x0.y);
            fma2(a1[1], y.x, x1.x); fma2(a1[1], y.y, x1.y);
            y = w2[k];
            fma2(a0[2], y.x, x0.x); fma2(a0[2], y.y, x0.y);
            fma2(a1[2], y.x, x1.x); fma2(a1[2], y.y, x1.y);
            y = w3[k];
            fma2(a0[3], y.x, x0.x); fma2(a0[3], y.y, x0.y);
            fma2(a1[3], y.x, x1.x); fma2(a1[3], y.y, x1.y);
        }
        int ob0 = t0 * Vn, ob1 = ob0 + Vn;
#pragma unroll
        for (int v = 0; v < 4; ++v) {
            int vv = v0 + v;
            if (vv < Vn) {
                float bv = bs[vv];
                outp[ob0 + vv] = red2(a0[v]) + bv;
                outp[ob1 + vv] = red2(a1[v]) + bv;
            }
        }
    }
}

__global__ __launch_bounds__(512, 1)
void logits_kernel(const float* __restrict__ emb, const int* __restrict__ target,
                   const float* __restrict__ W0, const float* __restrict__ b0,
                   const float* __restrict__ W1, const float* __restrict__ b1,
                   const float* __restrict__ W2, const float* __restrict__ b2,
                   float* __restrict__ out) {
    extern __shared__ float sm[];
    const int tid = threadIdx.x;
    const int ch = blockIdx.y;

    const float* W;
    const float* Bb;
    int K;
    if (ch == 0)      { W = W0; Bb = b0; K = 32; }
    else if (ch == 1) { W = W1; Bb = b1; K = 96; }
    else              { W = W2; Bb = b2; K = 160; }
    const int Kp = K + 4;

    float* Ws = sm;
    float* ins = sm + 260 * Kp;
    float* bs = ins + 64 * Kp;

    for (int idx = tid; idx < 260 * Kp; idx += 512) {
        int v = idx / Kp, k = idx - v * Kp;
        Ws[idx] = (v < Vn && k < K) ? W[v * K + k] : 0.f;
    }
    for (int idx = tid; idx < 260; idx += 512)
        bs[idx] = (idx < Vn) ? Bb[idx] : 0.f;

    for (int i = 0; i < 4; ++i) {
        const int rowidx = blockIdx.x * 4 + i;
        const int bb = rowidx >> 6;
        const int r = rowidx & 63;
        __syncthreads();   // Ws ready / prior row's compute done with ins

        const size_t diagbase = (size_t)(bb * 3 + ch) * Dn;
        for (int idx = tid; idx < 64 * Kp; idx += 512) {
            int t = idx / Kp, k = idx - t * Kp;
            float val = 0.f;
            if (k < 32) {
                val = g_outs_d[(diagbase + (r + t)) * 2048 + r * 32 + k];
            } else if (k < K) {
                int kk = k - 32;
                int chE = (kk < 64) ? 0 : 1;
                int ke = (kk < 64) ? kk : kk - 64;
                int tg = target[((bb * 3 + chE) * Rn + r) * Sn + t];
                val = emb[(size_t)(chE * Vn + tg) * En + ke];
            }
            ins[idx] = val;
        }
        __syncthreads();

        const int rowbase = ((bb * 3 + ch) * Rn + r) * Sn;
        float* outp = out + (size_t)rowbase * Vn;
        if (K == 32)       compute_logits<9>(Ws, ins, bs, outp, tid);
        else if (K == 96)  compute_logits<25>(Ws, ins, bs, outp, tid);
        else               compute_logits<41>(Ws, ins, bs, outp, tid);
    }
}

// ---------------------------------------------------------------------------
// Launch
// ---------------------------------------------------------------------------
extern "C" void kernel_launch(void* const* d_in, const int* in_sizes, int n_in,
                              void* d_out, int out_size) {
    (void)in_sizes; (void)n_in; (void)out_size;
    const int*   x      = (const int*)  d_in[0];
    const int*   target = (const int*)  d_in[1];
    const float* emb    = (const float*)d_in[2];
    const float* Wih0   = (const float*)d_in[3];
    const float* WihR   = (const float*)d_in[4];
    const float* Whh    = (const float*)d_in[5];
    const float* bih    = (const float*)d_in[6];
    const float* bhh    = (const float*)d_in[7];
    const float* h2eW   = (const float*)d_in[8];
    const float* h2eb   = (const float*)d_in[9];
    const float* adpW   = (const float*)d_in[10];
    const float* adpb   = (const float*)d_in[11];
    const float* redW   = (const float*)d_in[12];
    const float* redb   = (const float*)d_in[13];
    const float* greenW = (const float*)d_in[14];
    const float* greenb = (const float*)d_in[15];
    const float* blueW  = (const float*)d_in[16];
    const float* blueb  = (const float*)d_in[17];
    float* out = (float*)d_out;

    const size_t smem_rnn = (size_t)SM_TOT * sizeof(float);                       // 161,568 B
    const size_t smem_log = (size_t)(260 * 164 + 64 * 164 + 260) * sizeof(float); // 213,584 B

    cudaFuncSetAttribute(rnn_kernel, cudaFuncAttributeMaxDynamicSharedMemorySize,
                         (int)smem_rnn);
    cudaFuncSetAttribute(logits_kernel, cudaFuncAttributeMaxDynamicSharedMemorySize,
                         (int)smem_log);

    pre_kernel<<<352, 256>>>(emb, Wih0, h2eW, h2eb, adpW, adpb, bih);
    pre2_kernel<<<dim3(Dn, Bn * 3), 256>>>(x, Wih0, bhh);
    rnn_kernel<<<Bn * 3, 512, smem_rnn>>>(WihR, Whh, bih, bhh);
    logits_kernel<<<dim3(Bn * Rn / 4, 3), 512, smem_log>>>(emb, target, redW, redb,
                                                           greenW, greenb, blueW,
                                                           blueb, out);
}

// round 11
// speedup vs baseline: 8.2271x; 1.3365x over previous
#include <cuda_runtime.h>
#include <math.h>

// ---------------------------------------------------------------------------
// Problem constants
// ---------------------------------------------------------------------------
#define Bn 16
#define Hn 32
#define En 64
#define Vn 258
#define Rn 64
#define Sn 64
#define Dn 127   // number of wavefront diagonals (r + t)

// ---------------------------------------------------------------------------
// Global scratch (static __device__, no allocation)
// ---------------------------------------------------------------------------
__device__ float g_outs_d[Bn * 3 * Dn * Rn * Hn];        // diag layout [b][c][s][r][k]
__device__ float g_comb0[(size_t)Bn * 3 * Dn * 96 * 64]; // [b][c][s][g][r]
__device__ float g_T0[3 * 258 * 96];                     // Wih0 @ emb
__device__ float g_M1[3 * 96 * 32];                      // Wih0 @ h2eW
__device__ float g_M2[2 * 96 * 32];                      // Wih0 @ adpW
__device__ float g_b0[3 * 96];                           // bih0 + Wih0@(h2eb[+adpb])
__device__ int   g_flag[Bn * 3];                         // diag progress per (b,c)

// ---------------------------------------------------------------------------
// Packed f32x2 helpers
// ---------------------------------------------------------------------------
union P4 { float4 f; ulonglong2 u; };

__device__ __forceinline__ void fma2(unsigned long long& acc,
                                     unsigned long long a,
                                     unsigned long long b) {
    asm("fma.rn.f32x2 %0, %1, %2, %0;" : "+l"(acc) : "l"(a), "l"(b));
}
__device__ __forceinline__ float red2(unsigned long long acc) {
    float x, y;
    asm("mov.b64 {%0, %1}, %2;" : "=f"(x), "=f"(y) : "l"(acc));
    return x + y;
}
__device__ __forceinline__ void dot32(const float* __restrict__ w,
                                      const P4 x[8], unsigned long long& acc) {
    const ulonglong2* W = reinterpret_cast<const ulonglong2*>(w);
#pragma unroll
    for (int i = 0; i < 8; ++i) {
        ulonglong2 wv = W[i];
        fma2(acc, wv.x, x[i].u.x);
        fma2(acc, wv.y, x[i].u.y);
    }
}
__device__ __forceinline__ void load8s(const float* __restrict__ p, P4 x[8]) {
    const float4* q = reinterpret_cast<const float4*>(p);
#pragma unroll
    for (int i = 0; i < 8; ++i) x[i].f = q[i];
}
__device__ __forceinline__ float sigm(float x) {
    return 1.f / (1.f + __expf(-x));
}
__device__ __forceinline__ int ld_acq(const int* p) {
    int v;
    asm volatile("ld.global.acquire.gpu.s32 %0, [%1];" : "=r"(v) : "l"(p));
    return v;
}

// ---------------------------------------------------------------------------
// Pre-kernel 1: fold comb linear algebra into tables (+ zero pipeline flags)
// ---------------------------------------------------------------------------
__global__ void pre_kernel(const float* __restrict__ emb,
                           const float* __restrict__ Wih0,
                           const float* __restrict__ h2eW,
                           const float* __restrict__ h2eb,
                           const float* __restrict__ adpW,
                           const float* __restrict__ adpb,
                           const float* __restrict__ bih) {
    int idx = blockIdx.x * 256 + threadIdx.x;
    if (idx < 74304) {                       // T0[c][v][g]
        int c = idx / 24768, rem = idx % 24768;
        int v = rem / 96, g = rem % 96;
        const float* w = Wih0 + c * 6240 + g * 65;
        const float* e = emb + (size_t)(c * 258 + v) * 64;
        float s = 0.f;
        for (int j = 0; j < 64; ++j) s = fmaf(w[j], e[j], s);
        g_T0[idx] = s;
    } else if (idx < 74304 + 9216) {         // M1[c][g][j]
        int i = idx - 74304;
        int c = i / 3072, rem = i % 3072, g = rem / 32, j = rem % 32;
        const float* w = Wih0 + c * 6240 + g * 65;
        float s = 0.f;
        for (int e = 0; e < 65; ++e) s = fmaf(w[e], h2eW[c * 2080 + e * 32 + j], s);
        g_M1[i] = s;
    } else if (idx < 74304 + 9216 + 6144) {  // M2[c2][g][j]
        int i = idx - 74304 - 9216;
        int c2 = i / 3072, rem = i % 3072, g = rem / 32, j = rem % 32;
        const float* w = Wih0 + (c2 + 1) * 6240 + g * 65;
        float s = 0.f;
        for (int e = 0; e < 65; ++e) s = fmaf(w[e], adpW[c2 * 2080 + e * 32 + j], s);
        g_M2[i] = s;
    } else if (idx < 74304 + 9216 + 6144 + 288) {   // b0[c][g]
        int i = idx - 74304 - 9216 - 6144;
        int c = i / 96, g = i % 96;
        const float* w = Wih0 + c * 6240 + g * 65;
        float s = bih[c * 288 + g];
        for (int e = 0; e < 65; ++e) s = fmaf(w[e], h2eb[c * 65 + e], s);
        if (c > 0)
            for (int e = 0; e < 65; ++e) s = fmaf(w[e], adpb[(c - 1) * 65 + e], s);
        g_b0[i] = s;
    } else if (idx < 89952 + 48) {           // zero pipeline flags
        g_flag[idx - 89952] = 0;
    }
}

// ---------------------------------------------------------------------------
// Pre-kernel 2: materialize comb0 per cell, diagonal layout [b][c][s][g][r].
// ---------------------------------------------------------------------------
__global__ void pre2_kernel(const int* __restrict__ x,
                            const float* __restrict__ Wih0,
                            const float* __restrict__ bhh) {
    __shared__ float w64s[96], bias_s[96];
    __shared__ int xs[64];
    const int s = blockIdx.x;
    const int bc = blockIdx.y;           // b*3 + c
    const int c = bc % 3;
    const int tid = threadIdx.x;
    const int lo = (s > 63) ? s - 63 : 0;
    const int hi = (s < 63) ? s : 63;
    if (tid < 96) {
        w64s[tid] = Wih0[c * 6240 + tid * 65 + 64];
        float bb = g_b0[c * 96 + tid];
        if (tid < 64) bb += bhh[c * 288 + tid];      // bhh r,z (layer 0)
        bias_s[tid] = bb;
    }
    if (tid >= 96 && tid - 96 <= hi - lo) {
        int r = lo + (tid - 96);
        xs[r] = x[(bc * 64 + r) * 64 + (s - r)];
    }
    __syncthreads();
    float* outp = g_comb0 + ((size_t)bc * Dn + s) * 6144;
    const float* t0c = g_T0 + c * 258 * 96;
    for (int idx = tid; idx < 96 * 64; idx += 256) {
        int g = idx >> 6, r = idx & 63;
        if (r < lo || r > hi) continue;
        float rf = (float)r * 0.03125f - 1.0f;
        outp[idx] = t0c[xs[r] * 96 + g] + rf * w64s[g] + bias_s[g];
    }
}

// ---------------------------------------------------------------------------
// Shared-memory layout for the RNN role (floats)
// ---------------------------------------------------------------------------
constexpr int OFF_M1   = 0;        // 96 x 32
constexpr int OFF_M2   = 3072;
constexpr int OFF_WHH0 = 6144;
constexpr int OFF_WIH1 = 9216;
constexpr int OFF_WHH1 = 12288;
constexpr int OFF_WIH2 = 15360;
constexpr int OFF_WHH2 = 18432;
constexpr int OFF_B    = 21504;    // 3 x 128 (layer biases; l=0 uses only nh part)
constexpr int OFF_H0   = 21888;    // 2 x (64 x 36) ping-pong
constexpr int OFF_H1   = 26496;    // 2 x (64 x 36)
constexpr int OFF_H2   = 31104;    // 2 x (65 x 36), slot r+1 = row r, slot 0 = 0
constexpr int OFF_PC   = 35784;    // 2 x (64 x 36) prev-channel staging (double buf)

// ---------------------------------------------------------------------------
// RNN role: channel-pipelined wavefront row-RNN (one block per b x c).
// ---------------------------------------------------------------------------
__device__ void rnn_body(float* sm, int bc,
                         const float* __restrict__ WihR,
                         const float* __restrict__ Whh,
                         const float* __restrict__ bih,
                         const float* __restrict__ bhh) {
    const int tid = threadIdx.x;
    const int warp = tid >> 5, lane = tid & 31;
    const int c = bc % 3;
    const bool haspc = (c > 0);

    // ---- stage weights (once) ----
    for (int i = tid; i < 3072; i += 512) {
        sm[OFF_M1 + i]   = g_M1[c * 3072 + i];
        sm[OFF_WHH0 + i] = Whh[c * 9216 + i];
        sm[OFF_WIH1 + i] = WihR[c * 6144 + i];
        sm[OFF_WHH1 + i] = Whh[c * 9216 + 3072 + i];
        sm[OFF_WIH2 + i] = WihR[c * 6144 + 3072 + i];
        sm[OFF_WHH2 + i] = Whh[c * 9216 + 6144 + i];
        if (haspc) sm[OFF_M2 + i] = g_M2[(c - 1) * 3072 + i];
    }
    for (int i = tid; i < 384; i += 512) {
        int l = i >> 7, o = i & 127;
        float v;
        if (o < 64)
            v = ((l == 0) ? 0.f : bih[(c * 3 + l) * 96 + o] +
                                  bhh[(c * 3 + l) * 96 + o]);
        else if (o < 96) {
            int g = 64 + (o - 64);
            v = (l == 0) ? 0.f : bih[(c * 3 + l) * 96 + g];
        } else {
            int g = 64 + (o - 96);
            v = bhh[(c * 3 + l) * 96 + g];
        }
        sm[OFF_B + i] = v;
    }
    for (int i = tid; i < 13896; i += 512) sm[OFF_H0 + i] = 0.f;

    const float* gprev = g_outs_d + (size_t)(bc - 1) * Dn * 2048;  // valid iff c>0
    float* gcur = g_outs_d + (size_t)bc * Dn * 2048;
    const float* cchan = g_comb0 + (size_t)bc * Dn * 6144;
    const int* flag_prev = &g_flag[bc - 1];

    // prologue: stage prev-channel vector for step 0 (diag 0, row 0)
    if (haspc) {
        while (ld_acq(flag_prev) < 1) {}
        if (tid < 32) sm[OFF_PC + tid] = gprev[tid];
    }
    __syncthreads();

    for (int s = 0; s < Dn; ++s) {
        const int pong = s & 1, next = 1 - pong;
        const int lo = (s > 63) ? s - 63 : 0;
        const int hi = (s < 63) ? s : 63;
        const int nact = hi - lo + 1;
        const int RG = (nact > 32) ? 2 : 1;
        const int wpr = (RG == 2) ? 8 : 16;
        const int rg = (RG == 2) ? (warp & 1) : 0;
        const int slice = (RG == 2) ? (warp >> 1) : warp;

        const int jj = rg * 32 + lane;
        const bool valid = jj < nact;
        const int r = lo + (valid ? jj : (nact - 1));

        // ---- coalesced copy-out of previous step's layer-2 results ----
        if (s > 0) {
            const int lop = (s - 1 > 63) ? s - 64 : 0;
            const int hip = (s - 1 < 63) ? s - 1 : 63;
            const int np = hip - lop + 1;
            for (int idx = tid; idx < np * 32; idx += 512) {
                int j = idx >> 5, k = idx & 31, rr = lop + j;
                gcur[((size_t)(s - 1) * 64 + rr) * 32 + k] =
                    sm[OFF_H2 + pong * 2340 + (rr + 1) * 36 + k];
            }
        }

        // ================= layer 0 (comb folded into g_comb0) ==========
        {
            P4 h2p[8], h0c[8], pcc[8];
            load8s(sm + OFF_H2 + pong * 2340 + r * 36, h2p);
            load8s(sm + OFF_H0 + pong * 2304 + r * 36, h0c);
            if (haspc) load8s(sm + OFF_PC + pong * 2304 + r * 36, pcc);
            const float* cb = cchan + (size_t)s * 6144 + r;

            for (int k = slice; k < 32; k += wpr) {
                float c0r = cb[k * 64];
                float c0z = cb[(k + 32) * 64];
                float c0n = cb[(k + 64) * 64];
                unsigned long long ar = 0ull, az = 0ull, ani = 0ull, anh = 0ull;
                dot32(sm + OFF_M1 + k * 32, h2p, ar);
                dot32(sm + OFF_M1 + (k + 32) * 32, h2p, az);
                dot32(sm + OFF_M1 + (k + 64) * 32, h2p, ani);
                if (haspc) {
                    dot32(sm + OFF_M2 + k * 32, pcc, ar);
                    dot32(sm + OFF_M2 + (k + 32) * 32, pcc, az);
                    dot32(sm + OFF_M2 + (k + 64) * 32, pcc, ani);
                }
                dot32(sm + OFF_WHH0 + k * 32, h0c, ar);
                dot32(sm + OFF_WHH0 + (k + 32) * 32, h0c, az);
                dot32(sm + OFF_WHH0 + (k + 64) * 32, h0c, anh);
                float vr = red2(ar) + c0r;
                float vz = red2(az) + c0z;
                float vni = red2(ani) + c0n;
                float vnh = red2(anh) + sm[OFF_B + 96 + k];
                float rr = sigm(vr), zz = sigm(vz);
                float nn = tanhf(vni + rr * vnh);
                float hold = sm[OFF_H0 + pong * 2304 + r * 36 + k];
                float hnew = (1.f - zz) * nn + zz * hold;
                if (valid) sm[OFF_H0 + next * 2304 + r * 36 + k] = hnew;
            }
        }
        __syncthreads();

        // ---- publish: diags 0..s-1 of this channel are in g_outs_d ----
        if (tid == 0) {
            asm volatile("fence.acq_rel.gpu;" ::: "memory");
            asm volatile("st.global.release.gpu.s32 [%0], %1;"
                         :: "l"(&g_flag[bc]), "r"(s) : "memory");
        }

        // ---- stage prev-channel vectors for step s+1 (buffer `next`) ----
        if (haspc && s + 1 < Dn) {
            while (ld_acq(flag_prev) < s + 2) {}
            const int lo2 = (s + 1 > 63) ? s - 62 : 0;
            const int hi2 = (s + 1 < 63) ? s + 1 : 63;
            const int n2 = hi2 - lo2 + 1;
            for (int idx = tid; idx < n2 * 32; idx += 512) {
                int j = idx >> 5, k = idx & 31, rr = lo2 + j;
                sm[OFF_PC + next * 2304 + rr * 36 + k] =
                    gprev[((size_t)(s + 1) * 64 + rr) * 32 + k];
            }
        }

        // ================= layer 1 =================
        {
            P4 h0n[8], h1c[8];
            load8s(sm + OFF_H0 + next * 2304 + r * 36, h0n);
            load8s(sm + OFF_H1 + pong * 2304 + r * 36, h1c);
            for (int k = slice; k < 32; k += wpr) {
                unsigned long long ar = 0ull, az = 0ull, ani = 0ull, anh = 0ull;
                dot32(sm + OFF_WIH1 + k * 32, h0n, ar);
                dot32(sm + OFF_WHH1 + k * 32, h1c, ar);
                dot32(sm + OFF_WIH1 + (k + 32) * 32, h0n, az);
                dot32(sm + OFF_WHH1 + (k + 32) * 32, h1c, az);
                dot32(sm + OFF_WIH1 + (k + 64) * 32, h0n, ani);
                dot32(sm + OFF_WHH1 + (k + 64) * 32, h1c, anh);
                float vr = red2(ar) + sm[OFF_B + 128 + k];
                float vz = red2(az) + sm[OFF_B + 128 + k + 32];
                float vni = red2(ani) + sm[OFF_B + 128 + 64 + k];
                float vnh = red2(anh) + sm[OFF_B + 128 + 96 + k];
                float rr = sigm(vr), zz = sigm(vz);
                float nn = tanhf(vni + rr * vnh);
                float hold = sm[OFF_H1 + pong * 2304 + r * 36 + k];
                float hnew = (1.f - zz) * nn + zz * hold;
                if (valid) sm[OFF_H1 + next * 2304 + r * 36 + k] = hnew;
            }
        }
        __syncthreads();

        // ================= layer 2 =================
        {
            P4 h1n[8], h2c[8];
            load8s(sm + OFF_H1 + next * 2304 + r * 36, h1n);
            load8s(sm + OFF_H2 + pong * 2340 + (r + 1) * 36, h2c);
            for (int k = slice; k < 32; k += wpr) {
                unsigned long long ar = 0ull, az = 0ull, ani = 0ull, anh = 0ull;
                dot32(sm + OFF_WIH2 + k * 32, h1n, ar);
                dot32(sm + OFF_WHH2 + k * 32, h2c, ar);
                dot32(sm + OFF_WIH2 + (k + 32) * 32, h1n, az);
                dot32(sm + OFF_WHH2 + (k + 32) * 32, h2c, az);
                dot32(sm + OFF_WIH2 + (k + 64) * 32, h1n, ani);
                dot32(sm + OFF_WHH2 + (k + 64) * 32, h2c, anh);
                float vr = red2(ar) + sm[OFF_B + 256 + k];
                float vz = red2(az) + sm[OFF_B + 256 + k + 32];
                float vni = red2(ani) + sm[OFF_B + 256 + 64 + k];
                float vnh = red2(anh) + sm[OFF_B + 256 + 96 + k];
                float rr = sigm(vr), zz = sigm(vz);
                float nn = tanhf(vni + rr * vnh);
                float hold = sm[OFF_H2 + pong * 2340 + (r + 1) * 36 + k];
                float hnew = (1.f - zz) * nn + zz * hold;
                if (valid) sm[OFF_H2 + next * 2340 + (r + 1) * 36 + k] = hnew;
            }
        }
        // rolling zero: activate row s+1 for step s+1 (buffer `next`)
        if (s + 1 <= 63 && tid < 108) {
            int which = tid / 36, kk = tid - which * 36;
            if (which == 0)      sm[OFF_H0 + next * 2304 + (s + 1) * 36 + kk] = 0.f;
            else if (which == 1) sm[OFF_H1 + next * 2304 + (s + 1) * 36 + kk] = 0.f;
            else                 sm[OFF_H2 + next * 2340 + (s + 2) * 36 + kk] = 0.f;
        }
        __syncthreads();
    }
    // final copy-out: step 126 results live in buffer next(126) = 1
    if (tid < 32)
        gcur[((size_t)126 * 64 + 63) * 32 + tid] =
            sm[OFF_H2 + 1 * 2340 + 64 * 36 + tid];
    __syncthreads();
    if (tid == 0) {
        asm volatile("fence.acq_rel.gpu;" ::: "memory");
        asm volatile("st.global.release.gpu.s32 [%0], %1;"
                     :: "l"(&g_flag[bc]), "r"(200) : "memory");
    }
}

// ---------------------------------------------------------------------------
// Logits role: one row per block, f32x2 inner loop, flag-gated on RNN progress.
// ---------------------------------------------------------------------------
template <int N4>
__device__ __forceinline__ void compute_logits(const float* __restrict__ Ws,
                                               const float* __restrict__ ins,
                                               const float* __restrict__ bs,
                                               float* __restrict__ outp, int tid) {
    constexpr int Kp = N4 * 4;
    for (int tile = tid; tile < 65 * 32; tile += 512) {
        int vg = tile / 32, tg = tile - vg * 32;
        int t0 = tg * 2, v0 = vg * 4;
        const ulonglong2* w0 = reinterpret_cast<const ulonglong2*>(&Ws[(v0 + 0) * Kp]);
        const ulonglong2* w1 = reinterpret_cast<const ulonglong2*>(&Ws[(v0 + 1) * Kp]);
        const ulonglong2* w2 = reinterpret_cast<const ulonglong2*>(&Ws[(v0 + 2) * Kp]);
        const ulonglong2* w3 = reinterpret_cast<const ulonglong2*>(&Ws[(v0 + 3) * Kp]);
        const ulonglong2* i0 = reinterpret_cast<const ulonglong2*>(&ins[t0 * Kp]);
        const ulonglong2* i1 = reinterpret_cast<const ulonglong2*>(&ins[(t0 + 1) * Kp]);
        unsigned long long a0[4] = {0ull, 0ull, 0ull, 0ull};
        unsigned long long a1[4] = {0ull, 0ull, 0ull, 0ull};
#pragma unroll 4
        for (int k = 0; k < N4; ++k) {
            ulonglong2 x0 = i0[k], x1 = i1[k];
            ulonglong2 y;
            y = w0[k];
            fma2(a0[0], y.x, x0.x); fma2(a0[0], y.y, x0.y);
            fma2(a1[0], y.x, x1.x); fma2(a1[0], y.y, x1.y);
            y = w1[k];
            fma2(a0[1], y.x, x0.x); fma2(a0[1], y.y, x0.y);
            fma2(a1[1], y.x, x1.x); fma2(a1[1], y.y, x1.y);
            y = w2[k];
            fma2(a0[2], y.x, x0.x); fma2(a0[2], y.y, x0.y);
            fma2(a1[2], y.x, x1.x); fma2(a1[2], y.y, x1.y);
            y = w3[k];
            fma2(a0[3], y.x, x0.x); fma2(a0[3], y.y, x0.y);
            fma2(a1[3], y.x, x1.x); fma2(a1[3], y.y, x1.y);
        }
        int ob0 = t0 * Vn, ob1 = ob0 + Vn;
#pragma unroll
        for (int v = 0; v < 4; ++v) {
            int vv = v0 + v;
            if (vv < Vn) {
                float bv = bs[vv];
                outp[ob0 + vv] = red2(a0[v]) + bv;
                outp[ob1 + vv] = red2(a1[v]) + bv;
            }
        }
    }
}

__device__ void logits_body(float* sm, int lid,
                            const float* __restrict__ emb,
                            const int* __restrict__ target,
                            const float* __restrict__ W0, const float* __restrict__ b0,
                            const float* __restrict__ W1, const float* __restrict__ b1,
                            const float* __restrict__ W2, const float* __restrict__ b2,
                            float* __restrict__ out) {
    const int tid = threadIdx.x;
    // lid -> (r, bb, ch): r-major so earliest-ready rows get resident blocks
    const int r = lid / 48;
    const int rem = lid - r * 48;
    const int bb = rem / 3;
    const int ch = rem - bb * 3;

    const float* W;
    const float* Bb;
    int K;
    if (ch == 0)      { W = W0; Bb = b0; K = 32; }
    else if (ch == 1) { W = W1; Bb = b1; K = 96; }
    else              { W = W2; Bb = b2; K = 160; }
    const int Kp = K + 4;

    float* Ws = sm;
    float* ins = sm + 260 * Kp;
    float* bs = ins + 64 * Kp;

    // stage weights first (independent of RNN progress)
    for (int idx = tid; idx < 260 * Kp; idx += 512) {
        int v = idx / Kp, k = idx - v * Kp;
        Ws[idx] = (v < Vn && k < K) ? W[v * K + k] : 0.f;
    }
    for (int idx = tid; idx < 260; idx += 512)
        bs[idx] = (idx < Vn) ? Bb[idx] : 0.f;

    // wait for RNN: diags r..r+63 of (bb, ch) published when flag >= r+64
    const int need = r + 64;
    const int* fp = &g_flag[bb * 3 + ch];
    if (tid == 0) {
        int v = ld_acq(fp);
        while (v < need) { __nanosleep(256); v = ld_acq(fp); }
    }
    __syncthreads();   // broadcast acquire to block (leader-acquire + barrier)

    const size_t diagbase = (size_t)(bb * 3 + ch) * Dn;
    for (int idx = tid; idx < 64 * Kp; idx += 512) {
        int t = idx / Kp, k = idx - t * Kp;
        float val = 0.f;
        if (k < 32) {
            val = __ldcg(&g_outs_d[(diagbase + (r + t)) * 2048 + r * 32 + k]);
        } else if (k < K) {
            int kk = k - 32;
            int chE = (kk < 64) ? 0 : 1;
            int ke = (kk < 64) ? kk : kk - 64;
            int tg = target[((bb * 3 + chE) * Rn + r) * Sn + t];
            val = emb[(size_t)(chE * Vn + tg) * En + ke];
        }
        ins[idx] = val;
    }
    __syncthreads();

    const int rowbase = ((bb * 3 + ch) * Rn + r) * Sn;
    float* outp = out + (size_t)rowbase * Vn;
    if (K == 32)       compute_logits<9>(Ws, ins, bs, outp, tid);
    else if (K == 96)  compute_logits<25>(Ws, ins, bs, outp, tid);
    else               compute_logits<41>(Ws, ins, bs, outp, tid);
}

// ---------------------------------------------------------------------------
// Fused kernel: blocks 0..47 = RNN producers, blocks 48.. = logits consumers.
// 1 block/SM (smem-limited) => all 48 producers are resident in wave 1;
// flags are monotonic so later consumer blocks can never deadlock.
// ---------------------------------------------------------------------------
__global__ __launch_bounds__(512, 1)
void fused_kernel(const float* __restrict__ WihR, const float* __restrict__ Whh,
                  const float* __restrict__ bih, const float* __restrict__ bhh,
                  const float* __restrict__ emb, const int* __restrict__ target,
                  const float* __restrict__ W0, const float* __restrict__ b0,
                  const float* __restrict__ W1, const float* __restrict__ b1,
                  const float* __restrict__ W2, const float* __restrict__ b2,
                  float* __restrict__ out) {
    extern __shared__ float sm[];
    if (blockIdx.x < Bn * 3) {
        rnn_body(sm, blockIdx.x, WihR, Whh, bih, bhh);
    } else {
        logits_body(sm, blockIdx.x - Bn * 3, emb, target, W0, b0, W1, b1,
                    W2, b2, out);
    }
}

// ---------------------------------------------------------------------------
// Launch
// ---------------------------------------------------------------------------
extern "C" void kernel_launch(void* const* d_in, const int* in_sizes, int n_in,
                              void* d_out, int out_size) {
    (void)in_sizes; (void)n_in; (void)out_size;
    const int*   x      = (const int*)  d_in[0];
    const int*   target = (const int*)  d_in[1];
    const float* emb    = (const float*)d_in[2];
    const float* Wih0   = (const float*)d_in[3];
    const float* WihR   = (const float*)d_in[4];
    const float* Whh    = (const float*)d_in[5];
    const float* bih    = (const float*)d_in[6];
    const float* bhh    = (const float*)d_in[7];
    const float* h2eW   = (const float*)d_in[8];
    const float* h2eb   = (const float*)d_in[9];
    const float* adpW   = (const float*)d_in[10];
    const float* adpb   = (const float*)d_in[11];
    const float* redW   = (const float*)d_in[12];
    const float* redb   = (const float*)d_in[13];
    const float* greenW = (const float*)d_in[14];
    const float* greenb = (const float*)d_in[15];
    const float* blueW  = (const float*)d_in[16];
    const float* blueb  = (const float*)d_in[17];
    float* out = (float*)d_out;

    // logits role needs the most smem: 260*164 + 64*164 + 260 floats
    const size_t smem_fused = (size_t)(260 * 164 + 64 * 164 + 260) * sizeof(float);

    cudaFuncSetAttribute(fused_kernel, cudaFuncAttributeMaxDynamicSharedMemorySize,
                         (int)smem_fused);

    pre_kernel<<<352, 256>>>(emb, Wih0, h2eW, h2eb, adpW, adpb, bih);
    pre2_kernel<<<dim3(Dn, Bn * 3), 256>>>(x, Wih0, bhh);
    fused_kernel<<<Bn * 3 + Bn * Rn * 3, 512, smem_fused>>>(
        WihR, Whh, bih, bhh, emb, target, redW, redb, greenW, greenb,
        blueW, blueb, out);
}

// round 12
// speedup vs baseline: 9.3555x; 1.1372x over previous
#include <cuda_runtime.h>
#include <math.h>

// ---------------------------------------------------------------------------
// Problem constants
// ---------------------------------------------------------------------------
#define Bn 16
#define Hn 32
#define En 64
#define Vn 258
#define Rn 64
#define Sn 64
#define Dn 127   // number of wavefront diagonals (r + t)

// ---------------------------------------------------------------------------
// Global scratch (static __device__, no allocation)
// ---------------------------------------------------------------------------
__device__ float g_outs_d[Bn * 3 * Dn * Rn * Hn];        // diag layout [b][c][s][r][k]
__device__ float g_comb0[(size_t)Bn * 3 * Dn * 96 * 64]; // [b][c][s][g][r]
__device__ float g_T0[3 * 258 * 96];                     // Wih0 @ emb
__device__ float g_M1[3 * 96 * 32];                      // Wih0 @ h2eW
__device__ float g_M2[2 * 96 * 32];                      // Wih0 @ adpW
__device__ float g_b0[3 * 96];                           // bih0 + Wih0@(h2eb[+adpb])
__device__ int   g_flagH[Bn * 3 * 2];                    // diag progress per (b,c,half)

// ---------------------------------------------------------------------------
// Packed f32x2 helpers
// ---------------------------------------------------------------------------
union P4 { float4 f; ulonglong2 u; };

__device__ __forceinline__ void fma2(unsigned long long& acc,
                                     unsigned long long a,
                                     unsigned long long b) {
    asm("fma.rn.f32x2 %0, %1, %2, %0;" : "+l"(acc) : "l"(a), "l"(b));
}
__device__ __forceinline__ float red2(unsigned long long acc) {
    float x, y;
    asm("mov.b64 {%0, %1}, %2;" : "=f"(x), "=f"(y) : "l"(acc));
    return x + y;
}
__device__ __forceinline__ void dot32(const float* __restrict__ w,
                                      const P4 x[8], unsigned long long& acc) {
    const ulonglong2* W = reinterpret_cast<const ulonglong2*>(w);
#pragma unroll
    for (int i = 0; i < 8; ++i) {
        ulonglong2 wv = W[i];
        fma2(acc, wv.x, x[i].u.x);
        fma2(acc, wv.y, x[i].u.y);
    }
}
__device__ __forceinline__ void load8s(const float* __restrict__ p, P4 x[8]) {
    const float4* q = reinterpret_cast<const float4*>(p);
#pragma unroll
    for (int i = 0; i < 8; ++i) x[i].f = q[i];
}
__device__ __forceinline__ float sigm(float x) {
    return 1.f / (1.f + __expf(-x));
}
__device__ __forceinline__ int ld_acq(const int* p) {
    int v;
    asm volatile("ld.global.acquire.gpu.s32 %0, [%1];" : "=r"(v) : "l"(p));
    return v;
}

// ---------------------------------------------------------------------------
// Pre-kernel 1: fold comb linear algebra into tables (+ zero pipeline flags)
// ---------------------------------------------------------------------------
__global__ void pre_kernel(const float* __restrict__ emb,
                           const float* __restrict__ Wih0,
                           const float* __restrict__ h2eW,
                           const float* __restrict__ h2eb,
                           const float* __restrict__ adpW,
                           const float* __restrict__ adpb,
                           const float* __restrict__ bih) {
    int idx = blockIdx.x * 256 + threadIdx.x;
    if (idx < 74304) {                       // T0[c][v][g]
        int c = idx / 24768, rem = idx % 24768;
        int v = rem / 96, g = rem % 96;
        const float* w = Wih0 + c * 6240 + g * 65;
        const float* e = emb + (size_t)(c * 258 + v) * 64;
        float s = 0.f;
        for (int j = 0; j < 64; ++j) s = fmaf(w[j], e[j], s);
        g_T0[idx] = s;
    } else if (idx < 74304 + 9216) {         // M1[c][g][j]
        int i = idx - 74304;
        int c = i / 3072, rem = i % 3072, g = rem / 32, j = rem % 32;
        const float* w = Wih0 + c * 6240 + g * 65;
        float s = 0.f;
        for (int e = 0; e < 65; ++e) s = fmaf(w[e], h2eW[c * 2080 + e * 32 + j], s);
        g_M1[i] = s;
    } else if (idx < 74304 + 9216 + 6144) {  // M2[c2][g][j]
        int i = idx - 74304 - 9216;
        int c2 = i / 3072, rem = i % 3072, g = rem / 32, j = rem % 32;
        const float* w = Wih0 + (c2 + 1) * 6240 + g * 65;
        float s = 0.f;
        for (int e = 0; e < 65; ++e) s = fmaf(w[e], adpW[c2 * 2080 + e * 32 + j], s);
        g_M2[i] = s;
    } else if (idx < 74304 + 9216 + 6144 + 288) {   // b0[c][g]
        int i = idx - 74304 - 9216 - 6144;
        int c = i / 96, g = i % 96;
        const float* w = Wih0 + c * 6240 + g * 65;
        float s = bih[c * 288 + g];
        for (int e = 0; e < 65; ++e) s = fmaf(w[e], h2eb[c * 65 + e], s);
        if (c > 0)
            for (int e = 0; e < 65; ++e) s = fmaf(w[e], adpb[(c - 1) * 65 + e], s);
        g_b0[i] = s;
    } else if (idx < 89952 + 96) {           // zero pipeline flags
        g_flagH[idx - 89952] = 0;
    }
}

// ---------------------------------------------------------------------------
// Pre-kernel 2: materialize comb0 per cell, diagonal layout [b][c][s][g][r].
// ---------------------------------------------------------------------------
__global__ void pre2_kernel(const int* __restrict__ x,
                            const float* __restrict__ Wih0,
                            const float* __restrict__ bhh) {
    __shared__ float w64s[96], bias_s[96];
    __shared__ int xs[64];
    const int s = blockIdx.x;
    const int bc = blockIdx.y;           // b*3 + c
    const int c = bc % 3;
    const int tid = threadIdx.x;
    const int lo = (s > 63) ? s - 63 : 0;
    const int hi = (s < 63) ? s : 63;
    if (tid < 96) {
        w64s[tid] = Wih0[c * 6240 + tid * 65 + 64];
        float bb = g_b0[c * 96 + tid];
        if (tid < 64) bb += bhh[c * 288 + tid];      // bhh r,z (layer 0)
        bias_s[tid] = bb;
    }
    if (tid >= 96 && tid - 96 <= hi - lo) {
        int r = lo + (tid - 96);
        xs[r] = x[(bc * 64 + r) * 64 + (s - r)];
    }
    __syncthreads();
    float* outp = g_comb0 + ((size_t)bc * Dn + s) * 6144;
    const float* t0c = g_T0 + c * 258 * 96;
    for (int idx = tid; idx < 96 * 64; idx += 256) {
        int g = idx >> 6, r = idx & 63;
        if (r < lo || r > hi) continue;
        float rf = (float)r * 0.03125f - 1.0f;
        outp[idx] = t0c[xs[r] * 96 + g] + rf * w64s[g] + bias_s[g];
    }
}

// ---------------------------------------------------------------------------
// Shared-memory layout for the RNN producer role (floats)
// ---------------------------------------------------------------------------
constexpr int OFF_M1   = 0;        // 96 x 32
constexpr int OFF_M2   = 3072;
constexpr int OFF_WHH0 = 6144;
constexpr int OFF_WIH1 = 9216;
constexpr int OFF_WHH1 = 12288;
constexpr int OFF_WIH2 = 15360;
constexpr int OFF_WHH2 = 18432;
constexpr int OFF_B    = 21504;    // 3 x 128 (layer biases; l=0 uses only nh part)
constexpr int OFF_H0   = 21888;    // 2 x (32 x 36) ping-pong
constexpr int OFF_H1   = 24192;    // 2 x (32 x 36)
constexpr int OFF_H2   = 26496;    // 2 x (33 x 36): slot 0 = boundary/zero, slot j+1 = local row j
constexpr int OFF_PC   = 28872;    // 2 x (32 x 36) prev-channel staging
constexpr int SM_RNN_END = 31176;

// ---------------------------------------------------------------------------
// RNN producer: half a channel (32 rows) per block; 96 blocks total.
// pid = bc*2 + h. Half 1 consumes half 0's boundary row via g_outs_d.
// ---------------------------------------------------------------------------
__device__ void rnn_body(float* sm, int pid,
                         const float* __restrict__ WihR,
                         const float* __restrict__ Whh,
                         const float* __restrict__ bih,
                         const float* __restrict__ bhh) {
    const int tid = threadIdx.x;
    const int warp = tid >> 5, lane = tid & 31;
    const int bc = pid >> 1;
    const int h = pid & 1;
    const int R0 = h << 5;
    const int c = bc % 3;
    const bool haspc = (c > 0);

    // ---- stage weights (once) ----
    for (int i = tid; i < 3072; i += 512) {
        sm[OFF_M1 + i]   = g_M1[c * 3072 + i];
        sm[OFF_WHH0 + i] = Whh[c * 9216 + i];
        sm[OFF_WIH1 + i] = WihR[c * 6144 + i];
        sm[OFF_WHH1 + i] = Whh[c * 9216 + 3072 + i];
        sm[OFF_WIH2 + i] = WihR[c * 6144 + 3072 + i];
        sm[OFF_WHH2 + i] = Whh[c * 9216 + 6144 + i];
        if (haspc) sm[OFF_M2 + i] = g_M2[(c - 1) * 3072 + i];
    }
    for (int i = tid; i < 384; i += 512) {
        int l = i >> 7, o = i & 127;
        float v;
        if (o < 64)
            v = ((l == 0) ? 0.f : bih[(c * 3 + l) * 96 + o] +
                                  bhh[(c * 3 + l) * 96 + o]);
        else if (o < 96) {
            int g = 64 + (o - 64);
            v = (l == 0) ? 0.f : bih[(c * 3 + l) * 96 + g];
        } else {
            int g = 64 + (o - 96);
            v = bhh[(c * 3 + l) * 96 + g];
        }
        sm[OFF_B + i] = v;
    }
    for (int i = tid + OFF_H0; i < SM_RNN_END; i += 512) sm[i] = 0.f;

    const float* gprev = g_outs_d + (size_t)(bc - 1) * Dn * 2048;  // valid iff c>0
    float* gcur = g_outs_d + (size_t)bc * Dn * 2048;
    const float* cchan = g_comb0 + (size_t)bc * Dn * 6144;
    const int* flag_prev = &g_flagH[(bc - 1) * 2 + h];   // same half of prev channel
    const int* flag_h0 = &g_flagH[bc * 2];               // half 0 of own channel

    // prologue: PC for step 0 (diag 0 = row 0 only -> half 0)
    if (haspc && h == 0) {
        while (ld_acq(flag_prev) < 1) {}
        if (tid < 32) sm[OFF_PC + tid] = gprev[tid];
    }
    __syncthreads();

    for (int s = 0; s < Dn; ++s) {
        const int pong = s & 1, next = 1 - pong;
        const int lo = (s > 63) ? s - 63 : 0;
        const int hi = (s < 63) ? s : 63;
        const int lo_l = (lo > R0) ? lo : R0;
        const int hi_l = (hi < R0 + 31) ? hi : R0 + 31;
        const int nact = hi_l - lo_l + 1;                // may be <= 0

        const int jj = lane;
        const bool valid = jj < nact;
        const int r = lo_l + (valid ? jj : (nact > 0 ? nact - 1 : 0));
        const int j0 = r - R0;

        // ---- 1. coalesced copy-out of previous step's layer-2 results ----
        if (s > 0) {
            const int lop = (s - 1 > 63) ? s - 64 : 0;
            const int hip = (s - 1 < 63) ? s - 1 : 63;
            const int cl0 = (lop > R0) ? lop : R0;
            const int cl1 = (hip < R0 + 31) ? hip : R0 + 31;
            const int np = cl1 - cl0 + 1;
            for (int idx = tid; idx < np * 32; idx += 512) {
                int j = idx >> 5, k = idx & 31, rr = cl0 + j;
                gcur[((size_t)(s - 1) * 64 + rr) * 32 + k] =
                    sm[OFF_H2 + pong * 1188 + (rr - R0 + 1) * 36 + k];
            }
        }
        // ---- boundary: half 1 needs half 0's row 31 output of step s-1 ----
        if (h == 1 && s >= 32 && s <= 95) {
            while (ld_acq(flag_h0) < s) {}
            if (tid < 32)
                sm[OFF_H2 + pong * 1188 + tid] =
                    __ldcg(&gcur[((size_t)(s - 1) * 64 + 31) * 32 + tid]);
        }
        __syncthreads();

        // ---- publish: diags <= s-1 of this half are in g_outs_d ----
        if (tid == 0) {
            asm volatile("fence.acq_rel.gpu;" ::: "memory");
            asm volatile("st.global.release.gpu.s32 [%0], %1;"
                         :: "l"(&g_flagH[pid]), "r"(s) : "memory");
        }

        // ================= layer 0 (comb folded into g_comb0) ==========
        if (nact > 0) {
            P4 h2p[8], h0c[8], pcc[8];
            load8s(sm + OFF_H2 + pong * 1188 + j0 * 36, h2p);
            load8s(sm + OFF_H0 + pong * 1152 + j0 * 36, h0c);
            if (haspc) load8s(sm + OFF_PC + pong * 1152 + j0 * 36, pcc);
            const float* cb = cchan + (size_t)s * 6144 + r;

            for (int k = warp; k < 32; k += 16) {
                float c0r = cb[k * 64];
                float c0z = cb[(k + 32) * 64];
                float c0n = cb[(k + 64) * 64];
                unsigned long long ar = 0ull, az = 0ull, ani = 0ull, anh = 0ull;
                dot32(sm + OFF_M1 + k * 32, h2p, ar);
                dot32(sm + OFF_M1 + (k + 32) * 32, h2p, az);
                dot32(sm + OFF_M1 + (k + 64) * 32, h2p, ani);
                if (haspc) {
                    dot32(sm + OFF_M2 + k * 32, pcc, ar);
                    dot32(sm + OFF_M2 + (k + 32) * 32, pcc, az);
                    dot32(sm + OFF_M2 + (k + 64) * 32, pcc, ani);
                }
                dot32(sm + OFF_WHH0 + k * 32, h0c, ar);
                dot32(sm + OFF_WHH0 + (k + 32) * 32, h0c, az);
                dot32(sm + OFF_WHH0 + (k + 64) * 32, h0c, anh);
                float vr = red2(ar) + c0r;
                float vz = red2(az) + c0z;
                float vni = red2(ani) + c0n;
                float vnh = red2(anh) + sm[OFF_B + 96 + k];
                float rr = sigm(vr), zz = sigm(vz);
                float nn = tanhf(vni + rr * vnh);
                float hold = sm[OFF_H0 + pong * 1152 + j0 * 36 + k];
                float hnew = (1.f - zz) * nn + zz * hold;
                if (valid) sm[OFF_H0 + next * 1152 + j0 * 36 + k] = hnew;
            }
        }
        __syncthreads();

        // ---- stage prev-channel vectors for step s+1 (buffer `next`) ----
        if (haspc && s + 1 < Dn) {
            const int lo2 = (s + 1 > 63) ? s - 62 : 0;
            const int hi2 = (s + 1 < 63) ? s + 1 : 63;
            const int c0 = (lo2 > R0) ? lo2 : R0;
            const int c1 = (hi2 < R0 + 31) ? hi2 : R0 + 31;
            const int n2 = c1 - c0 + 1;
            if (n2 > 0) {
                while (ld_acq(flag_prev) < s + 2) {}
                for (int idx = tid; idx < n2 * 32; idx += 512) {
                    int j = idx >> 5, k = idx & 31, rr = c0 + j;
                    sm[OFF_PC + next * 1152 + (rr - R0) * 36 + k] =
                        gprev[((size_t)(s + 1) * 64 + rr) * 32 + k];
                }
            }
        }

        // ================= layer 1 =================
        if (nact > 0) {
            P4 h0n[8], h1c[8];
            load8s(sm + OFF_H0 + next * 1152 + j0 * 36, h0n);
            load8s(sm + OFF_H1 + pong * 1152 + j0 * 36, h1c);
            for (int k = warp; k < 32; k += 16) {
                unsigned long long ar = 0ull, az = 0ull, ani = 0ull, anh = 0ull;
                dot32(sm + OFF_WIH1 + k * 32, h0n, ar);
                dot32(sm + OFF_WHH1 + k * 32, h1c, ar);
                dot32(sm + OFF_WIH1 + (k + 32) * 32, h0n, az);
                dot32(sm + OFF_WHH1 + (k + 32) * 32, h1c, az);
                dot32(sm + OFF_WIH1 + (k + 64) * 32, h0n, ani);
                dot32(sm + OFF_WHH1 + (k + 64) * 32, h1c, anh);
                float vr = red2(ar) + sm[OFF_B + 128 + k];
                float vz = red2(az) + sm[OFF_B + 128 + k + 32];
                float vni = red2(ani) + sm[OFF_B + 128 + 64 + k];
                float vnh = red2(anh) + sm[OFF_B + 128 + 96 + k];
                float rr = sigm(vr), zz = sigm(vz);
                float nn = tanhf(vni + rr * vnh);
                float hold = sm[OFF_H1 + pong * 1152 + j0 * 36 + k];
                float hnew = (1.f - zz) * nn + zz * hold;
                if (valid) sm[OFF_H1 + next * 1152 + j0 * 36 + k] = hnew;
            }
        }
        __syncthreads();

        // ================= layer 2 =================
        if (nact > 0) {
            P4 h1n[8], h2c[8];
            load8s(sm + OFF_H1 + next * 1152 + j0 * 36, h1n);
            load8s(sm + OFF_H2 + pong * 1188 + (j0 + 1) * 36, h2c);
            for (int k = warp; k < 32; k += 16) {
                unsigned long long ar = 0ull, az = 0ull, ani = 0ull, anh = 0ull;
                dot32(sm + OFF_WIH2 + k * 32, h1n, ar);
                dot32(sm + OFF_WHH2 + k * 32, h2c, ar);
                dot32(sm + OFF_WIH2 + (k + 32) * 32, h1n, az);
                dot32(sm + OFF_WHH2 + (k + 32) * 32, h2c, az);
                dot32(sm + OFF_WIH2 + (k + 64) * 32, h1n, ani);
                dot32(sm + OFF_WHH2 + (k + 64) * 32, h2c, anh);
                float vr = red2(ar) + sm[OFF_B + 256 + k];
                float vz = red2(az) + sm[OFF_B + 256 + k + 32];
                float vni = red2(ani) + sm[OFF_B + 256 + 64 + k];
                float vnh = red2(anh) + sm[OFF_B + 256 + 96 + k];
                float rr = sigm(vr), zz = sigm(vz);
                float nn = tanhf(vni + rr * vnh);
                float hold = sm[OFF_H2 + pong * 1188 + (j0 + 1) * 36 + k];
                float hnew = (1.f - zz) * nn + zz * hold;
                if (valid) sm[OFF_H2 + next * 1188 + (j0 + 1) * 36 + k] = hnew;
            }
        }
        // rolling zero: activate row s+1 (if owned) for step s+1
        if (s + 1 >= R0 && s + 1 <= R0 + 31 && tid < 108) {
            int which = tid / 36, kk = tid - which * 36;
            int j = s + 1 - R0;
            if (which == 0)      sm[OFF_H0 + next * 1152 + j * 36 + kk] = 0.f;
            else if (which == 1) sm[OFF_H1 + next * 1152 + j * 36 + kk] = 0.f;
            else                 sm[OFF_H2 + next * 1188 + (j + 1) * 36 + kk] = 0.f;
        }
        __syncthreads();
    }
    // final copy-out: diag 126 = row 63 only (half 1); buffer next(126)=1
    if (h == 1 && tid < 32)
        gcur[((size_t)126 * 64 + 63) * 32 + tid] =
            sm[OFF_H2 + 1 * 1188 + 32 * 36 + tid];
    __syncthreads();
    if (tid == 0) {
        asm volatile("fence.acq_rel.gpu;" ::: "memory");
        asm volatile("st.global.release.gpu.s32 [%0], %1;"
                     :: "l"(&g_flagH[pid]), "r"(200) : "memory");
    }
}

// ---------------------------------------------------------------------------
// Logits role: one row per block, f32x2 inner loop, flag-gated on RNN progress.
// ---------------------------------------------------------------------------
template <int N4>
__device__ __forceinline__ void compute_logits(const float* __restrict__ Ws,
                                               const float* __restrict__ ins,
                                               const float* __restrict__ bs,
                                               float* __restrict__ outp, int tid) {
    constexpr int Kp = N4 * 4;
    for (int tile = tid; tile < 65 * 32; tile += 512) {
        int vg = tile / 32, tg = tile - vg * 32;
        int t0 = tg * 2, v0 = vg * 4;
        const ulonglong2* w0 = reinterpret_cast<const ulonglong2*>(&Ws[(v0 + 0) * Kp]);
        const ulonglong2* w1 = reinterpret_cast<const ulonglong2*>(&Ws[(v0 + 1) * Kp]);
        const ulonglong2* w2 = reinterpret_cast<const ulonglong2*>(&Ws[(v0 + 2) * Kp]);
        const ulonglong2* w3 = reinterpret_cast<const ulonglong2*>(&Ws[(v0 + 3) * Kp]);
        const ulonglong2* i0 = reinterpret_cast<const ulonglong2*>(&ins[t0 * Kp]);
        const ulonglong2* i1 = reinterpret_cast<const ulonglong2*>(&ins[(t0 + 1) * Kp]);
        unsigned long long a0[4] = {0ull, 0ull, 0ull, 0ull};
        unsigned long long a1[4] = {0ull, 0ull, 0ull, 0ull};
#pragma unroll 4
        for (int k = 0; k < N4; ++k) {
            ulonglong2 x0 = i0[k], x1 = i1[k];
            ulonglong2 y;
            y = w0[k];
            fma2(a0[0], y.x, x0.x); fma2(a0[0], y.y, x0.y);
            fma2(a1[0], y.x, x1.x); fma2(a1[0], y.y, x1.y);
            y = w1[k];
            fma2(a0[1], y.x, x0.x); fma2(a0[1], y.y, x0.y);
            fma2(a1[1], y.x, x1.x); fma2(a1[1], y.y, x1.y);
            y = w2[k];
            fma2(a0[2], y.x, x0.x); fma2(a0[2], y.y, x0.y);
            fma2(a1[2], y.x, x1.x); fma2(a1[2], y.y, x1.y);
            y = w3[k];
            fma2(a0[3], y.x, x0.x); fma2(a0[3], y.y, x0.y);
            fma2(a1[3], y.x, x1.x); fma2(a1[3], y.y, x1.y);
        }
        int ob0 = t0 * Vn, ob1 = ob0 + Vn;
#pragma unroll
        for (int v = 0; v < 4; ++v) {
            int vv = v0 + v;
            if (vv < Vn) {
                float bv = bs[vv];
                outp[ob0 + vv] = red2(a0[v]) + bv;
                outp[ob1 + vv] = red2(a1[v]) + bv;
            }
        }
    }
}

__device__ void logits_body(float* sm, int lid,
                            const float* __restrict__ emb,
                            const int* __restrict__ target,
                            const float* __restrict__ W0, const float* __restrict__ b0,
                            const float* __restrict__ W1, const float* __restrict__ b1,
                            const float* __restrict__ W2, const float* __restrict__ b2,
                            float* __restrict__ out) {
    const int tid = threadIdx.x;
    // lid -> (r, bb, ch): r-major so earliest-ready rows get resident blocks
    const int r = lid / 48;
    const int rem = lid - r * 48;
    const int bb = rem / 3;
    const int ch = rem - bb * 3;

    const float* W;
    const float* Bb;
    int K;
    if (ch == 0)      { W = W0; Bb = b0; K = 32; }
    else if (ch == 1) { W = W1; Bb = b1; K = 96; }
    else              { W = W2; Bb = b2; K = 160; }
    const int Kp = K + 4;

    float* Ws = sm;
    float* ins = sm + 260 * Kp;
    float* bs = ins + 64 * Kp;

    // stage weights first (independent of RNN progress)
    for (int idx = tid; idx < 260 * Kp; idx += 512) {
        int v = idx / Kp, k = idx - v * Kp;
        Ws[idx] = (v < Vn && k < K) ? W[v * K + k] : 0.f;
    }
    for (int idx = tid; idx < 260; idx += 512)
        bs[idx] = (idx < Vn) ? Bb[idx] : 0.f;

    // wait for RNN: row r diags r..r+63 ready when its half's flag >= r+64
    const int need = r + 64;
    const int* fp = &g_flagH[(bb * 3 + ch) * 2 + (r >> 5)];
    if (tid == 0) {
        int v = ld_acq(fp);
        while (v < need) { __nanosleep(256); v = ld_acq(fp); }
    }
    __syncthreads();   // broadcast acquire to block (leader-acquire + barrier)

    const size_t diagbase = (size_t)(bb * 3 + ch) * Dn;
    for (int idx = tid; idx < 64 * Kp; idx += 512) {
        int t = idx / Kp, k = idx - t * Kp;
        float val = 0.f;
        if (k < 32) {
            val = __ldcg(&g_outs_d[(diagbase + (r + t)) * 2048 + r * 32 + k]);
        } else if (k < K) {
            int kk = k - 32;
            int chE = (kk < 64) ? 0 : 1;
            int ke = (kk < 64) ? kk : kk - 64;
            int tg = target[((bb * 3 + chE) * Rn + r) * Sn + t];
            val = emb[(size_t)(chE * Vn + tg) * En + ke];
        }
        ins[idx] = val;
    }
    __syncthreads();

    const int rowbase = ((bb * 3 + ch) * Rn + r) * Sn;
    float* outp = out + (size_t)rowbase * Vn;
    if (K == 32)       compute_logits<9>(Ws, ins, bs, outp, tid);
    else if (K == 96)  compute_logits<25>(Ws, ins, bs, outp, tid);
    else               compute_logits<41>(Ws, ins, bs, outp, tid);
}

// ---------------------------------------------------------------------------
// Fused kernel: blocks 0..95 = RNN half-channel producers, 96.. = logits.
// 1 block/SM => all 96 producers resident in wave 1; flags monotonic.
// ---------------------------------------------------------------------------
__global__ __launch_bounds__(512, 1)
void fused_kernel(const float* __restrict__ WihR, const float* __restrict__ Whh,
                  const float* __restrict__ bih, const float* __restrict__ bhh,
                  const float* __restrict__ emb, const int* __restrict__ target,
                  const float* __restrict__ W0, const float* __restrict__ b0,
                  const float* __restrict__ W1, const float* __restrict__ b1,
                  const float* __restrict__ W2, const float* __restrict__ b2,
                  float* __restrict__ out) {
    extern __shared__ float sm[];
    if (blockIdx.x < Bn * 3 * 2) {
        rnn_body(sm, blockIdx.x, WihR, Whh, bih, bhh);
    } else {
        logits_body(sm, blockIdx.x - Bn * 3 * 2, emb, target, W0, b0, W1, b1,
                    W2, b2, out);
    }
}

// ---------------------------------------------------------------------------
// Launch
// ---------------------------------------------------------------------------
extern "C" void kernel_launch(void* const* d_in, const int* in_sizes, int n_in,
                              void* d_out, int out_size) {
    (void)in_sizes; (void)n_in; (void)out_size;
    const int*   x      = (const int*)  d_in[0];
    const int*   target = (const int*)  d_in[1];
    const float* emb    = (const float*)d_in[2];
    const float* Wih0   = (const float*)d_in[3];
    const float* WihR   = (const float*)d_in[4];
    const float* Whh    = (const float*)d_in[5];
    const float* bih    = (const float*)d_in[6];
    const float* bhh    = (const float*)d_in[7];
    const float* h2eW   = (const float*)d_in[8];
    const float* h2eb   = (const float*)d_in[9];
    const float* adpW   = (const float*)d_in[10];
    const float* adpb   = (const float*)d_in[11];
    const float* redW   = (const float*)d_in[12];
    const float* redb   = (const float*)d_in[13];
    const float* greenW = (const float*)d_in[14];
    const float* greenb = (const float*)d_in[15];
    const float* blueW  = (const float*)d_in[16];
    const float* blueb  = (const float*)d_in[17];
    float* out = (float*)d_out;

    // logits role needs the most smem: 260*164 + 64*164 + 260 floats
    const size_t smem_fused = (size_t)(260 * 164 + 64 * 164 + 260) * sizeof(float);

    cudaFuncSetAttribute(fused_kernel, cudaFuncAttributeMaxDynamicSharedMemorySize,
                         (int)smem_fused);

    pre_kernel<<<352, 256>>>(emb, Wih0, h2eW, h2eb, adpW, adpb, bih);
    pre2_kernel<<<dim3(Dn, Bn * 3), 256>>>(x, Wih0, bhh);
    fused_kernel<<<Bn * 3 * 2 + Bn * Rn * 3, 512, smem_fused>>>(
        WihR, Whh, bih, bhh, emb, target, redW, redb, greenW, greenb,
        blueW, blueb, out);
}

// round 13
// speedup vs baseline: 10.6798x; 1.1416x over previous
#include <cuda_runtime.h>
#include <math.h>

// ---------------------------------------------------------------------------
// Problem constants
// ---------------------------------------------------------------------------
#define Bn 16
#define Hn 32
#define En 64
#define Vn 258
#define Rn 64
#define Sn 64
#define Dn 127   // number of wavefront diagonals (r + t)

// ---------------------------------------------------------------------------
// Global scratch (static __device__, no allocation)
// ---------------------------------------------------------------------------
__device__ float g_outs_d[Bn * 3 * Dn * Rn * Hn];        // diag layout [b][c][s][r][k]
__device__ float g_comb0[(size_t)Bn * 3 * Dn * 96 * 64]; // [b][c][s][g][r]
__device__ float g_T0[3 * 258 * 96];                     // Wih0 @ emb
__device__ float g_M1[3 * 96 * 32];                      // Wih0 @ h2eW
__device__ float g_M2[2 * 96 * 32];                      // Wih0 @ adpW
__device__ float g_b0[3 * 96];                           // bih0 + Wih0@(h2eb[+adpb])
__device__ int   g_flagH[Bn * 3 * 2];                    // diag progress per (b,c,half)

// ---------------------------------------------------------------------------
// Packed f32x2 helpers
// ---------------------------------------------------------------------------
union P4 { float4 f; ulonglong2 u; };

__device__ __forceinline__ void fma2(unsigned long long& acc,
                                     unsigned long long a,
                                     unsigned long long b) {
    asm("fma.rn.f32x2 %0, %1, %2, %0;" : "+l"(acc) : "l"(a), "l"(b));
}
__device__ __forceinline__ float red2(unsigned long long acc) {
    float x, y;
    asm("mov.b64 {%0, %1}, %2;" : "=f"(x), "=f"(y) : "l"(acc));
    return x + y;
}
__device__ __forceinline__ void dot32(const float* __restrict__ w,
                                      const P4 x[8], unsigned long long& acc) {
    const ulonglong2* W = reinterpret_cast<const ulonglong2*>(w);
#pragma unroll
    for (int i = 0; i < 8; ++i) {
        ulonglong2 wv = W[i];
        fma2(acc, wv.x, x[i].u.x);
        fma2(acc, wv.y, x[i].u.y);
    }
}
__device__ __forceinline__ void load8s(const float* __restrict__ p, P4 x[8]) {
    const float4* q = reinterpret_cast<const float4*>(p);
#pragma unroll
    for (int i = 0; i < 8; ++i) x[i].f = q[i];
}
__device__ __forceinline__ float sigm(float x) {
    return 1.f / (1.f + __expf(-x));
}
__device__ __forceinline__ int ld_acq(const int* p) {
    int v;
    asm volatile("ld.global.acquire.gpu.s32 %0, [%1];" : "=r"(v) : "l"(p));
    return v;
}

// ---------------------------------------------------------------------------
// Pre-kernel 1: fold comb linear algebra into tables (+ zero pipeline flags)
// ---------------------------------------------------------------------------
__global__ void pre_kernel(const float* __restrict__ emb,
                           const float* __restrict__ Wih0,
                           const float* __restrict__ h2eW,
                           const float* __restrict__ h2eb,
                           const float* __restrict__ adpW,
                           const float* __restrict__ adpb,
                           const float* __restrict__ bih) {
    int idx = blockIdx.x * 256 + threadIdx.x;
    if (idx < 74304) {                       // T0[c][v][g]
        int c = idx / 24768, rem = idx % 24768;
        int v = rem / 96, g = rem % 96;
        const float* w = Wih0 + c * 6240 + g * 65;
        const float* e = emb + (size_t)(c * 258 + v) * 64;
        float s = 0.f;
        for (int j = 0; j < 64; ++j) s = fmaf(w[j], e[j], s);
        g_T0[idx] = s;
    } else if (idx < 74304 + 9216) {         // M1[c][g][j]
        int i = idx - 74304;
        int c = i / 3072, rem = i % 3072, g = rem / 32, j = rem % 32;
        const float* w = Wih0 + c * 6240 + g * 65;
        float s = 0.f;
        for (int e = 0; e < 65; ++e) s = fmaf(w[e], h2eW[c * 2080 + e * 32 + j], s);
        g_M1[i] = s;
    } else if (idx < 74304 + 9216 + 6144) {  // M2[c2][g][j]
        int i = idx - 74304 - 9216;
        int c2 = i / 3072, rem = i % 3072, g = rem / 32, j = rem % 32;
        const float* w = Wih0 + (c2 + 1) * 6240 + g * 65;
        float s = 0.f;
        for (int e = 0; e < 65; ++e) s = fmaf(w[e], adpW[c2 * 2080 + e * 32 + j], s);
        g_M2[i] = s;
    } else if (idx < 74304 + 9216 + 6144 + 288) {   // b0[c][g]
        int i = idx - 74304 - 9216 - 6144;
        int c = i / 96, g = i % 96;
        const float* w = Wih0 + c * 6240 + g * 65;
        float s = bih[c * 288 + g];
        for (int e = 0; e < 65; ++e) s = fmaf(w[e], h2eb[c * 65 + e], s);
        if (c > 0)
            for (int e = 0; e < 65; ++e) s = fmaf(w[e], adpb[(c - 1) * 65 + e], s);
        g_b0[i] = s;
    } else if (idx < 89952 + 96) {           // zero pipeline flags
        g_flagH[idx - 89952] = 0;
    }
}

// ---------------------------------------------------------------------------
// Pre-kernel 2: materialize comb0 per cell, diagonal layout [b][c][s][g][r].
// ---------------------------------------------------------------------------
__global__ void pre2_kernel(const int* __restrict__ x,
                            const float* __restrict__ Wih0,
                            const float* __restrict__ bhh) {
    __shared__ float w64s[96], bias_s[96];
    __shared__ int xs[64];
    const int s = blockIdx.x;
    const int bc = blockIdx.y;           // b*3 + c
    const int c = bc % 3;
    const int tid = threadIdx.x;
    const int lo = (s > 63) ? s - 63 : 0;
    const int hi = (s < 63) ? s : 63;
    if (tid < 96) {
        w64s[tid] = Wih0[c * 6240 + tid * 65 + 64];
        float bb = g_b0[c * 96 + tid];
        if (tid < 64) bb += bhh[c * 288 + tid];      // bhh r,z (layer 0)
        bias_s[tid] = bb;
    }
    if (tid >= 96 && tid - 96 <= hi - lo) {
        int r = lo + (tid - 96);
        xs[r] = x[(bc * 64 + r) * 64 + (s - r)];
    }
    __syncthreads();
    float* outp = g_comb0 + ((size_t)bc * Dn + s) * 6144;
    const float* t0c = g_T0 + c * 258 * 96;
    for (int idx = tid; idx < 96 * 64; idx += 256) {
        int g = idx >> 6, r = idx & 63;
        if (r < lo || r > hi) continue;
        float rf = (float)r * 0.03125f - 1.0f;
        outp[idx] = t0c[xs[r] * 96 + g] + rf * w64s[g] + bias_s[g];
    }
}

// ---------------------------------------------------------------------------
// Shared-memory layout for the RNN producer role (floats)
// ---------------------------------------------------------------------------
constexpr int OFF_M1   = 0;        // 96 x 32
constexpr int OFF_M2   = 3072;
constexpr int OFF_WHH0 = 6144;
constexpr int OFF_WIH1 = 9216;
constexpr int OFF_WHH1 = 12288;
constexpr int OFF_WIH2 = 15360;
constexpr int OFF_WHH2 = 18432;
constexpr int OFF_B    = 21504;    // 3 x 128 (layer biases; l=0 uses only nh part)
constexpr int OFF_H0   = 21888;    // 2 x (32 x 36) ping-pong
constexpr int OFF_H1   = 24192;    // 2 x (32 x 36)
constexpr int OFF_H2   = 26496;    // 2 x (33 x 36): slot 0 = boundary/zero, slot j+1 = local row j
constexpr int OFF_PC   = 28872;    // 2 x (32 x 36) prev-channel staging
constexpr int SM_RNN_END = 31176;

// ---------------------------------------------------------------------------
// RNN producer: half a channel (32 rows) per block; 96 blocks total.
// pid = bc*2 + h. Half 1 consumes half 0's boundary row via g_outs_d.
// ---------------------------------------------------------------------------
__device__ void rnn_body(float* sm, int pid,
                         const float* __restrict__ WihR,
                         const float* __restrict__ Whh,
                         const float* __restrict__ bih,
                         const float* __restrict__ bhh) {
    const int tid = threadIdx.x;
    const int warp = tid >> 5, lane = tid & 31;
    const int bc = pid >> 1;
    const int h = pid & 1;
    const int R0 = h << 5;
    const int c = bc % 3;
    const bool haspc = (c > 0);

    // ---- stage weights (once) ----
    for (int i = tid; i < 3072; i += 512) {
        sm[OFF_M1 + i]   = g_M1[c * 3072 + i];
        sm[OFF_WHH0 + i] = Whh[c * 9216 + i];
        sm[OFF_WIH1 + i] = WihR[c * 6144 + i];
        sm[OFF_WHH1 + i] = Whh[c * 9216 + 3072 + i];
        sm[OFF_WIH2 + i] = WihR[c * 6144 + 3072 + i];
        sm[OFF_WHH2 + i] = Whh[c * 9216 + 6144 + i];
        if (haspc) sm[OFF_M2 + i] = g_M2[(c - 1) * 3072 + i];
    }
    for (int i = tid; i < 384; i += 512) {
        int l = i >> 7, o = i & 127;
        float v;
        if (o < 64)
            v = ((l == 0) ? 0.f : bih[(c * 3 + l) * 96 + o] +
                                  bhh[(c * 3 + l) * 96 + o]);
        else if (o < 96) {
            int g = 64 + (o - 64);
            v = (l == 0) ? 0.f : bih[(c * 3 + l) * 96 + g];
        } else {
            int g = 64 + (o - 96);
            v = bhh[(c * 3 + l) * 96 + g];
        }
        sm[OFF_B + i] = v;
    }
    for (int i = tid + OFF_H0; i < SM_RNN_END; i += 512) sm[i] = 0.f;

    const float* gprev = g_outs_d + (size_t)(bc - 1) * Dn * 2048;  // valid iff c>0
    float* gcur = g_outs_d + (size_t)bc * Dn * 2048;
    const float* cchan = g_comb0 + (size_t)bc * Dn * 6144;
    const int* flag_prev = &g_flagH[(bc - 1) * 2 + h];   // same half of prev channel
    const int* flag_h0 = &g_flagH[bc * 2];               // half 0 of own channel

    // prologue: PC for step 0 (diag 0 = row 0 only -> half 0)
    if (haspc && h == 0) {
        while (ld_acq(flag_prev) < 1) {}
        if (tid < 32) sm[OFF_PC + tid] = gprev[tid];
    }
    __syncthreads();

    for (int s = 0; s < Dn; ++s) {
        const int pong = s & 1, next = 1 - pong;
        const int lo = (s > 63) ? s - 63 : 0;
        const int hi = (s < 63) ? s : 63;
        const int lo_l = (lo > R0) ? lo : R0;
        const int hi_l = (hi < R0 + 31) ? hi : R0 + 31;
        const int nact = hi_l - lo_l + 1;                // may be <= 0

        const int jj = lane;
        const bool valid = jj < nact;
        const int r = lo_l + (valid ? jj : (nact > 0 ? nact - 1 : 0));
        const int j0 = r - R0;

        // ---- 1. coalesced copy-out of previous step's layer-2 results ----
        if (s > 0) {
            const int lop = (s - 1 > 63) ? s - 64 : 0;
            const int hip = (s - 1 < 63) ? s - 1 : 63;
            const int cl0 = (lop > R0) ? lop : R0;
            const int cl1 = (hip < R0 + 31) ? hip : R0 + 31;
            const int np = cl1 - cl0 + 1;
            for (int idx = tid; idx < np * 32; idx += 512) {
                int j = idx >> 5, k = idx & 31, rr = cl0 + j;
                gcur[((size_t)(s - 1) * 64 + rr) * 32 + k] =
                    sm[OFF_H2 + pong * 1188 + (rr - R0 + 1) * 36 + k];
            }
        }
        // ---- boundary: half 1 needs half 0's row 31 output of step s-1 ----
        if (h == 1 && s >= 32 && s <= 95) {
            while (ld_acq(flag_h0) < s) {}
            if (tid < 32)
                sm[OFF_H2 + pong * 1188 + tid] =
                    __ldcg(&gcur[((size_t)(s - 1) * 64 + 31) * 32 + tid]);
        }
        __syncthreads();

        // ---- publish: diags <= s-1 of this half are in g_outs_d ----
        if (tid == 0) {
            asm volatile("fence.acq_rel.gpu;" ::: "memory");
            asm volatile("st.global.release.gpu.s32 [%0], %1;"
                         :: "l"(&g_flagH[pid]), "r"(s) : "memory");
        }

        // ================= layer 0 (comb folded into g_comb0) ==========
        if (nact > 0) {
            P4 h2p[8], h0c[8], pcc[8];
            load8s(sm + OFF_H2 + pong * 1188 + j0 * 36, h2p);
            load8s(sm + OFF_H0 + pong * 1152 + j0 * 36, h0c);
            if (haspc) load8s(sm + OFF_PC + pong * 1152 + j0 * 36, pcc);
            const float* cb = cchan + (size_t)s * 6144 + r;

            for (int k = warp; k < 32; k += 16) {
                float c0r = cb[k * 64];
                float c0z = cb[(k + 32) * 64];
                float c0n = cb[(k + 64) * 64];
                unsigned long long ar = 0ull, az = 0ull, ani = 0ull, anh = 0ull;
                dot32(sm + OFF_M1 + k * 32, h2p, ar);
                dot32(sm + OFF_M1 + (k + 32) * 32, h2p, az);
                dot32(sm + OFF_M1 + (k + 64) * 32, h2p, ani);
                if (haspc) {
                    dot32(sm + OFF_M2 + k * 32, pcc, ar);
                    dot32(sm + OFF_M2 + (k + 32) * 32, pcc, az);
                    dot32(sm + OFF_M2 + (k + 64) * 32, pcc, ani);
                }
                dot32(sm + OFF_WHH0 + k * 32, h0c, ar);
                dot32(sm + OFF_WHH0 + (k + 32) * 32, h0c, az);
                dot32(sm + OFF_WHH0 + (k + 64) * 32, h0c, anh);
                float vr = red2(ar) + c0r;
                float vz = red2(az) + c0z;
                float vni = red2(ani) + c0n;
                float vnh = red2(anh) + sm[OFF_B + 96 + k];
                float rr = sigm(vr), zz = sigm(vz);
                float nn = tanhf(vni + rr * vnh);
                float hold = sm[OFF_H0 + pong * 1152 + j0 * 36 + k];
                float hnew = (1.f - zz) * nn + zz * hold;
                if (valid) sm[OFF_H0 + next * 1152 + j0 * 36 + k] = hnew;
            }
        }
        __syncthreads();

        // ---- stage prev-channel vectors for step s+1 (buffer `next`) ----
        if (haspc && s + 1 < Dn) {
            const int lo2 = (s + 1 > 63) ? s - 62 : 0;
            const int hi2 = (s + 1 < 63) ? s + 1 : 63;
            const int c0 = (lo2 > R0) ? lo2 : R0;
            const int c1 = (hi2 < R0 + 31) ? hi2 : R0 + 31;
            const int n2 = c1 - c0 + 1;
            if (n2 > 0) {
                while (ld_acq(flag_prev) < s + 2) {}
                for (int idx = tid; idx < n2 * 32; idx += 512) {
                    int j = idx >> 5, k = idx & 31, rr = c0 + j;
                    sm[OFF_PC + next * 1152 + (rr - R0) * 36 + k] =
                        gprev[((size_t)(s + 1) * 64 + rr) * 32 + k];
                }
            }
        }

        // ================= layer 1 =================
        if (nact > 0) {
            P4 h0n[8], h1c[8];
            load8s(sm + OFF_H0 + next * 1152 + j0 * 36, h0n);
            load8s(sm + OFF_H1 + pong * 1152 + j0 * 36, h1c);
            for (int k = warp; k < 32; k += 16) {
                unsigned long long ar = 0ull, az = 0ull, ani = 0ull, anh = 0ull;
                dot32(sm + OFF_WIH1 + k * 32, h0n, ar);
                dot32(sm + OFF_WHH1 + k * 32, h1c, ar);
                dot32(sm + OFF_WIH1 + (k + 32) * 32, h0n, az);
                dot32(sm + OFF_WHH1 + (k + 32) * 32, h1c, az);
                dot32(sm + OFF_WIH1 + (k + 64) * 32, h0n, ani);
                dot32(sm + OFF_WHH1 + (k + 64) * 32, h1c, anh);
                float vr = red2(ar) + sm[OFF_B + 128 + k];
                float vz = red2(az) + sm[OFF_B + 128 + k + 32];
                float vni = red2(ani) + sm[OFF_B + 128 + 64 + k];
                float vnh = red2(anh) + sm[OFF_B + 128 + 96 + k];
                float rr = sigm(vr), zz = sigm(vz);
                float nn = tanhf(vni + rr * vnh);
                float hold = sm[OFF_H1 + pong * 1152 + j0 * 36 + k];
                float hnew = (1.f - zz) * nn + zz * hold;
                if (valid) sm[OFF_H1 + next * 1152 + j0 * 36 + k] = hnew;
            }
        }
        __syncthreads();

        // ================= layer 2 =================
        if (nact > 0) {
            P4 h1n[8], h2c[8];
            load8s(sm + OFF_H1 + next * 1152 + j0 * 36, h1n);
            load8s(sm + OFF_H2 + pong * 1188 + (j0 + 1) * 36, h2c);
            for (int k = warp; k < 32; k += 16) {
                unsigned long long ar = 0ull, az = 0ull, ani = 0ull, anh = 0ull;
                dot32(sm + OFF_WIH2 + k * 32, h1n, ar);
                dot32(sm + OFF_WHH2 + k * 32, h2c, ar);
                dot32(sm + OFF_WIH2 + (k + 32) * 32, h1n, az);
                dot32(sm + OFF_WHH2 + (k + 32) * 32, h2c, az);
                dot32(sm + OFF_WIH2 + (k + 64) * 32, h1n, ani);
                dot32(sm + OFF_WHH2 + (k + 64) * 32, h2c, anh);
                float vr = red2(ar) + sm[OFF_B + 256 + k];
                float vz = red2(az) + sm[OFF_B + 256 + k + 32];
                float vni = red2(ani) + sm[OFF_B + 256 + 64 + k];
                float vnh = red2(anh) + sm[OFF_B + 256 + 96 + k];
                float rr = sigm(vr), zz = sigm(vz);
                float nn = tanhf(vni + rr * vnh);
                float hold = sm[OFF_H2 + pong * 1188 + (j0 + 1) * 36 + k];
                float hnew = (1.f - zz) * nn + zz * hold;
                if (valid) sm[OFF_H2 + next * 1188 + (j0 + 1) * 36 + k] = hnew;
            }
        }
        // rolling zero: activate row s+1 (if owned) for step s+1
        if (s + 1 >= R0 && s + 1 <= R0 + 31 && tid < 108) {
            int which = tid / 36, kk = tid - which * 36;
            int j = s + 1 - R0;
            if (which == 0)      sm[OFF_H0 + next * 1152 + j * 36 + kk] = 0.f;
            else if (which == 1) sm[OFF_H1 + next * 1152 + j * 36 + kk] = 0.f;
            else                 sm[OFF_H2 + next * 1188 + (j + 1) * 36 + kk] = 0.f;
        }
        __syncthreads();
    }
    // final copy-out: diag 126 = row 63 only (half 1); buffer next(126)=1
    if (h == 1 && tid < 32)
        gcur[((size_t)126 * 64 + 63) * 32 + tid] =
            sm[OFF_H2 + 1 * 1188 + 32 * 36 + tid];
    __syncthreads();
    if (tid == 0) {
        asm volatile("fence.acq_rel.gpu;" ::: "memory");
        asm volatile("st.global.release.gpu.s32 [%0], %1;"
                     :: "l"(&g_flagH[pid]), "r"(200) : "memory");
    }
}

// ---------------------------------------------------------------------------
// Logits role v2: transposed inputs + packed weights.
//   insT[k2][t] : float2 of (ins[t][2k2], ins[t][2k2+1])  -> coalesced LDS.64
//   Wp[q][k2][vl][kk] : 8 v-rows x 2 k per (q,k2)          -> broadcast LDS.128
// Warp = (v-stream, t-half); thread owns (t, v-octet), 8 u64 accumulators.
// ---------------------------------------------------------------------------
template <int K2>
__device__ __forceinline__ void compute_logits(const float* __restrict__ Wp,
                                               const float* __restrict__ insT,
                                               const float* __restrict__ bs,
                                               float* __restrict__ outp, int tid) {
    const int warp = tid >> 5, lane = tid & 31;
    const int stream = warp >> 1;            // 0..7
    const int t = ((warp & 1) << 5) + lane;  // 0..63
    const unsigned long long* ip =
        reinterpret_cast<const unsigned long long*>(insT) + t;

    for (int q = stream; q < 33; q += 8) {   // v-octets (264 padded v)
        unsigned long long a[8] = {0ull, 0ull, 0ull, 0ull, 0ull, 0ull, 0ull, 0ull};
        const ulonglong2* wp =
            reinterpret_cast<const ulonglong2*>(Wp + q * (K2 * 16));
#pragma unroll 4
        for (int k2 = 0; k2 < K2; ++k2) {
            ulonglong2 w01 = wp[k2 * 4 + 0];
            ulonglong2 w23 = wp[k2 * 4 + 1];
            ulonglong2 w45 = wp[k2 * 4 + 2];
            ulonglong2 w67 = wp[k2 * 4 + 3];
            unsigned long long iv = ip[k2 * 64];
            fma2(a[0], w01.x, iv); fma2(a[1], w01.y, iv);
            fma2(a[2], w23.x, iv); fma2(a[3], w23.y, iv);
            fma2(a[4], w45.x, iv); fma2(a[5], w45.y, iv);
            fma2(a[6], w67.x, iv); fma2(a[7], w67.y, iv);
        }
        const int v0 = q * 8;
        float2* op = reinterpret_cast<float2*>(outp + t * Vn + v0);
        if (v0 + 8 <= Vn) {
#pragma unroll
            for (int j = 0; j < 4; ++j) {
                float2 o;
                o.x = red2(a[2 * j]) + bs[v0 + 2 * j];
                o.y = red2(a[2 * j + 1]) + bs[v0 + 2 * j + 1];
                op[j] = o;
            }
        } else {   // v0 = 256: only v 256, 257 are real
            float2 o;
            o.x = red2(a[0]) + bs[v0];
            o.y = red2(a[1]) + bs[v0 + 1];
            op[0] = o;
        }
    }
}

__device__ void logits_body(float* sm, int lid,
                            const float* __restrict__ emb,
                            const int* __restrict__ target,
                            const float* __restrict__ W0, const float* __restrict__ b0,
                            const float* __restrict__ W1, const float* __restrict__ b1,
                            const float* __restrict__ W2, const float* __restrict__ b2,
                            float* __restrict__ out) {
    const int tid = threadIdx.x;
    // lid -> (r, bb, ch): r-major so earliest-ready rows get resident blocks
    const int r = lid / 48;
    const int rem = lid - r * 48;
    const int bb = rem / 3;
    const int ch = rem - bb * 3;

    const float* W;
    const float* Bb;
    int K;
    if (ch == 0)      { W = W0; Bb = b0; K = 32; }
    else if (ch == 1) { W = W1; Bb = b1; K = 96; }
    else              { W = W2; Bb = b2; K = 160; }
    const int K2 = K >> 1;

    float* Wp = sm;                    // 264 * K floats (packed)
    float* insT = sm + 264 * K;        // 64 * K floats (transposed, float2 pairs)
    float* bs = insT + 64 * K;         // 264

    // stage packed weights + bias first (independent of RNN progress)
    for (int idx = tid; idx < 264 * K; idx += 512) {
        int v = idx / K, k = idx - v * K;
        float val = (v < Vn) ? W[v * K + k] : 0.f;
        int q = v >> 3, vl = v & 7, k2 = k >> 1, kk = k & 1;
        Wp[((q * K2 + k2) * 8 + vl) * 2 + kk] = val;
    }
    for (int idx = tid; idx < 264; idx += 512)
        bs[idx] = (idx < Vn) ? Bb[idx] : 0.f;

    // wait for RNN: row r diags r..r+63 ready when its half's flag >= r+64
    const int need = r + 64;
    const int* fp = &g_flagH[(bb * 3 + ch) * 2 + (r >> 5)];
    if (tid == 0) {
        int v = ld_acq(fp);
        while (v < need) { __nanosleep(256); v = ld_acq(fp); }
    }
    __syncthreads();   // broadcast acquire to block (leader-acquire + barrier)

    const size_t diagbase = (size_t)(bb * 3 + ch) * Dn;
    for (int idx = tid; idx < 64 * K; idx += 512) {
        int t = idx / K, k = idx - t * K;
        float val;
        if (k < 32) {
            val = __ldcg(&g_outs_d[(diagbase + (r + t)) * 2048 + r * 32 + k]);
        } else {
            int kk = k - 32;
            int chE = (kk < 64) ? 0 : 1;
            int ke = (kk < 64) ? kk : kk - 64;
            int tg = target[((bb * 3 + chE) * Rn + r) * Sn + t];
            val = emb[(size_t)(chE * Vn + tg) * En + ke];
        }
        insT[((k >> 1) * 64 + t) * 2 + (k & 1)] = val;
    }
    __syncthreads();

    const int rowbase = ((bb * 3 + ch) * Rn + r) * Sn;
    float* outp = out + (size_t)rowbase * Vn;
    if (K == 32)       compute_logits<16>(Wp, insT, bs, outp, tid);
    else if (K == 96)  compute_logits<48>(Wp, insT, bs, outp, tid);
    else               compute_logits<80>(Wp, insT, bs, outp, tid);
}

// ---------------------------------------------------------------------------
// Fused kernel: blocks 0..95 = RNN half-channel producers, 96.. = logits.
// 1 block/SM => all 96 producers resident in wave 1; flags monotonic.
// ---------------------------------------------------------------------------
__global__ __launch_bounds__(512, 1)
void fused_kernel(const float* __restrict__ WihR, const float* __restrict__ Whh,
                  const float* __restrict__ bih, const float* __restrict__ bhh,
                  const float* __restrict__ emb, const int* __restrict__ target,
                  const float* __restrict__ W0, const float* __restrict__ b0,
                  const float* __restrict__ W1, const float* __restrict__ b1,
                  const float* __restrict__ W2, const float* __restrict__ b2,
                  float* __restrict__ out) {
    extern __shared__ float sm[];
    if (blockIdx.x < Bn * 3 * 2) {
        rnn_body(sm, blockIdx.x, WihR, Whh, bih, bhh);
    } else {
        logits_body(sm, blockIdx.x - Bn * 3 * 2, emb, target, W0, b0, W1, b1,
                    W2, b2, out);
    }
}

// ---------------------------------------------------------------------------
// Launch
// ---------------------------------------------------------------------------
extern "C" void kernel_launch(void* const* d_in, const int* in_sizes, int n_in,
                              void* d_out, int out_size) {
    (void)in_sizes; (void)n_in; (void)out_size;
    const int*   x      = (const int*)  d_in[0];
    const int*   target = (const int*)  d_in[1];
    const float* emb    = (const float*)d_in[2];
    const float* Wih0   = (const float*)d_in[3];
    const float* WihR   = (const float*)d_in[4];
    const float* Whh    = (const float*)d_in[5];
    const float* bih    = (const float*)d_in[6];
    const float* bhh    = (const float*)d_in[7];
    const float* h2eW   = (const float*)d_in[8];
    const float* h2eb   = (const float*)d_in[9];
    const float* adpW   = (const float*)d_in[10];
    const float* adpb   = (const float*)d_in[11];
    const float* redW   = (const float*)d_in[12];
    const float* redb   = (const float*)d_in[13];
    const float* greenW = (const float*)d_in[14];
    const float* greenb = (const float*)d_in[15];
    const float* blueW  = (const float*)d_in[16];
    const float* blueb  = (const float*)d_in[17];
    float* out = (float*)d_out;

    // logits role needs the most smem: (264 + 64) * 160 + 264 floats = 210,976 B
    const size_t smem_fused = (size_t)(264 * 160 + 64 * 160 + 264) * sizeof(float);

    cudaFuncSetAttribute(fused_kernel, cudaFuncAttributeMaxDynamicSharedMemorySize,
                         (int)smem_fused);

    pre_kernel<<<352, 256>>>(emb, Wih0, h2eW, h2eb, adpW, adpb, bih);
    pre2_kernel<<<dim3(Dn, Bn * 3), 256>>>(x, Wih0, bhh);
    fused_kernel<<<Bn * 3 * 2 + Bn * Rn * 3, 512, smem_fused>>>(
        WihR, Whh, bih, bhh, emb, target, redW, redb, greenW, greenb,
        blueW, blueb, out);
}

// round 14
// speedup vs baseline: 10.8878x; 1.0195x over previous
#include <cuda_runtime.h>
#include <math.h>

// ---------------------------------------------------------------------------
// Problem constants
// ---------------------------------------------------------------------------
#define Bn 16
#define Hn 32
#define En 64
#define Vn 258
#define Rn 64
#define Sn 64
#define Dn 127   // number of wavefront diagonals (r + t)

// ---------------------------------------------------------------------------
// Global scratch (static __device__, no allocation)
// ---------------------------------------------------------------------------
__device__ float g_outs_d[Bn * 3 * Dn * Rn * Hn];        // diag layout [b][c][s][r][k]
__device__ float g_comb0[(size_t)Bn * 3 * Dn * 96 * 64]; // [b][c][s][g][r]
__device__ float g_T0[3 * 258 * 96];                     // Wih0 @ emb
__device__ float g_M1[3 * 96 * 32];                      // Wih0 @ h2eW
__device__ float g_M2[2 * 96 * 32];                      // Wih0 @ adpW
__device__ float g_b0[3 * 96];                           // bih0 + Wih0@(h2eb[+adpb])
__device__ int   g_flagH[Bn * 3 * 2];                    // diag progress per (b,c,half)

// ---------------------------------------------------------------------------
// Packed f32x2 helpers
// ---------------------------------------------------------------------------
union P4 { float4 f; ulonglong2 u; };

__device__ __forceinline__ void fma2(unsigned long long& acc,
                                     unsigned long long a,
                                     unsigned long long b) {
    asm("fma.rn.f32x2 %0, %1, %2, %0;" : "+l"(acc) : "l"(a), "l"(b));
}
__device__ __forceinline__ float red2(unsigned long long acc) {
    float x, y;
    asm("mov.b64 {%0, %1}, %2;" : "=f"(x), "=f"(y) : "l"(acc));
    return x + y;
}
__device__ __forceinline__ void dot32(const float* __restrict__ w,
                                      const P4 x[8], unsigned long long& acc) {
    const ulonglong2* W = reinterpret_cast<const ulonglong2*>(w);
#pragma unroll
    for (int i = 0; i < 8; ++i) {
        ulonglong2 wv = W[i];
        fma2(acc, wv.x, x[i].u.x);
        fma2(acc, wv.y, x[i].u.y);
    }
}
__device__ __forceinline__ void load8s(const float* __restrict__ p, P4 x[8]) {
    const float4* q = reinterpret_cast<const float4*>(p);
#pragma unroll
    for (int i = 0; i < 8; ++i) x[i].f = q[i];
}
// HW tanh approximation (sm_75+): single MUFU op, max abs err ~1e-5.
__device__ __forceinline__ float tanh_ap(float x) {
    float y;
    asm("tanh.approx.f32 %0, %1;" : "=f"(y) : "f"(x));
    return y;
}
__device__ __forceinline__ float sigm(float x) {
    return fmaf(tanh_ap(0.5f * x), 0.5f, 0.5f);
}
__device__ __forceinline__ int ld_acq(const int* p) {
    int v;
    asm volatile("ld.global.acquire.gpu.s32 %0, [%1];" : "=r"(v) : "l"(p));
    return v;
}

// ---------------------------------------------------------------------------
// Pre-kernel 1: fold comb linear algebra into tables (+ zero pipeline flags)
// ---------------------------------------------------------------------------
__global__ void pre_kernel(const float* __restrict__ emb,
                           const float* __restrict__ Wih0,
                           const float* __restrict__ h2eW,
                           const float* __restrict__ h2eb,
                           const float* __restrict__ adpW,
                           const float* __restrict__ adpb,
                           const float* __restrict__ bih) {
    int idx = blockIdx.x * 256 + threadIdx.x;
    if (idx < 74304) {                       // T0[c][v][g]
        int c = idx / 24768, rem = idx % 24768;
        int v = rem / 96, g = rem % 96;
        const float* w = Wih0 + c * 6240 + g * 65;
        const float* e = emb + (size_t)(c * 258 + v) * 64;
        float s = 0.f;
        for (int j = 0; j < 64; ++j) s = fmaf(w[j], e[j], s);
        g_T0[idx] = s;
    } else if (idx < 74304 + 9216) {         // M1[c][g][j]
        int i = idx - 74304;
        int c = i / 3072, rem = i % 3072, g = rem / 32, j = rem % 32;
        const float* w = Wih0 + c * 6240 + g * 65;
        float s = 0.f;
        for (int e = 0; e < 65; ++e) s = fmaf(w[e], h2eW[c * 2080 + e * 32 + j], s);
        g_M1[i] = s;
    } else if (idx < 74304 + 9216 + 6144) {  // M2[c2][g][j]
        int i = idx - 74304 - 9216;
        int c2 = i / 3072, rem = i % 3072, g = rem / 32, j = rem % 32;
        const float* w = Wih0 + (c2 + 1) * 6240 + g * 65;
        float s = 0.f;
        for (int e = 0; e < 65; ++e) s = fmaf(w[e], adpW[c2 * 2080 + e * 32 + j], s);
        g_M2[i] = s;
    } else if (idx < 74304 + 9216 + 6144 + 288) {   // b0[c][g]
        int i = idx - 74304 - 9216 - 6144;
        int c = i / 96, g = i % 96;
        const float* w = Wih0 + c * 6240 + g * 65;
        float s = bih[c * 288 + g];
        for (int e = 0; e < 65; ++e) s = fmaf(w[e], h2eb[c * 65 + e], s);
        if (c > 0)
            for (int e = 0; e < 65; ++e) s = fmaf(w[e], adpb[(c - 1) * 65 + e], s);
        g_b0[i] = s;
    } else if (idx < 89952 + 96) {           // zero pipeline flags
        g_flagH[idx - 89952] = 0;
    }
}

// ---------------------------------------------------------------------------
// Pre-kernel 2: materialize comb0 per cell, diagonal layout [b][c][s][g][r].
// ---------------------------------------------------------------------------
__global__ void pre2_kernel(const int* __restrict__ x,
                            const float* __restrict__ Wih0,
                            const float* __restrict__ bhh) {
    __shared__ float w64s[96], bias_s[96];
    __shared__ int xs[64];
    const int s = blockIdx.x;
    const int bc = blockIdx.y;           // b*3 + c
    const int c = bc % 3;
    const int tid = threadIdx.x;
    const int lo = (s > 63) ? s - 63 : 0;
    const int hi = (s < 63) ? s : 63;
    if (tid < 96) {
        w64s[tid] = Wih0[c * 6240 + tid * 65 + 64];
        float bb = g_b0[c * 96 + tid];
        if (tid < 64) bb += bhh[c * 288 + tid];      // bhh r,z (layer 0)
        bias_s[tid] = bb;
    }
    if (tid >= 96 && tid - 96 <= hi - lo) {
        int r = lo + (tid - 96);
        xs[r] = x[(bc * 64 + r) * 64 + (s - r)];
    }
    __syncthreads();
    float* outp = g_comb0 + ((size_t)bc * Dn + s) * 6144;
    const float* t0c = g_T0 + c * 258 * 96;
    for (int idx = tid; idx < 96 * 64; idx += 256) {
        int g = idx >> 6, r = idx & 63;
        if (r < lo || r > hi) continue;
        float rf = (float)r * 0.03125f - 1.0f;
        outp[idx] = t0c[xs[r] * 96 + g] + rf * w64s[g] + bias_s[g];
    }
}

// ---------------------------------------------------------------------------
// Shared-memory layout for the RNN producer role (floats)
// ---------------------------------------------------------------------------
constexpr int OFF_M1   = 0;        // 96 x 32
constexpr int OFF_M2   = 3072;
constexpr int OFF_WHH0 = 6144;
constexpr int OFF_WIH1 = 9216;
constexpr int OFF_WHH1 = 12288;
constexpr int OFF_WIH2 = 15360;
constexpr int OFF_WHH2 = 18432;
constexpr int OFF_B    = 21504;    // 3 x 128 (layer biases; l=0 uses only nh part)
constexpr int OFF_H0   = 21888;    // 2 x (32 x 36) ping-pong
constexpr int OFF_H1   = 24192;    // 2 x (32 x 36)
constexpr int OFF_H2   = 26496;    // 2 x (33 x 36): slot 0 = boundary/zero, slot j+1 = local row j
constexpr int OFF_PC   = 28872;    // 2 x (32 x 36) prev-channel staging
constexpr int SM_RNN_END = 31176;

// ---------------------------------------------------------------------------
// RNN producer: half a channel (32 rows) per block; 96 blocks total.
// pid = bc*2 + h. Half 1 consumes half 0's boundary row via g_outs_d.
// ---------------------------------------------------------------------------
__device__ void rnn_body(float* sm, int pid,
                         const float* __restrict__ WihR,
                         const float* __restrict__ Whh,
                         const float* __restrict__ bih,
                         const float* __restrict__ bhh) {
    const int tid = threadIdx.x;
    const int warp = tid >> 5, lane = tid & 31;
    const int bc = pid >> 1;
    const int h = pid & 1;
    const int R0 = h << 5;
    const int c = bc % 3;
    const bool haspc = (c > 0);

    // ---- stage weights (once) ----
    for (int i = tid; i < 3072; i += 512) {
        sm[OFF_M1 + i]   = g_M1[c * 3072 + i];
        sm[OFF_WHH0 + i] = Whh[c * 9216 + i];
        sm[OFF_WIH1 + i] = WihR[c * 6144 + i];
        sm[OFF_WHH1 + i] = Whh[c * 9216 + 3072 + i];
        sm[OFF_WIH2 + i] = WihR[c * 6144 + 3072 + i];
        sm[OFF_WHH2 + i] = Whh[c * 9216 + 6144 + i];
        if (haspc) sm[OFF_M2 + i] = g_M2[(c - 1) * 3072 + i];
    }
    for (int i = tid; i < 384; i += 512) {
        int l = i >> 7, o = i & 127;
        float v;
        if (o < 64)
            v = ((l == 0) ? 0.f : bih[(c * 3 + l) * 96 + o] +
                                  bhh[(c * 3 + l) * 96 + o]);
        else if (o < 96) {
            int g = 64 + (o - 64);
            v = (l == 0) ? 0.f : bih[(c * 3 + l) * 96 + g];
        } else {
            int g = 64 + (o - 96);
            v = bhh[(c * 3 + l) * 96 + g];
        }
        sm[OFF_B + i] = v;
    }
    for (int i = tid + OFF_H0; i < SM_RNN_END; i += 512) sm[i] = 0.f;

    const float* gprev = g_outs_d + (size_t)(bc - 1) * Dn * 2048;  // valid iff c>0
    float* gcur = g_outs_d + (size_t)bc * Dn * 2048;
    const float* cchan = g_comb0 + (size_t)bc * Dn * 6144;
    const int* flag_prev = &g_flagH[(bc - 1) * 2 + h];   // same half of prev channel
    const int* flag_h0 = &g_flagH[bc * 2];               // half 0 of own channel

    // prologue: PC for step 0 (diag 0 = row 0 only -> half 0)
    if (haspc && h == 0) {
        if (tid == 0) { while (ld_acq(flag_prev) < 1) {} }
    }
    __syncthreads();
    if (haspc && h == 0 && tid < 32) sm[OFF_PC + tid] = gprev[tid];
    __syncthreads();

    for (int s = 0; s < Dn; ++s) {
        const int pong = s & 1, next = 1 - pong;
        const int lo = (s > 63) ? s - 63 : 0;
        const int hi = (s < 63) ? s : 63;
        const int lo_l = (lo > R0) ? lo : R0;
        const int hi_l = (hi < R0 + 31) ? hi : R0 + 31;
        const int nact = hi_l - lo_l + 1;                // may be <= 0

        const int jj = lane;
        const bool valid = jj < nact;
        const int r = lo_l + (valid ? jj : (nact > 0 ? nact - 1 : 0));
        const int j0 = r - R0;

        // ---- 1. coalesced copy-out of previous step's layer-2 results ----
        if (s > 0) {
            const int lop = (s - 1 > 63) ? s - 64 : 0;
            const int hip = (s - 1 < 63) ? s - 1 : 63;
            const int cl0 = (lop > R0) ? lop : R0;
            const int cl1 = (hip < R0 + 31) ? hip : R0 + 31;
            const int np = cl1 - cl0 + 1;
            for (int idx = tid; idx < np * 32; idx += 512) {
                int j = idx >> 5, k = idx & 31, rr = cl0 + j;
                gcur[((size_t)(s - 1) * 64 + rr) * 32 + k] =
                    sm[OFF_H2 + pong * 1188 + (rr - R0 + 1) * 36 + k];
            }
        }
        // ---- boundary: half 1 needs half 0's row 31 output of step s-1 ----
        if (h == 1 && s >= 32 && s <= 95) {
            if (tid == 0) { while (ld_acq(flag_h0) < s) {} }
            __syncthreads();
            if (tid < 32)
                sm[OFF_H2 + pong * 1188 + tid] =
                    __ldcg(&gcur[((size_t)(s - 1) * 64 + 31) * 32 + tid]);
        }
        __syncthreads();

        // ---- publish: diags <= s-1 of this half are in g_outs_d ----
        if (tid == 0) {
            asm volatile("fence.acq_rel.gpu;" ::: "memory");
            asm volatile("st.global.release.gpu.s32 [%0], %1;"
                         :: "l"(&g_flagH[pid]), "r"(s) : "memory");
        }

        // ================= layer 0 (comb folded into g_comb0) ==========
        if (nact > 0) {
            const float* h2base = sm + OFF_H2 + pong * 1188 + j0 * 36;
            const float* h0base = sm + OFF_H0 + pong * 1152 + j0 * 36;
            const float* pcbase = sm + OFF_PC + pong * 1152 + j0 * 36;
            const float* cb = cchan + (size_t)s * 6144 + r;

            for (int k = warp; k < 32; k += 16) {
                float c0r = cb[k * 64];
                float c0z = cb[(k + 32) * 64];
                float c0n = cb[(k + 64) * 64];
                unsigned long long ar = 0ull, az = 0ull, ani = 0ull, anh = 0ull;
                P4 xv[8];
                load8s(h2base, xv);                      // x = out(r-1, t)
                dot32(sm + OFF_M1 + k * 32, xv, ar);
                dot32(sm + OFF_M1 + (k + 32) * 32, xv, az);
                dot32(sm + OFF_M1 + (k + 64) * 32, xv, ani);
                if (haspc) {
                    load8s(pcbase, xv);                  // x = prev-channel out
                    dot32(sm + OFF_M2 + k * 32, xv, ar);
                    dot32(sm + OFF_M2 + (k + 32) * 32, xv, az);
                    dot32(sm + OFF_M2 + (k + 64) * 32, xv, ani);
                }
                load8s(h0base, xv);                      // x = h0 state
                dot32(sm + OFF_WHH0 + k * 32, xv, ar);
                dot32(sm + OFF_WHH0 + (k + 32) * 32, xv, az);
                dot32(sm + OFF_WHH0 + (k + 64) * 32, xv, anh);
                float vr = red2(ar) + c0r;
                float vz = red2(az) + c0z;
                float vni = red2(ani) + c0n;
                float vnh = red2(anh) + sm[OFF_B + 96 + k];
                float rr = sigm(vr), zz = sigm(vz);
                float nn = tanh_ap(fmaf(rr, vnh, vni));
                float hold = h0base[k];
                float hnew = fmaf(zz, hold - nn, nn);
                if (valid) sm[OFF_H0 + next * 1152 + j0 * 36 + k] = hnew;
            }
        }
        __syncthreads();

        // ---- stage prev-channel vectors for step s+1 (buffer `next`) ----
        if (haspc && s + 1 < Dn) {
            const int lo2 = (s + 1 > 63) ? s - 62 : 0;
            const int hi2 = (s + 1 < 63) ? s + 1 : 63;
            const int c0 = (lo2 > R0) ? lo2 : R0;
            const int c1 = (hi2 < R0 + 31) ? hi2 : R0 + 31;
            const int n2 = c1 - c0 + 1;
            if (n2 > 0) {
                if (tid == 0) { while (ld_acq(flag_prev) < s + 2) {} }
                __syncthreads();
                for (int idx = tid; idx < n2 * 32; idx += 512) {
                    int j = idx >> 5, k = idx & 31, rr = c0 + j;
                    sm[OFF_PC + next * 1152 + (rr - R0) * 36 + k] =
                        gprev[((size_t)(s + 1) * 64 + rr) * 32 + k];
                }
            }
        }

        // ================= layer 1 =================
        if (nact > 0) {
            P4 h0n[8], h1c[8];
            load8s(sm + OFF_H0 + next * 1152 + j0 * 36, h0n);
            load8s(sm + OFF_H1 + pong * 1152 + j0 * 36, h1c);
            for (int k = warp; k < 32; k += 16) {
                unsigned long long ar = 0ull, az = 0ull, ani = 0ull, anh = 0ull;
                dot32(sm + OFF_WIH1 + k * 32, h0n, ar);
                dot32(sm + OFF_WHH1 + k * 32, h1c, ar);
                dot32(sm + OFF_WIH1 + (k + 32) * 32, h0n, az);
                dot32(sm + OFF_WHH1 + (k + 32) * 32, h1c, az);
                dot32(sm + OFF_WIH1 + (k + 64) * 32, h0n, ani);
                dot32(sm + OFF_WHH1 + (k + 64) * 32, h1c, anh);
                float vr = red2(ar) + sm[OFF_B + 128 + k];
                float vz = red2(az) + sm[OFF_B + 128 + k + 32];
                float vni = red2(ani) + sm[OFF_B + 128 + 64 + k];
                float vnh = red2(anh) + sm[OFF_B + 128 + 96 + k];
                float rr = sigm(vr), zz = sigm(vz);
                float nn = tanh_ap(fmaf(rr, vnh, vni));
                float hold = sm[OFF_H1 + pong * 1152 + j0 * 36 + k];
                float hnew = fmaf(zz, hold - nn, nn);
                if (valid) sm[OFF_H1 + next * 1152 + j0 * 36 + k] = hnew;
            }
        }
        __syncthreads();

        // ================= layer 2 =================
        if (nact > 0) {
            P4 h1n[8], h2c[8];
            load8s(sm + OFF_H1 + next * 1152 + j0 * 36, h1n);
            load8s(sm + OFF_H2 + pong * 1188 + (j0 + 1) * 36, h2c);
            for (int k = warp; k < 32; k += 16) {
                unsigned long long ar = 0ull, az = 0ull, ani = 0ull, anh = 0ull;
                dot32(sm + OFF_WIH2 + k * 32, h1n, ar);
                dot32(sm + OFF_WHH2 + k * 32, h2c, ar);
                dot32(sm + OFF_WIH2 + (k + 32) * 32, h1n, az);
                dot32(sm + OFF_WHH2 + (k + 32) * 32, h2c, az);
                dot32(sm + OFF_WIH2 + (k + 64) * 32, h1n, ani);
                dot32(sm + OFF_WHH2 + (k + 64) * 32, h2c, anh);
                float vr = red2(ar) + sm[OFF_B + 256 + k];
                float vz = red2(az) + sm[OFF_B + 256 + k + 32];
                float vni = red2(ani) + sm[OFF_B + 256 + 64 + k];
                float vnh = red2(anh) + sm[OFF_B + 256 + 96 + k];
                float rr = sigm(vr), zz = sigm(vz);
                float nn = tanh_ap(fmaf(rr, vnh, vni));
                float hold = sm[OFF_H2 + pong * 1188 + (j0 + 1) * 36 + k];
                float hnew = fmaf(zz, hold - nn, nn);
                if (valid) sm[OFF_H2 + next * 1188 + (j0 + 1) * 36 + k] = hnew;
            }
        }
        // rolling zero: activate row s+1 (if owned) for step s+1
        if (s + 1 >= R0 && s + 1 <= R0 + 31 && tid < 108) {
            int which = tid / 36, kk = tid - which * 36;
            int j = s + 1 - R0;
            if (which == 0)      sm[OFF_H0 + next * 1152 + j * 36 + kk] = 0.f;
            else if (which == 1) sm[OFF_H1 + next * 1152 + j * 36 + kk] = 0.f;
            else                 sm[OFF_H2 + next * 1188 + (j + 1) * 36 + kk] = 0.f;
        }
        __syncthreads();
    }
    // final copy-out: diag 126 = row 63 only (half 1); buffer next(126)=1
    if (h == 1 && tid < 32)
        gcur[((size_t)126 * 64 + 63) * 32 + tid] =
            sm[OFF_H2 + 1 * 1188 + 32 * 36 + tid];
    __syncthreads();
    if (tid == 0) {
        asm volatile("fence.acq_rel.gpu;" ::: "memory");
        asm volatile("st.global.release.gpu.s32 [%0], %1;"
                     :: "l"(&g_flagH[pid]), "r"(200) : "memory");
    }
}

// ---------------------------------------------------------------------------
// Logits role v2: transposed inputs + packed weights.
// ---------------------------------------------------------------------------
template <int K2>
__device__ __forceinline__ void compute_logits(const float* __restrict__ Wp,
                                               const float* __restrict__ insT,
                                               const float* __restrict__ bs,
                                               float* __restrict__ outp, int tid) {
    const int warp = tid >> 5, lane = tid & 31;
    const int stream = warp >> 1;            // 0..7
    const int t = ((warp & 1) << 5) + lane;  // 0..63
    const unsigned long long* ip =
        reinterpret_cast<const unsigned long long*>(insT) + t;

    for (int q = stream; q < 33; q += 8) {   // v-octets (264 padded v)
        unsigned long long a[8] = {0ull, 0ull, 0ull, 0ull, 0ull, 0ull, 0ull, 0ull};
        const ulonglong2* wp =
            reinterpret_cast<const ulonglong2*>(Wp + q * (K2 * 16));
#pragma unroll 4
        for (int k2 = 0; k2 < K2; ++k2) {
            ulonglong2 w01 = wp[k2 * 4 + 0];
            ulonglong2 w23 = wp[k2 * 4 + 1];
            ulonglong2 w45 = wp[k2 * 4 + 2];
            ulonglong2 w67 = wp[k2 * 4 + 3];
            unsigned long long iv = ip[k2 * 64];
            fma2(a[0], w01.x, iv); fma2(a[1], w01.y, iv);
            fma2(a[2], w23.x, iv); fma2(a[3], w23.y, iv);
            fma2(a[4], w45.x, iv); fma2(a[5], w45.y, iv);
            fma2(a[6], w67.x, iv); fma2(a[7], w67.y, iv);
        }
        const int v0 = q * 8;
        float2* op = reinterpret_cast<float2*>(outp + t * Vn + v0);
        if (v0 + 8 <= Vn) {
#pragma unroll
            for (int j = 0; j < 4; ++j) {
                float2 o;
                o.x = red2(a[2 * j]) + bs[v0 + 2 * j];
                o.y = red2(a[2 * j + 1]) + bs[v0 + 2 * j + 1];
                op[j] = o;
            }
        } else {   // v0 = 256: only v 256, 257 are real
            float2 o;
            o.x = red2(a[0]) + bs[v0];
            o.y = red2(a[1]) + bs[v0 + 1];
            op[0] = o;
        }
    }
}

__device__ void logits_body(float* sm, int lid,
                            const float* __restrict__ emb,
                            const int* __restrict__ target,
                            const float* __restrict__ W0, const float* __restrict__ b0,
                            const float* __restrict__ W1, const float* __restrict__ b1,
                            const float* __restrict__ W2, const float* __restrict__ b2,
                            float* __restrict__ out) {
    const int tid = threadIdx.x;
    // lid -> (r, bb, ch): r-major so earliest-ready rows get resident blocks
    const int r = lid / 48;
    const int rem = lid - r * 48;
    const int bb = rem / 3;
    const int ch = rem - bb * 3;

    const float* W;
    const float* Bb;
    int K;
    if (ch == 0)      { W = W0; Bb = b0; K = 32; }
    else if (ch == 1) { W = W1; Bb = b1; K = 96; }
    else              { W = W2; Bb = b2; K = 160; }
    const int K2 = K >> 1;

    float* Wp = sm;                    // 264 * K floats (packed)
    float* insT = sm + 264 * K;        // 64 * K floats (transposed, float2 pairs)
    float* bs = insT + 64 * K;         // 264

    // stage packed weights + bias first (independent of RNN progress)
    for (int idx = tid; idx < 264 * K; idx += 512) {
        int v = idx / K, k = idx - v * K;
        float val = (v < Vn) ? W[v * K + k] : 0.f;
        int q = v >> 3, vl = v & 7, k2 = k >> 1, kk = k & 1;
        Wp[((q * K2 + k2) * 8 + vl) * 2 + kk] = val;
    }
    for (int idx = tid; idx < 264; idx += 512)
        bs[idx] = (idx < Vn) ? Bb[idx] : 0.f;

    // wait for RNN: row r diags r..r+63 ready when its half's flag >= r+64
    const int need = r + 64;
    const int* fp = &g_flagH[(bb * 3 + ch) * 2 + (r >> 5)];
    if (tid == 0) {
        int v = ld_acq(fp);
        while (v < need) { __nanosleep(256); v = ld_acq(fp); }
    }
    __syncthreads();   // broadcast acquire to block (leader-acquire + barrier)

    const size_t diagbase = (size_t)(bb * 3 + ch) * Dn;
    for (int idx = tid; idx < 64 * K; idx += 512) {
        int t = idx / K, k = idx - t * K;
        float val;
        if (k < 32) {
            val = __ldcg(&g_outs_d[(diagbase + (r + t)) * 2048 + r * 32 + k]);
        } else {
            int kk = k - 32;
            int chE = (kk < 64) ? 0 : 1;
            int ke = (kk < 64) ? kk : kk - 64;
            int tg = target[((bb * 3 + chE) * Rn + r) * Sn + t];
            val = emb[(size_t)(chE * Vn + tg) * En + ke];
        }
        insT[((k >> 1) * 64 + t) * 2 + (k & 1)] = val;
    }
    __syncthreads();

    const int rowbase = ((bb * 3 + ch) * Rn + r) * Sn;
    float* outp = out + (size_t)rowbase * Vn;
    if (K == 32)       compute_logits<16>(Wp, insT, bs, outp, tid);
    else if (K == 96)  compute_logits<48>(Wp, insT, bs, outp, tid);
    else               compute_logits<80>(Wp, insT, bs, outp, tid);
}

// ---------------------------------------------------------------------------
// Fused kernel: blocks 0..95 = RNN half-channel producers, 96.. = logits.
// 1 block/SM => all 96 producers resident in wave 1; flags monotonic.
// ---------------------------------------------------------------------------
__global__ __launch_bounds__(512, 1)
void fused_kernel(const float* __restrict__ WihR, const float* __restrict__ Whh,
                  const float* __restrict__ bih, const float* __restrict__ bhh,
                  const float* __restrict__ emb, const int* __restrict__ target,
                  const float* __restrict__ W0, const float* __restrict__ b0,
                  const float* __restrict__ W1, const float* __restrict__ b1,
                  const float* __restrict__ W2, const float* __restrict__ b2,
                  float* __restrict__ out) {
    extern __shared__ float sm[];
    if (blockIdx.x < Bn * 3 * 2) {
        rnn_body(sm, blockIdx.x, WihR, Whh, bih, bhh);
    } else {
        logits_body(sm, blockIdx.x - Bn * 3 * 2, emb, target, W0, b0, W1, b1,
                    W2, b2, out);
    }
}

// ---------------------------------------------------------------------------
// Launch
// ---------------------------------------------------------------------------
extern "C" void kernel_launch(void* const* d_in, const int* in_sizes, int n_in,
                              void* d_out, int out_size) {
    (void)in_sizes; (void)n_in; (void)out_size;
    const int*   x      = (const int*)  d_in[0];
    const int*   target = (const int*)  d_in[1];
    const float* emb    = (const float*)d_in[2];
    const float* Wih0   = (const float*)d_in[3];
    const float* WihR   = (const float*)d_in[4];
    const float* Whh    = (const float*)d_in[5];
    const float* bih    = (const float*)d_in[6];
    const float* bhh    = (const float*)d_in[7];
    const float* h2eW   = (const float*)d_in[8];
    const float* h2eb   = (const float*)d_in[9];
    const float* adpW   = (const float*)d_in[10];
    const float* adpb   = (const float*)d_in[11];
    const float* redW   = (const float*)d_in[12];
    const float* redb   = (const float*)d_in[13];
    const float* greenW = (const float*)d_in[14];
    const float* greenb = (const float*)d_in[15];
    const float* blueW  = (const float*)d_in[16];
    const float* blueb  = (const float*)d_in[17];
    float* out = (float*)d_out;

    // logits role needs the most smem: (264 + 64) * 160 + 264 floats = 210,976 B
    const size_t smem_fused = (size_t)(264 * 160 + 64 * 160 + 264) * sizeof(float);

    cudaFuncSetAttribute(fused_kernel, cudaFuncAttributeMaxDynamicSharedMemorySize,
                         (int)smem_fused);

    pre_kernel<<<352, 256>>>(emb, Wih0, h2eW, h2eb, adpW, adpb, bih);
    pre2_kernel<<<dim3(Dn, Bn * 3), 256>>>(x, Wih0, bhh);
    fused_kernel<<<Bn * 3 * 2 + Bn * Rn * 3, 512, smem_fused>>>(
        WihR, Whh, bih, bhh, emb, target, redW, redb, greenW, greenb,
        blueW, blueb, out);
}

// round 15
// speedup vs baseline: 12.0527x; 1.1070x over previous
#include <cuda_runtime.h>
#include <math.h>

// ---------------------------------------------------------------------------
// Problem constants
// ---------------------------------------------------------------------------
#define Bn 16
#define Hn 32
#define En 64
#define Vn 258
#define Rn 64
#define Sn 64
#define Dn 127   // number of wavefront diagonals (r + t)

// ---------------------------------------------------------------------------
// Global scratch (static __device__, no allocation)
// ---------------------------------------------------------------------------
__device__ float g_outs_d[Bn * 3 * Dn * Rn * Hn];        // diag layout [b][c][s][r][k]
__device__ float g_comb0[(size_t)Bn * 3 * Dn * 96 * 64]; // [b][c][s][g][r]
__device__ float g_T0[3 * 258 * 96];                     // Wih0 @ emb
__device__ float g_M1[3 * 96 * 32];                      // Wih0 @ h2eW
__device__ float g_M2[2 * 96 * 32];                      // Wih0 @ adpW
__device__ float g_b0[3 * 96];                           // bih0 + Wih0@(h2eb[+adpb])
__device__ int   g_flagH[Bn * 3 * 2];                    // diag progress per (b,c,half)

// ---------------------------------------------------------------------------
// Packed f32x2 helpers
// ---------------------------------------------------------------------------
union P4 { float4 f; ulonglong2 u; };

__device__ __forceinline__ void fma2(unsigned long long& acc,
                                     unsigned long long a,
                                     unsigned long long b) {
    asm("fma.rn.f32x2 %0, %1, %2, %0;" : "+l"(acc) : "l"(a), "l"(b));
}
__device__ __forceinline__ float red2(unsigned long long acc) {
    float x, y;
    asm("mov.b64 {%0, %1}, %2;" : "=f"(x), "=f"(y) : "l"(acc));
    return x + y;
}
__device__ __forceinline__ void dot32(const float* __restrict__ w,
                                      const P4 x[8], unsigned long long& acc) {
    const ulonglong2* W = reinterpret_cast<const ulonglong2*>(w);
#pragma unroll
    for (int i = 0; i < 8; ++i) {
        ulonglong2 wv = W[i];
        fma2(acc, wv.x, x[i].u.x);
        fma2(acc, wv.y, x[i].u.y);
    }
}
__device__ __forceinline__ void load8s(const float* __restrict__ p, P4 x[8]) {
    const float4* q = reinterpret_cast<const float4*>(p);
#pragma unroll
    for (int i = 0; i < 8; ++i) x[i].f = q[i];
}
// HW tanh approximation (sm_75+): single MUFU op, max abs err ~1e-5.
__device__ __forceinline__ float tanh_ap(float x) {
    float y;
    asm("tanh.approx.f32 %0, %1;" : "=f"(y) : "f"(x));
    return y;
}
__device__ __forceinline__ float sigm(float x) {
    return fmaf(tanh_ap(0.5f * x), 0.5f, 0.5f);
}
__device__ __forceinline__ int ld_acq(const int* p) {
    int v;
    asm volatile("ld.global.acquire.gpu.s32 %0, [%1];" : "=r"(v) : "l"(p));
    return v;
}

// ---------------------------------------------------------------------------
// Pre-kernel 1: fold comb linear algebra into tables (+ zero pipeline flags)
// ---------------------------------------------------------------------------
__global__ void pre_kernel(const float* __restrict__ emb,
                           const float* __restrict__ Wih0,
                           const float* __restrict__ h2eW,
                           const float* __restrict__ h2eb,
                           const float* __restrict__ adpW,
                           const float* __restrict__ adpb,
                           const float* __restrict__ bih) {
    int idx = blockIdx.x * 256 + threadIdx.x;
    if (idx < 74304) {                       // T0[c][v][g]
        int c = idx / 24768, rem = idx % 24768;
        int v = rem / 96, g = rem % 96;
        const float* w = Wih0 + c * 6240 + g * 65;
        const float* e = emb + (size_t)(c * 258 + v) * 64;
        float s = 0.f;
        for (int j = 0; j < 64; ++j) s = fmaf(w[j], e[j], s);
        g_T0[idx] = s;
    } else if (idx < 74304 + 9216) {         // M1[c][g][j]
        int i = idx - 74304;
        int c = i / 3072, rem = i % 3072, g = rem / 32, j = rem % 32;
        const float* w = Wih0 + c * 6240 + g * 65;
        float s = 0.f;
        for (int e = 0; e < 65; ++e) s = fmaf(w[e], h2eW[c * 2080 + e * 32 + j], s);
        g_M1[i] = s;
    } else if (idx < 74304 + 9216 + 6144) {  // M2[c2][g][j]
        int i = idx - 74304 - 9216;
        int c2 = i / 3072, rem = i % 3072, g = rem / 32, j = rem % 32;
        const float* w = Wih0 + (c2 + 1) * 6240 + g * 65;
        float s = 0.f;
        for (int e = 0; e < 65; ++e) s = fmaf(w[e], adpW[c2 * 2080 + e * 32 + j], s);
        g_M2[i] = s;
    } else if (idx < 74304 + 9216 + 6144 + 288) {   // b0[c][g]
        int i = idx - 74304 - 9216 - 6144;
        int c = i / 96, g = i % 96;
        const float* w = Wih0 + c * 6240 + g * 65;
        float s = bih[c * 288 + g];
        for (int e = 0; e < 65; ++e) s = fmaf(w[e], h2eb[c * 65 + e], s);
        if (c > 0)
            for (int e = 0; e < 65; ++e) s = fmaf(w[e], adpb[(c - 1) * 65 + e], s);
        g_b0[i] = s;
    } else if (idx < 89952 + 96) {           // zero pipeline flags
        g_flagH[idx - 89952] = 0;
    }
}

// ---------------------------------------------------------------------------
// Pre-kernel 2: materialize comb0 per cell, diagonal layout [b][c][s][g][r].
// ---------------------------------------------------------------------------
__global__ void pre2_kernel(const int* __restrict__ x,
                            const float* __restrict__ Wih0,
                            const float* __restrict__ bhh) {
    __shared__ float w64s[96], bias_s[96];
    __shared__ int xs[64];
    const int s = blockIdx.x;
    const int bc = blockIdx.y;           // b*3 + c
    const int c = bc % 3;
    const int tid = threadIdx.x;
    const int lo = (s > 63) ? s - 63 : 0;
    const int hi = (s < 63) ? s : 63;
    if (tid < 96) {
        w64s[tid] = Wih0[c * 6240 + tid * 65 + 64];
        float bb = g_b0[c * 96 + tid];
        if (tid < 64) bb += bhh[c * 288 + tid];      // bhh r,z (layer 0)
        bias_s[tid] = bb;
    }
    if (tid >= 96 && tid - 96 <= hi - lo) {
        int r = lo + (tid - 96);
        xs[r] = x[(bc * 64 + r) * 64 + (s - r)];
    }
    __syncthreads();
    float* outp = g_comb0 + ((size_t)bc * Dn + s) * 6144;
    const float* t0c = g_T0 + c * 258 * 96;
    for (int idx = tid; idx < 96 * 64; idx += 256) {
        int g = idx >> 6, r = idx & 63;
        if (r < lo || r > hi) continue;
        float rf = (float)r * 0.03125f - 1.0f;
        outp[idx] = t0c[xs[r] * 96 + g] + rf * w64s[g] + bias_s[g];
    }
}

// ---------------------------------------------------------------------------
// Shared-memory layout for the RNN producer role (floats)
// ---------------------------------------------------------------------------
constexpr int OFF_M1   = 0;        // 96 x 32
constexpr int OFF_M2   = 3072;
constexpr int OFF_WHH0 = 6144;
constexpr int OFF_WIH1 = 9216;
constexpr int OFF_WHH1 = 12288;
constexpr int OFF_WIH2 = 15360;
constexpr int OFF_WHH2 = 18432;
constexpr int OFF_B    = 21504;    // 3 x 128 (layer biases; l=0 uses only nh part)
constexpr int OFF_H0   = 21888;    // 2 x (32 x 36) ping-pong
constexpr int OFF_H1   = 24192;    // 2 x (32 x 36)
constexpr int OFF_H2   = 26496;    // 2 x (33 x 36): slot 0 = boundary/zero, slot j+1 = local row j
constexpr int OFF_PC   = 28872;    // 2 x (32 x 36) prev-channel staging
constexpr int SM_RNN_END = 31176;

// ---------------------------------------------------------------------------
// RNN producer: half a channel (32 rows) per block; 96 blocks total.
// Warp-specialized: warps 0-7 compute (4 k-units each, 16 packed accs);
// warps 8-15 move data (copy-out, PC staging, boundary, zeros) concurrently.
// ---------------------------------------------------------------------------
__device__ void rnn_body(float* sm, int pid,
                         const float* __restrict__ WihR,
                         const float* __restrict__ Whh,
                         const float* __restrict__ bih,
                         const float* __restrict__ bhh) {
    const int tid = threadIdx.x;
    const int warp = tid >> 5, lane = tid & 31;
    const int bc = pid >> 1;
    const int h = pid & 1;
    const int R0 = h << 5;
    const int c = bc % 3;
    const bool haspc = (c > 0);

    // ---- stage weights (once) ----
    for (int i = tid; i < 3072; i += 512) {
        sm[OFF_M1 + i]   = g_M1[c * 3072 + i];
        sm[OFF_WHH0 + i] = Whh[c * 9216 + i];
        sm[OFF_WIH1 + i] = WihR[c * 6144 + i];
        sm[OFF_WHH1 + i] = Whh[c * 9216 + 3072 + i];
        sm[OFF_WIH2 + i] = WihR[c * 6144 + 3072 + i];
        sm[OFF_WHH2 + i] = Whh[c * 9216 + 6144 + i];
        if (haspc) sm[OFF_M2 + i] = g_M2[(c - 1) * 3072 + i];
    }
    for (int i = tid; i < 384; i += 512) {
        int l = i >> 7, o = i & 127;
        float v;
        if (o < 64)
            v = ((l == 0) ? 0.f : bih[(c * 3 + l) * 96 + o] +
                                  bhh[(c * 3 + l) * 96 + o]);
        else if (o < 96) {
            int g = 64 + (o - 64);
            v = (l == 0) ? 0.f : bih[(c * 3 + l) * 96 + g];
        } else {
            int g = 64 + (o - 96);
            v = bhh[(c * 3 + l) * 96 + g];
        }
        sm[OFF_B + i] = v;
    }
    for (int i = tid + OFF_H0; i < SM_RNN_END; i += 512) sm[i] = 0.f;

    const float* gprev = g_outs_d + (size_t)(bc - 1) * Dn * 2048;  // valid iff c>0
    float* gcur = g_outs_d + (size_t)bc * Dn * 2048;
    const float* cchan = g_comb0 + (size_t)bc * Dn * 6144;
    const int* flag_prev = &g_flagH[(bc - 1) * 2 + h];   // same half of prev channel
    const int* flag_h0 = &g_flagH[bc * 2];               // half 0 of own channel

    // prologue: PC for step 0 (diag 0 = row 0 only -> half 0)
    if (haspc && h == 0) {
        if (tid == 0) { while (ld_acq(flag_prev) < 1) {} }
    }
    __syncthreads();
    if (haspc && h == 0 && tid < 32) sm[OFF_PC + tid] = gprev[tid];
    __syncthreads();

    for (int s = 0; s < Dn; ++s) {
        const int pong = s & 1, next = 1 - pong;
        const int lo = (s > 63) ? s - 63 : 0;
        const int hi = (s < 63) ? s : 63;
        const int lo_l = (lo > R0) ? lo : R0;
        const int hi_l = (hi < R0 + 31) ? hi : R0 + 31;
        const int nact = hi_l - lo_l + 1;                // may be <= 0

        const bool valid = lane < nact;
        const int r = lo_l + (valid ? lane : (nact > 0 ? nact - 1 : 0));
        const int j0 = r - R0;
        const bool cw = (warp < 8) && (nact > 0);        // compute role
        const int dtid = tid - 256;                      // data-warp linear id

        // ---- top: boundary fetch (warp 8) for half 1 ----
        if (h == 1 && s >= 32 && s <= 95 && warp == 8) {
            if (lane == 0) { while (ld_acq(flag_h0) < s) {} }
            __syncwarp();
            sm[OFF_H2 + pong * 1188 + lane] =
                __ldcg(&gcur[((size_t)(s - 1) * 64 + 31) * 32 + lane]);
        }
        __syncthreads();   // sync1: boundary visible, prior step fully done

        // ================= window 1: L0 || copy-out + PC stage ============
        if (cw) {
            const float* h2base = sm + OFF_H2 + pong * 1188 + j0 * 36;
            const float* h0base = sm + OFF_H0 + pong * 1152 + j0 * 36;
            const float* pcbase = sm + OFF_PC + pong * 1152 + j0 * 36;
            const float* cb = cchan + (size_t)s * 6144 + r;

            float c0[12];
#pragma unroll
            for (int kq = 0; kq < 4; ++kq) {
                int k = warp + kq * 8;
                c0[kq * 3 + 0] = cb[k * 64];
                c0[kq * 3 + 1] = cb[(k + 32) * 64];
                c0[kq * 3 + 2] = cb[(k + 64) * 64];
            }
            unsigned long long ar[4] = {0,0,0,0}, az[4] = {0,0,0,0};
            unsigned long long ani[4] = {0,0,0,0}, anh[4] = {0,0,0,0};
            P4 xv[8];
            load8s(h2base, xv);
#pragma unroll
            for (int kq = 0; kq < 4; ++kq) {
                int k = warp + kq * 8;
                dot32(sm + OFF_M1 + k * 32, xv, ar[kq]);
                dot32(sm + OFF_M1 + (k + 32) * 32, xv, az[kq]);
                dot32(sm + OFF_M1 + (k + 64) * 32, xv, ani[kq]);
            }
            if (haspc) {
                load8s(pcbase, xv);
#pragma unroll
                for (int kq = 0; kq < 4; ++kq) {
                    int k = warp + kq * 8;
                    dot32(sm + OFF_M2 + k * 32, xv, ar[kq]);
                    dot32(sm + OFF_M2 + (k + 32) * 32, xv, az[kq]);
                    dot32(sm + OFF_M2 + (k + 64) * 32, xv, ani[kq]);
                }
            }
            load8s(h0base, xv);
#pragma unroll
            for (int kq = 0; kq < 4; ++kq) {
                int k = warp + kq * 8;
                dot32(sm + OFF_WHH0 + k * 32, xv, ar[kq]);
                dot32(sm + OFF_WHH0 + (k + 32) * 32, xv, az[kq]);
                dot32(sm + OFF_WHH0 + (k + 64) * 32, xv, anh[kq]);
            }
#pragma unroll
            for (int kq = 0; kq < 4; ++kq) {
                int k = warp + kq * 8;
                float vr = red2(ar[kq]) + c0[kq * 3 + 0];
                float vz = red2(az[kq]) + c0[kq * 3 + 1];
                float vni = red2(ani[kq]) + c0[kq * 3 + 2];
                float vnh = red2(anh[kq]) + sm[OFF_B + 96 + k];
                float rr = sigm(vr), zz = sigm(vz);
                float nn = tanh_ap(fmaf(rr, vnh, vni));
                float hold = h0base[k];
                float hnew = fmaf(zz, hold - nn, nn);
                if (valid) sm[OFF_H0 + next * 1152 + j0 * 36 + k] = hnew;
            }
        } else if (warp >= 8) {
            // copy-out previous step's layer-2 results (reads H2 pong)
            if (s > 0) {
                const int lop = (s - 1 > 63) ? s - 64 : 0;
                const int hip = (s - 1 < 63) ? s - 1 : 63;
                const int cl0 = (lop > R0) ? lop : R0;
                const int cl1 = (hip < R0 + 31) ? hip : R0 + 31;
                const int np = cl1 - cl0 + 1;
                for (int idx = dtid; idx < np * 32; idx += 256) {
                    int j = idx >> 5, k = idx & 31, rr = cl0 + j;
                    gcur[((size_t)(s - 1) * 64 + rr) * 32 + k] =
                        sm[OFF_H2 + pong * 1188 + (rr - R0 + 1) * 36 + k];
                }
            }
            // PC staging for step s+1 (writes PC next)
            if (haspc && s + 1 < Dn) {
                const int lo2 = (s + 1 > 63) ? s - 62 : 0;
                const int hi2 = (s + 1 < 63) ? s + 1 : 63;
                const int c0_ = (lo2 > R0) ? lo2 : R0;
                const int c1_ = (hi2 < R0 + 31) ? hi2 : R0 + 31;
                const int n2 = c1_ - c0_ + 1;
                if (n2 > 0) {
                    if (dtid == 0) { while (ld_acq(flag_prev) < s + 2) {} }
                    asm volatile("bar.sync 1, 256;" ::: "memory");
                    for (int idx = dtid; idx < n2 * 32; idx += 256) {
                        int j = idx >> 5, k = idx & 31, rr = c0_ + j;
                        sm[OFF_PC + next * 1152 + (rr - R0) * 36 + k] =
                            gprev[((size_t)(s + 1) * 64 + rr) * 32 + k];
                    }
                }
            }
        }
        __syncthreads();   // sync2: copy-out of diag s-1 complete

        // ---- publish: diags <= s-1 of this half are in g_outs_d ----
        if (tid == 0) {
            asm volatile("fence.acq_rel.gpu;" ::: "memory");
            asm volatile("st.global.release.gpu.s32 [%0], %1;"
                         :: "l"(&g_flagH[pid]), "r"(s) : "memory");
        }

        // ================= window 2: L1 =================
        if (cw) {
            unsigned long long ar[4] = {0,0,0,0}, az[4] = {0,0,0,0};
            unsigned long long ani[4] = {0,0,0,0}, anh[4] = {0,0,0,0};
            P4 xv[8];
            const float* h1base = sm + OFF_H1 + pong * 1152 + j0 * 36;
            load8s(sm + OFF_H0 + next * 1152 + j0 * 36, xv);
#pragma unroll
            for (int kq = 0; kq < 4; ++kq) {
                int k = warp + kq * 8;
                dot32(sm + OFF_WIH1 + k * 32, xv, ar[kq]);
                dot32(sm + OFF_WIH1 + (k + 32) * 32, xv, az[kq]);
                dot32(sm + OFF_WIH1 + (k + 64) * 32, xv, ani[kq]);
            }
            load8s(h1base, xv);
#pragma unroll
            for (int kq = 0; kq < 4; ++kq) {
                int k = warp + kq * 8;
                dot32(sm + OFF_WHH1 + k * 32, xv, ar[kq]);
                dot32(sm + OFF_WHH1 + (k + 32) * 32, xv, az[kq]);
                dot32(sm + OFF_WHH1 + (k + 64) * 32, xv, anh[kq]);
            }
#pragma unroll
            for (int kq = 0; kq < 4; ++kq) {
                int k = warp + kq * 8;
                float vr = red2(ar[kq]) + sm[OFF_B + 128 + k];
                float vz = red2(az[kq]) + sm[OFF_B + 128 + 32 + k];
                float vni = red2(ani[kq]) + sm[OFF_B + 128 + 64 + k];
                float vnh = red2(anh[kq]) + sm[OFF_B + 128 + 96 + k];
                float rr = sigm(vr), zz = sigm(vz);
                float nn = tanh_ap(fmaf(rr, vnh, vni));
                float hold = h1base[k];
                float hnew = fmaf(zz, hold - nn, nn);
                if (valid) sm[OFF_H1 + next * 1152 + j0 * 36 + k] = hnew;
            }
        }
        __syncthreads();   // sync3

        // ================= window 3: L2 || rolling zeros =================
        if (cw) {
            unsigned long long ar[4] = {0,0,0,0}, az[4] = {0,0,0,0};
            unsigned long long ani[4] = {0,0,0,0}, anh[4] = {0,0,0,0};
            P4 xv[8];
            const float* h2base = sm + OFF_H2 + pong * 1188 + (j0 + 1) * 36;
            load8s(sm + OFF_H1 + next * 1152 + j0 * 36, xv);
#pragma unroll
            for (int kq = 0; kq < 4; ++kq) {
                int k = warp + kq * 8;
                dot32(sm + OFF_WIH2 + k * 32, xv, ar[kq]);
                dot32(sm + OFF_WIH2 + (k + 32) * 32, xv, az[kq]);
                dot32(sm + OFF_WIH2 + (k + 64) * 32, xv, ani[kq]);
            }
            load8s(h2base, xv);
#pragma unroll
            for (int kq = 0; kq < 4; ++kq) {
                int k = warp + kq * 8;
                dot32(sm + OFF_WHH2 + k * 32, xv, ar[kq]);
                dot32(sm + OFF_WHH2 + (k + 32) * 32, xv, az[kq]);
                dot32(sm + OFF_WHH2 + (k + 64) * 32, xv, anh[kq]);
            }
#pragma unroll
            for (int kq = 0; kq < 4; ++kq) {
                int k = warp + kq * 8;
                float vr = red2(ar[kq]) + sm[OFF_B + 256 + k];
                float vz = red2(az[kq]) + sm[OFF_B + 256 + 32 + k];
                float vni = red2(ani[kq]) + sm[OFF_B + 256 + 64 + k];
                float vnh = red2(anh[kq]) + sm[OFF_B + 256 + 96 + k];
                float rr = sigm(vr), zz = sigm(vz);
                float nn = tanh_ap(fmaf(rr, vnh, vni));
                float hold = h2base[k];
                float hnew = fmaf(zz, hold - nn, nn);
                if (valid) sm[OFF_H2 + next * 1188 + (j0 + 1) * 36 + k] = hnew;
            }
        } else if (warp >= 8) {
            // rolling zero: activate row s+1 (if owned) for step s+1
            if (s + 1 >= R0 && s + 1 <= R0 + 31 && dtid < 108) {
                int which = dtid / 36, kk = dtid - which * 36;
                int j = s + 1 - R0;
                if (which == 0)      sm[OFF_H0 + next * 1152 + j * 36 + kk] = 0.f;
                else if (which == 1) sm[OFF_H1 + next * 1152 + j * 36 + kk] = 0.f;
                else                 sm[OFF_H2 + next * 1188 + (j + 1) * 36 + kk] = 0.f;
            }
        }
        __syncthreads();   // sync4 (end of step)
    }
    // final copy-out: diag 126 = row 63 only (half 1); buffer next(126)=1
    if (h == 1 && tid < 32)
        gcur[((size_t)126 * 64 + 63) * 32 + tid] =
            sm[OFF_H2 + 1 * 1188 + 32 * 36 + tid];
    __syncthreads();
    if (tid == 0) {
        asm volatile("fence.acq_rel.gpu;" ::: "memory");
        asm volatile("st.global.release.gpu.s32 [%0], %1;"
                     :: "l"(&g_flagH[pid]), "r"(200) : "memory");
    }
}

// ---------------------------------------------------------------------------
// Logits role: transposed inputs + packed weights (unchanged from R12/13).
// ---------------------------------------------------------------------------
template <int K2>
__device__ __forceinline__ void compute_logits(const float* __restrict__ Wp,
                                               const float* __restrict__ insT,
                                               const float* __restrict__ bs,
                                               float* __restrict__ outp, int tid) {
    const int warp = tid >> 5, lane = tid & 31;
    const int stream = warp >> 1;            // 0..7
    const int t = ((warp & 1) << 5) + lane;  // 0..63
    const unsigned long long* ip =
        reinterpret_cast<const unsigned long long*>(insT) + t;

    for (int q = stream; q < 33; q += 8) {   // v-octets (264 padded v)
        unsigned long long a[8] = {0ull, 0ull, 0ull, 0ull, 0ull, 0ull, 0ull, 0ull};
        const ulonglong2* wp =
            reinterpret_cast<const ulonglong2*>(Wp + q * (K2 * 16));
#pragma unroll 4
        for (int k2 = 0; k2 < K2; ++k2) {
            ulonglong2 w01 = wp[k2 * 4 + 0];
            ulonglong2 w23 = wp[k2 * 4 + 1];
            ulonglong2 w45 = wp[k2 * 4 + 2];
            ulonglong2 w67 = wp[k2 * 4 + 3];
            unsigned long long iv = ip[k2 * 64];
            fma2(a[0], w01.x, iv); fma2(a[1], w01.y, iv);
            fma2(a[2], w23.x, iv); fma2(a[3], w23.y, iv);
            fma2(a[4], w45.x, iv); fma2(a[5], w45.y, iv);
            fma2(a[6], w67.x, iv); fma2(a[7], w67.y, iv);
        }
        const int v0 = q * 8;
        float2* op = reinterpret_cast<float2*>(outp + t * Vn + v0);
        if (v0 + 8 <= Vn) {
#pragma unroll
            for (int j = 0; j < 4; ++j) {
                float2 o;
                o.x = red2(a[2 * j]) + bs[v0 + 2 * j];
                o.y = red2(a[2 * j + 1]) + bs[v0 + 2 * j + 1];
                op[j] = o;
            }
        } else {   // v0 = 256: only v 256, 257 are real
            float2 o;
            o.x = red2(a[0]) + bs[v0];
            o.y = red2(a[1]) + bs[v0 + 1];
            op[0] = o;
        }
    }
}

__device__ void logits_body(float* sm, int lid,
                            const float* __restrict__ emb,
                            const int* __restrict__ target,
                            const float* __restrict__ W0, const float* __restrict__ b0,
                            const float* __restrict__ W1, const float* __restrict__ b1,
                            const float* __restrict__ W2, const float* __restrict__ b2,
                            float* __restrict__ out) {
    const int tid = threadIdx.x;
    // lid -> (r, bb, ch): r-major so earliest-ready rows get resident blocks
    const int r = lid / 48;
    const int rem = lid - r * 48;
    const int bb = rem / 3;
    const int ch = rem - bb * 3;

    const float* W;
    const float* Bb;
    int K;
    if (ch == 0)      { W = W0; Bb = b0; K = 32; }
    else if (ch == 1) { W = W1; Bb = b1; K = 96; }
    else              { W = W2; Bb = b2; K = 160; }
    const int K2 = K >> 1;

    float* Wp = sm;                    // 264 * K floats (packed)
    float* insT = sm + 264 * K;        // 64 * K floats (transposed, float2 pairs)
    float* bs = insT + 64 * K;         // 264

    // stage packed weights + bias first (independent of RNN progress)
    for (int idx = tid; idx < 264 * K; idx += 512) {
        int v = idx / K, k = idx - v * K;
        float val = (v < Vn) ? W[v * K + k] : 0.f;
        int q = v >> 3, vl = v & 7, k2 = k >> 1, kk = k & 1;
        Wp[((q * K2 + k2) * 8 + vl) * 2 + kk] = val;
    }
    for (int idx = tid; idx < 264; idx += 512)
        bs[idx] = (idx < Vn) ? Bb[idx] : 0.f;

    // wait for RNN: row r diags r..r+63 ready when its half's flag >= r+64
    const int need = r + 64;
    const int* fp = &g_flagH[(bb * 3 + ch) * 2 + (r >> 5)];
    if (tid == 0) {
        int v = ld_acq(fp);
        while (v < need) { __nanosleep(256); v = ld_acq(fp); }
    }
    __syncthreads();   // broadcast acquire to block (leader-acquire + barrier)

    const size_t diagbase = (size_t)(bb * 3 + ch) * Dn;
    for (int idx = tid; idx < 64 * K; idx += 512) {
        int t = idx / K, k = idx - t * K;
        float val;
        if (k < 32) {
            val = __ldcg(&g_outs_d[(diagbase + (r + t)) * 2048 + r * 32 + k]);
        } else {
            int kk = k - 32;
            int chE = (kk < 64) ? 0 : 1;
            int ke = (kk < 64) ? kk : kk - 64;
            int tg = target[((bb * 3 + chE) * Rn + r) * Sn + t];
            val = emb[(size_t)(chE * Vn + tg) * En + ke];
        }
        insT[((k >> 1) * 64 + t) * 2 + (k & 1)] = val;
    }
    __syncthreads();

    const int rowbase = ((bb * 3 + ch) * Rn + r) * Sn;
    float* outp = out + (size_t)rowbase * Vn;
    if (K == 32)       compute_logits<16>(Wp, insT, bs, outp, tid);
    else if (K == 96)  compute_logits<48>(Wp, insT, bs, outp, tid);
    else               compute_logits<80>(Wp, insT, bs, outp, tid);
}

// ---------------------------------------------------------------------------
// Fused kernel: blocks 0..95 = RNN half-channel producers, 96.. = logits.
// 1 block/SM => all 96 producers resident in wave 1; flags monotonic.
// ---------------------------------------------------------------------------
__global__ __launch_bounds__(512, 1)
void fused_kernel(const float* __restrict__ WihR, const float* __restrict__ Whh,
                  const float* __restrict__ bih, const float* __restrict__ bhh,
                  const float* __restrict__ emb, const int* __restrict__ target,
                  const float* __restrict__ W0, const float* __restrict__ b0,
                  const float* __restrict__ W1, const float* __restrict__ b1,
                  const float* __restrict__ W2, const float* __restrict__ b2,
                  float* __restrict__ out) {
    extern __shared__ float sm[];
    if (blockIdx.x < Bn * 3 * 2) {
        rnn_body(sm, blockIdx.x, WihR, Whh, bih, bhh);
    } else {
        logits_body(sm, blockIdx.x - Bn * 3 * 2, emb, target, W0, b0, W1, b1,
                    W2, b2, out);
    }
}

// ---------------------------------------------------------------------------
// Launch
// ---------------------------------------------------------------------------
extern "C" void kernel_launch(void* const* d_in, const int* in_sizes, int n_in,
                              void* d_out, int out_size) {
    (void)in_sizes; (void)n_in; (void)out_size;
    const int*   x      = (const int*)  d_in[0];
    const int*   target = (const int*)  d_in[1];
    const float* emb    = (const float*)d_in[2];
    const float* Wih0   = (const float*)d_in[3];
    const float* WihR   = (const float*)d_in[4];
    const float* Whh    = (const float*)d_in[5];
    const float* bih    = (const float*)d_in[6];
    const float* bhh    = (const float*)d_in[7];
    const float* h2eW   = (const float*)d_in[8];
    const float* h2eb   = (const float*)d_in[9];
    const float* adpW   = (const float*)d_in[10];
    const float* adpb   = (const float*)d_in[11];
    const float* redW   = (const float*)d_in[12];
    const float* redb   = (const float*)d_in[13];
    const float* greenW = (const float*)d_in[14];
    const float* greenb = (const float*)d_in[15];
    const float* blueW  = (const float*)d_in[16];
    const float* blueb  = (const float*)d_in[17];
    float* out = (float*)d_out;

    // logits role needs the most smem: (264 + 64) * 160 + 264 floats = 210,976 B
    const size_t smem_fused = (size_t)(264 * 160 + 64 * 160 + 264) * sizeof(float);

    cudaFuncSetAttribute(fused_kernel, cudaFuncAttributeMaxDynamicSharedMemorySize,
                         (int)smem_fused);

    pre_kernel<<<352, 256>>>(emb, Wih0, h2eW, h2eb, adpW, adpb, bih);
    pre2_kernel<<<dim3(Dn, Bn * 3), 256>>>(x, Wih0, bhh);
    fused_kernel<<<Bn * 3 * 2 + Bn * Rn * 3, 512, smem_fused>>>(
        WihR, Whh, bih, bhh, emb, target, redW, redb, greenW, greenb,
        blueW, blueb, out);
}